// round 6
// baseline (speedup 1.0000x reference)
#include <cuda_runtime.h>
#include <cuda_fp16.h>
#include <cstdint>

#define NB 4
#define NS 1024
#define NR 12
#define NDIM 512
#define NH 8
#define ND 64
#define NROWS (NB*NS*NR)        /* 49152 */
#define NKV (NS+1)              /* 1025  */
#define LDSIM 1040              /* fp32 sim ld */
#define LDAT 1088               /* fp16 attn / v_t ld (mult of 32) */
#define RD (NR*ND)              /* 768 */
#define BH (NB*NH)              /* 32 */

// smem: per stage, A 128x40 halves + B 128x40 halves (k-slab 32)
#define LDS 40
#define ASTG (128*LDS)              /* 5120 halves */
#define STG  (2*ASTG)               /* 10240 halves per stage */
#define GEMM_SMEM (2*STG*2)         /* 40960 bytes */

// ---------------- scratch ----------------
__device__ __half g_xnh [(size_t)NROWS * NDIM];
__device__ __half g_ctxh[(size_t)NROWS * NDIM];
__device__ __half g_ctxl[(size_t)NROWS * NDIM];
__device__ __half g_wqh [512*512],  g_wql [512*512];
__device__ __half g_wkvh[1024*512], g_wkvl[1024*512];
__device__ __half g_woh [512*512],  g_wol [512*512];
__device__ __half g_qh  [(size_t)BH * NS * RD];
__device__ __half g_kh  [(size_t)BH * NKV * RD];
__device__ float  g_vf  [(size_t)BH * NKV * RD];
__device__ __half g_vth [(size_t)BH * RD * LDAT];
__device__ __half g_vtl [(size_t)BH * RD * LDAT];
__device__ float  g_sim [(size_t)BH * NS * LDSIM];
__device__ __half g_ath [(size_t)BH * NS * LDAT];
__device__ __half g_atl [(size_t)BH * NS * LDAT];
__device__ __half g_oh  [(size_t)NROWS * NDIM];
__device__ __half g_ol  [(size_t)NROWS * NDIM];
__device__ float  g_out [(size_t)NROWS * NDIM];

// ---------------- helpers ----------------
__device__ __forceinline__ uint32_t smem_u32(const void* p) {
    uint32_t a;
    asm("{ .reg .u64 t; cvta.to.shared.u64 t, %1; cvt.u32.u64 %0, t; }" : "=r"(a) : "l"(p));
    return a;
}
__device__ __forceinline__ void ldsm4(uint32_t* r, uint32_t addr) {
    asm volatile("ldmatrix.sync.aligned.m8n8.x4.shared.b16 {%0,%1,%2,%3}, [%4];"
                 : "=r"(r[0]), "=r"(r[1]), "=r"(r[2]), "=r"(r[3]) : "r"(addr));
}
__device__ __forceinline__ void mma16816(float* c, const uint32_t* a, uint32_t b0, uint32_t b1) {
    asm volatile("mma.sync.aligned.m16n8k16.row.col.f32.f16.f16.f32 "
                 "{%0,%1,%2,%3}, {%4,%5,%6,%7}, {%8,%9}, {%0,%1,%2,%3};"
                 : "+f"(c[0]), "+f"(c[1]), "+f"(c[2]), "+f"(c[3])
                 : "r"(a[0]), "r"(a[1]), "r"(a[2]), "r"(a[3]), "r"(b0), "r"(b1));
}
__device__ __forceinline__ uint32_t pk_hi(float a, float b) {
    __half2 t = __floats2half2_rn(a, b);
    return *(uint32_t*)&t;
}
__device__ __forceinline__ uint32_t pk_lo(float a, float b) {
    float ha = __half2float(__float2half_rn(a));
    float hb = __half2float(__float2half_rn(b));
    __half2 t = __floats2half2_rn(a - ha, b - hb);
    return *(uint32_t*)&t;
}
__device__ __forceinline__ void split1(float v, __half* ph, __half* pl) {
    __half h = __float2half_rn(v);
    *ph = h; *pl = __float2half_rn(v - __half2float(h));
}

// ------- HMMA GEMM: D[m,n] = sum_k A[m,k]*B[n,k]; NREG=1 (hi only) or 3 (hi/lo) -------
#define GQPROJ 0
#define GKPROJ 1
#define GVPROJ 2
#define GSIM   3
#define GAV    4
#define GOPROJ 5

template<int MODE>
__global__ __launch_bounds__(256, 2) void gemm_hmma()
{
    extern __shared__ __half sh[];
    const int tid = threadIdx.x, lane = tid & 31, wid = tid >> 5;
    const int m0 = blockIdx.y * 128, n0 = blockIdx.x * 128;

    constexpr int NREG = (MODE==GVPROJ || MODE==GAV || MODE==GOPROJ) ? 3 : 1;
    constexpr int Nn   = MODE==GSIM ? NKV : MODE==GAV ? RD : 512;
    constexpr int K    = MODE==GSIM ? RD : MODE==GAV ? LDAT : 512;
    constexpr int SPR  = K / 32;
    constexpr int S    = NREG * SPR;

    const __half *Ah, *Al, *Bh, *Bl;
    if constexpr (MODE == GQPROJ)      { Ah=g_xnh;  Al=g_xnh;  Bh=g_wqh;  Bl=g_wqh; }
    else if constexpr (MODE == GKPROJ) { Ah=g_ctxh; Al=g_ctxh; Bh=g_wkvh; Bl=g_wkvh; }
    else if constexpr (MODE == GVPROJ) { Ah=g_ctxh; Al=g_ctxl;
                                         Bh=g_wkvh + 512*512; Bl=g_wkvl + 512*512; }
    else if constexpr (MODE == GSIM) {
        size_t z = blockIdx.z;
        Ah=g_qh + z*(size_t)NS*RD;  Al=Ah;
        Bh=g_kh + z*(size_t)NKV*RD; Bl=Bh;
    } else if constexpr (MODE == GAV) {
        size_t z = blockIdx.z;
        Ah=g_ath + z*(size_t)NS*LDAT; Al=g_atl + z*(size_t)NS*LDAT;
        Bh=g_vth + z*(size_t)RD*LDAT; Bl=g_vtl + z*(size_t)RD*LDAT;
    } else                             { Ah=g_oh;   Al=g_ol;   Bh=g_woh;  Bl=g_wol; }

    // warp tiling: 2 (m) x 4 (n); warp tile 64m x 32n
    const int m0w = (wid & 1) * 64;
    const int n0w = (wid >> 1) * 32;
    const int lrow = tid >> 2;              // 0..63
    const int lc   = (tid & 3) * 8;         // half offset within 32

    const uint32_t smb = smem_u32(sh);
    const uint32_t aAddr = smb + (uint32_t)(((m0w + (lane & 15)) * LDS + ((lane >> 4) << 3)) * 2);
    const uint32_t bAddr = smb + (uint32_t)((ASTG + (n0w + (lane & 15)) * LDS + ((lane >> 4) << 3)) * 2);

    float acc[4][4][4] = {};
    uint4 pa0, pa1, pb0, pb1;

    auto ldslab = [&](int s) {
        const int rg = s / SPR;
        const int k0 = (s - rg * SPR) * 32;
        const __half* Ap = (rg == 1) ? Al : Ah;
        const __half* Bp = (rg == 2) ? Bl : Bh;
        pa0 = *(const uint4*)(Ap + (size_t)(m0 + lrow)      * K + k0 + lc);
        pa1 = *(const uint4*)(Ap + (size_t)(m0 + lrow + 64) * K + k0 + lc);
        const uint4 z4 = make_uint4(0u,0u,0u,0u);
        pb0 = (n0 + lrow      < Nn) ? *(const uint4*)(Bp + (size_t)(n0 + lrow)      * K + k0 + lc) : z4;
        pb1 = (n0 + lrow + 64 < Nn) ? *(const uint4*)(Bp + (size_t)(n0 + lrow + 64) * K + k0 + lc) : z4;
    };
    auto stslab = [&](int buf) {
        __half* st = sh + buf * STG;
        *(uint4*)(st + lrow * LDS + lc)        = pa0;
        *(uint4*)(st + (lrow + 64) * LDS + lc) = pa1;
        *(uint4*)(st + ASTG + lrow * LDS + lc)        = pb0;
        *(uint4*)(st + ASTG + (lrow + 64) * LDS + lc) = pb1;
    };
    auto compute = [&](int buf) {
        const uint32_t aB = aAddr + buf * (STG * 2);
        const uint32_t bB = bAddr + buf * (STG * 2);
#pragma unroll
        for (int k16 = 0; k16 < 2; k16++) {
            uint32_t a[4][4], b[2][4];
#pragma unroll
            for (int mf = 0; mf < 4; mf++) ldsm4(a[mf], aB + mf * (16*LDS*2) + k16 * 32);
#pragma unroll
            for (int nf = 0; nf < 2; nf++) ldsm4(b[nf], bB + nf * (16*LDS*2) + k16 * 32);
#pragma unroll
            for (int mf = 0; mf < 4; mf++)
#pragma unroll
                for (int j = 0; j < 4; j++)
                    mma16816(acc[mf][j], a[mf], b[j>>1][j&1], b[j>>1][(j&1)+2]);
        }
    };

    ldslab(0);
    stslab(0);
    for (int s = 0; s < S; s++) {
        __syncthreads();
        if (s + 1 < S) ldslab(s + 1);
        compute(s & 1);
        if (s + 1 < S) stslab((s + 1) & 1);
    }

    // epilogue
    const int rbase = m0 + m0w + (lane >> 2);
    const int cbase = n0 + n0w + (lane & 3) * 2;
#pragma unroll
    for (int mf = 0; mf < 4; mf++)
#pragma unroll
    for (int half = 0; half < 2; half++) {
        const int gm = rbase + mf * 16 + half * 8;
#pragma unroll
        for (int j = 0; j < 4; j++) {
            const int gn = cbase + j * 8;
            const float v0 = acc[mf][j][half * 2 + 0];
            const float v1 = acc[mf][j][half * 2 + 1];
            if constexpr (MODE == GQPROJ) {
                int rr = gm % NR, t = gm / NR; int nn = t & (NS-1); int b = t >> 10;
                int h = gn >> 6, d = gn & 63;
                size_t off = ((size_t)((b << 3) + h) * NS + nn) * RD + rr * ND + d;
                *(uint32_t*)(g_qh + off) = pk_hi(v0, v1);
            } else if constexpr (MODE == GKPROJ) {
                int rr = gm % NR, t = gm / NR; int nn = t & (NS-1); int b = t >> 10;
                int h = gn >> 6, d = gn & 63;
                size_t off = ((size_t)((b << 3) + h) * NKV + nn + 1) * RD + rr * ND + d;
                *(uint32_t*)(g_kh + off) = pk_hi(v0, v1);
            } else if constexpr (MODE == GVPROJ) {
                int rr = gm % NR, t = gm / NR; int nn = t & (NS-1); int b = t >> 10;
                int h = gn >> 6, d = gn & 63;
                size_t off = ((size_t)((b << 3) + h) * NKV + nn + 1) * RD + rr * ND + d;
                *(float2*)(g_vf + off) = make_float2(v0, v1);
            } else if constexpr (MODE == GSIM) {
                const float QS = (0.125f / 128.0f) * 0.28867513459481287f;
                size_t z = blockIdx.z;
                float* cr = g_sim + (z * NS + gm) * (size_t)LDSIM + gn;
                if (gn + 1 < NKV)      *(float2*)cr = make_float2(v0 * QS, v1 * QS);
                else if (gn < NKV)     cr[0] = v0 * QS;
            } else if constexpr (MODE == GAV) {
                size_t z = blockIdx.z; int b = (int)(z >> 3), h = (int)(z & 7);
                int rr = gn >> 6, d = gn & 63;
                size_t off = (((size_t)b * NS + gm) * NR + rr) * NDIM + h * ND + d;
                *(uint32_t*)(g_oh + off) = pk_hi(v0, v1);
                *(uint32_t*)(g_ol + off) = pk_lo(v0, v1);
            } else {
                *(float2*)(g_out + (size_t)gm * NDIM + gn) = make_float2(v0, v1);
            }
        }
    }
}

// ---------------- fp32 -> hi/lo fp16 ----------------
__global__ void conv_hilo(const float* __restrict__ src,
                          __half* __restrict__ hi, __half* __restrict__ lo, int n4)
{
    int i = blockIdx.x * 256 + threadIdx.x;
    if (i >= n4) return;
    float4 v = ((const float4*)src)[i];
    *(uint2*)(hi + 4*(size_t)i) = make_uint2(pk_hi(v.x, v.y), pk_hi(v.z, v.w));
    *(uint2*)(lo + 4*(size_t)i) = make_uint2(pk_lo(v.x, v.y), pk_lo(v.z, v.w));
}

// ---------------- LN(x) -> xn hi ----------------
__global__ void ln_in(const float* __restrict__ xin, const float* __restrict__ g)
{
    __shared__ float red1[4], red2[4];
    size_t row = blockIdx.x;
    int tid = threadIdx.x;                 // 128
    float4 v = ((const float4*)(xin + row * NDIM))[tid];
    float s = v.x + v.y + v.z + v.w;
#pragma unroll
    for (int o = 16; o; o >>= 1) s += __shfl_xor_sync(0xffffffffu, s, o);
    if ((tid & 31) == 0) red1[tid >> 5] = s;
    __syncthreads();
    float mean = (red1[0] + red1[1] + red1[2] + red1[3]) * (1.0f / NDIM);
    float d0 = v.x - mean, d1 = v.y - mean, d2 = v.z - mean, d3 = v.w - mean;
    float ss = d0*d0 + d1*d1 + d2*d2 + d3*d3;
#pragma unroll
    for (int o = 16; o; o >>= 1) ss += __shfl_xor_sync(0xffffffffu, ss, o);
    if ((tid & 31) == 0) red2[tid >> 5] = ss;
    __syncthreads();
    float var = (red2[0] + red2[1] + red2[2] + red2[3]) * (1.0f / NDIM);
    float inv = rsqrtf(var + 1e-5f);
    float4 gv = ((const float4*)g)[tid];
    float o0 = d0*inv*gv.x, o1 = d1*inv*gv.y, o2 = d2*inv*gv.z, o3 = d3*inv*gv.w;
    *(uint2*)(g_xnh + row*NDIM + tid*4) = make_uint2(pk_hi(o0,o1), pk_hi(o2,o3));
}

// ---------------- null kv ----------------
__global__ void fill_null(const float* __restrict__ nkv)
{
    int idx = blockIdx.x * 256 + threadIdx.x;
    if (idx >= BH * RD) return;
    int bh = idx / RD, rd = idx % RD, d = rd & 63;
    g_kh[(size_t)bh * NKV * RD + rd] = __float2half_rn(nkv[d]);
    g_vf[(size_t)bh * NKV * RD + rd] = nkv[64 + d];
}

// ---------------- v transpose: [bh, j, rd] fp32 -> [bh, rd, j] hi/lo fp16 ----------------
__global__ void transpose_v()
{
    __shared__ float t[32][33];
    int z = blockIdx.z;
    int j0 = blockIdx.x * 32, rd0 = blockIdx.y * 32;
    const float* src = g_vf + (size_t)z * NKV * RD;
#pragma unroll
    for (int k = 0; k < 4; k++) {
        int jj = threadIdx.y + k * 8;
        int j = j0 + jj;
        t[jj][threadIdx.x] = (j < NKV) ? src[(size_t)j * RD + rd0 + threadIdx.x] : 0.f;
    }
    __syncthreads();
#pragma unroll
    for (int k = 0; k < 4; k++) {
        int dd = threadIdx.y + k * 8;
        float v = t[threadIdx.x][dd];
        size_t off = ((size_t)z * RD + rd0 + dd) * LDAT + j0 + threadIdx.x;
        split1(v, &g_vth[off], &g_vtl[off]);
    }
}

// ---------------- pb-relax softmax -> attn hi/lo fp16 (pad zeros) ----------------
__global__ void softmax_kernel()
{
    __shared__ float red[8];
    size_t gi = blockIdx.x;
    const float* p = g_sim + gi * LDSIM;
    __half* ah = g_ath + gi * LDAT;
    __half* al = g_atl + gi * LDAT;
    int tid = threadIdx.x;  // 256
    float vals[5];
    float mx = -1e30f;
#pragma unroll
    for (int it = 0; it < 5; it++) {
        int idx = tid + it * 256;
        float v = (idx < NKV) ? p[idx] : -1e30f;
        vals[it] = v; mx = fmaxf(mx, v);
    }
#pragma unroll
    for (int o = 16; o; o >>= 1) mx = fmaxf(mx, __shfl_xor_sync(0xffffffffu, mx, o));
    if ((tid & 31) == 0) red[tid >> 5] = mx;
    __syncthreads();
    float bm = red[0];
#pragma unroll
    for (int w = 1; w < 8; w++) bm = fmaxf(bm, red[w]);
    __syncthreads();
    float s = 0.f;
#pragma unroll
    for (int it = 0; it < 5; it++) {
        int idx = tid + it * 256;
        float e = (idx < NKV) ? expf((vals[it] - bm) * 128.0f) : 0.f;
        vals[it] = e; s += e;
    }
#pragma unroll
    for (int o = 16; o; o >>= 1) s += __shfl_xor_sync(0xffffffffu, s, o);
    if ((tid & 31) == 0) red[tid >> 5] = s;
    __syncthreads();
    float bs = red[0]+red[1]+red[2]+red[3]+red[4]+red[5]+red[6]+red[7];
    float inv = 1.0f / bs;
#pragma unroll
    for (int it = 0; it < 5; it++) {
        int idx = tid + it * 256;
        if (idx < LDAT) split1(vals[it] * inv, &ah[idx], &al[idx]);
    }
}

// ---------------- final LN ----------------
__global__ void ln_final(const float* __restrict__ g, float* __restrict__ yout)
{
    __shared__ float red1[4], red2[4];
    size_t row = blockIdx.x;
    int tid = threadIdx.x;
    float4 v = ((const float4*)(g_out + row * NDIM))[tid];
    float s = v.x + v.y + v.z + v.w;
#pragma unroll
    for (int o = 16; o; o >>= 1) s += __shfl_xor_sync(0xffffffffu, s, o);
    if ((tid & 31) == 0) red1[tid >> 5] = s;
    __syncthreads();
    float mean = (red1[0] + red1[1] + red1[2] + red1[3]) * (1.0f / NDIM);
    float d0 = v.x - mean, d1 = v.y - mean, d2 = v.z - mean, d3 = v.w - mean;
    float ss = d0*d0 + d1*d1 + d2*d2 + d3*d3;
#pragma unroll
    for (int o = 16; o; o >>= 1) ss += __shfl_xor_sync(0xffffffffu, ss, o);
    if ((tid & 31) == 0) red2[tid >> 5] = ss;
    __syncthreads();
    float var = (red2[0] + red2[1] + red2[2] + red2[3]) * (1.0f / NDIM);
    float inv = rsqrtf(var + 1e-5f);
    float4 gv = ((const float4*)g)[tid];
    ((float4*)(yout + row * NDIM))[tid] =
        make_float4(d0*inv*gv.x, d1*inv*gv.y, d2*inv*gv.z, d3*inv*gv.w);
}

// ---------------- launch ----------------
extern "C" void kernel_launch(void* const* d_in, const int* in_sizes, int n_in,
                              void* d_out, int out_size)
{
    const float* x        = (const float*)d_in[0];
    const float* context  = (const float*)d_in[1];
    const float* norm_g   = (const float*)d_in[2];
    const float* to_q_w   = (const float*)d_in[3];
    const float* to_kv_w  = (const float*)d_in[4];
    const float* null_kv  = (const float*)d_in[5];
    const float* to_out_w = (const float*)d_in[6];
    const float* out_ng   = (const float*)d_in[7];
    float* out = (float*)d_out;

    static bool attr_done = false;
    if (!attr_done) {
        cudaFuncSetAttribute(gemm_hmma<GQPROJ>, cudaFuncAttributeMaxDynamicSharedMemorySize, GEMM_SMEM);
        cudaFuncSetAttribute(gemm_hmma<GKPROJ>, cudaFuncAttributeMaxDynamicSharedMemorySize, GEMM_SMEM);
        cudaFuncSetAttribute(gemm_hmma<GVPROJ>, cudaFuncAttributeMaxDynamicSharedMemorySize, GEMM_SMEM);
        cudaFuncSetAttribute(gemm_hmma<GSIM>,   cudaFuncAttributeMaxDynamicSharedMemorySize, GEMM_SMEM);
        cudaFuncSetAttribute(gemm_hmma<GAV>,    cudaFuncAttributeMaxDynamicSharedMemorySize, GEMM_SMEM);
        cudaFuncSetAttribute(gemm_hmma<GOPROJ>, cudaFuncAttributeMaxDynamicSharedMemorySize, GEMM_SMEM);
        attr_done = true;
    }

    __half *wqh, *wql, *wkvh, *wkvl, *woh, *wol, *ctxh, *ctxl;
    cudaGetSymbolAddress((void**)&wqh,  g_wqh);  cudaGetSymbolAddress((void**)&wql,  g_wql);
    cudaGetSymbolAddress((void**)&wkvh, g_wkvh); cudaGetSymbolAddress((void**)&wkvl, g_wkvl);
    cudaGetSymbolAddress((void**)&woh,  g_woh);  cudaGetSymbolAddress((void**)&wol,  g_wol);
    cudaGetSymbolAddress((void**)&ctxh, g_ctxh); cudaGetSymbolAddress((void**)&ctxl, g_ctxl);

    // 0. conversions to hi/lo fp16
    conv_hilo<<<(NROWS*NDIM/4 + 255)/256, 256>>>(context, ctxh, ctxl, NROWS*NDIM/4);
    conv_hilo<<<(512*512/4 + 255)/256, 256>>>(to_q_w,  wqh,  wql,  512*512/4);
    conv_hilo<<<(1024*512/4 + 255)/256, 256>>>(to_kv_w, wkvh, wkvl, 1024*512/4);
    conv_hilo<<<(512*512/4 + 255)/256, 256>>>(to_out_w, woh,  wol,  512*512/4);
    // 1. xn = LN(x) -> hi
    ln_in<<<NROWS, 128>>>(x, norm_g);
    // 2. q = xn @ Wq^T (hi-only) -> q fp16 [bh,i,rd]
    gemm_hmma<GQPROJ><<<dim3(512/128, NROWS/128, 1), 256, GEMM_SMEM>>>();
    // 3a. k = ctx @ Wk^T (hi-only) -> k fp16 [bh,j+1,rd]
    gemm_hmma<GKPROJ><<<dim3(512/128, NROWS/128, 1), 256, GEMM_SMEM>>>();
    // 3b. v = ctx @ Wv^T (3-term) -> v fp32 [bh,j+1,rd]
    gemm_hmma<GVPROJ><<<dim3(512/128, NROWS/128, 1), 256, GEMM_SMEM>>>();
    // 4. null kv row 0
    fill_null<<<(BH*RD + 255)/256, 256>>>(null_kv);
    // 5. sim = (q @ k^T) * scale (hi-only) -> fp32 [bh,i,1040]
    gemm_hmma<GSIM><<<dim3((NKV + 127)/128, NS/128, BH), 256, GEMM_SMEM>>>();
    // 6. softmax -> attn hi/lo [bh,i,1088] (zero pad)
    softmax_kernel<<<BH * NS, 256>>>();
    // 7. v transpose -> v_t hi/lo [bh,rd,1088] (zero pad)
    transpose_v<<<dim3(LDAT/32, RD/32, BH), dim3(32, 8)>>>();
    // 8. o = attn @ v (3-term) -> o hi/lo [b,n,r,(h d)]
    gemm_hmma<GAV><<<dim3(RD/128, NS/128, BH), 256, GEMM_SMEM>>>();
    // 9. out = o @ Wout^T (3-term) -> fp32 g_out
    gemm_hmma<GOPROJ><<<dim3(512/128, NROWS/128, 1), 256, GEMM_SMEM>>>();
    // 10. final LN -> d_out
    ln_final<<<NROWS, 128>>>(out_ng, out);
    (void)in_sizes; (void)n_in; (void)out_size;
}

// round 7
// speedup vs baseline: 1.7022x; 1.7022x over previous
#include <cuda_runtime.h>
#include <cuda_fp16.h>
#include <cstdint>

#define NB 4
#define NS 1024
#define NR 12
#define NDIM 512
#define NH 8
#define ND 64
#define NROWS (NB*NS*NR)        /* 49152 */
#define NKV (NS+1)              /* 1025  */
#define LDSIM 1040              /* fp32 sim ld */
#define LDAT 1056               /* fp16 attn / v_t ld (mult of 32) */
#define RD (NR*ND)              /* 768 */
#define BH (NB*NH)              /* 32 */

// smem: per stage, A 128x40 halves + B 128x40 halves (k-slab 32)
#define LDS 40
#define ASTG (128*LDS)              /* 5120 halves */
#define STG  (2*ASTG)               /* 10240 halves per stage */
#define GEMM_SMEM (2*STG*2)         /* 40960 bytes */

// ---------------- scratch ----------------
__device__ __half g_xnh [(size_t)NROWS * NDIM];
__device__ __half g_ctxh[(size_t)NROWS * NDIM];
__device__ __half g_ctxl[(size_t)NROWS * NDIM];
__device__ __half g_wqh [512*512];
__device__ __half g_wkvh[1024*512], g_wkvl[1024*512];
__device__ __half g_woh [512*512],  g_wol [512*512];
__device__ __half g_qh  [(size_t)BH * NS * RD];
__device__ __half g_kh  [(size_t)BH * NKV * RD];
__device__ float  g_vf  [(size_t)BH * NKV * RD];
__device__ __half g_vth [(size_t)BH * RD * LDAT];
__device__ float  g_sim [(size_t)BH * NS * LDSIM];
__device__ __half g_ath [(size_t)BH * NS * LDAT];
__device__ __half g_atl [(size_t)BH * NS * LDAT];
__device__ __half g_oh  [(size_t)NROWS * NDIM];
__device__ __half g_ol  [(size_t)NROWS * NDIM];
__device__ float  g_out [(size_t)NROWS * NDIM];

// ---------------- helpers ----------------
__device__ __forceinline__ uint32_t smem_u32(const void* p) {
    uint32_t a;
    asm("{ .reg .u64 t; cvta.to.shared.u64 t, %1; cvt.u32.u64 %0, t; }" : "=r"(a) : "l"(p));
    return a;
}
__device__ __forceinline__ void ldsm4(uint32_t* r, uint32_t addr) {
    asm volatile("ldmatrix.sync.aligned.m8n8.x4.shared.b16 {%0,%1,%2,%3}, [%4];"
                 : "=r"(r[0]), "=r"(r[1]), "=r"(r[2]), "=r"(r[3]) : "r"(addr));
}
__device__ __forceinline__ void mma16816(float* c, const uint32_t* a, uint32_t b0, uint32_t b1) {
    asm volatile("mma.sync.aligned.m16n8k16.row.col.f32.f16.f16.f32 "
                 "{%0,%1,%2,%3}, {%4,%5,%6,%7}, {%8,%9}, {%0,%1,%2,%3};"
                 : "+f"(c[0]), "+f"(c[1]), "+f"(c[2]), "+f"(c[3])
                 : "r"(a[0]), "r"(a[1]), "r"(a[2]), "r"(a[3]), "r"(b0), "r"(b1));
}
__device__ __forceinline__ uint32_t pk_hi(float a, float b) {
    __half2 t = __floats2half2_rn(a, b);
    return *(uint32_t*)&t;
}
__device__ __forceinline__ uint32_t pk_lo(float a, float b) {
    float ha = __half2float(__float2half_rn(a));
    float hb = __half2float(__float2half_rn(b));
    __half2 t = __floats2half2_rn(a - ha, b - hb);
    return *(uint32_t*)&t;
}
__device__ __forceinline__ void split1(float v, __half* ph, __half* pl) {
    __half h = __float2half_rn(v);
    *ph = h; *pl = __float2half_rn(v - __half2float(h));
}

// ------- HMMA GEMM: D[m,n] = sum_k A[m,k]*B[n,k]; NREG regions along K -------
// region 0: Ah*Bh   region 1: Al*Bh   region 2: Ah*Bl
#define GQPROJ 0
#define GKPROJ 1
#define GVPROJ 2
#define GSIM   3
#define GAV    4
#define GOPROJ 5

template<int MODE>
__global__ __launch_bounds__(256, 2) void gemm_hmma()
{
    extern __shared__ __half sh[];
    const int tid = threadIdx.x, lane = tid & 31, wid = tid >> 5;
    const int m0 = blockIdx.y * 128, n0 = blockIdx.x * 128;

    constexpr int NREG = (MODE==GVPROJ || MODE==GOPROJ) ? 3 :
                         (MODE==GAV) ? 2 : 1;
    constexpr int Nn   = MODE==GSIM ? NKV : MODE==GAV ? RD : 512;
    constexpr int K    = MODE==GSIM ? RD : MODE==GAV ? LDAT : 512;
    constexpr int SPR  = K / 32;
    constexpr int S    = NREG * SPR;

    const __half *Ah, *Al, *Bh, *Bl;
    if constexpr (MODE == GQPROJ)      { Ah=g_xnh;  Al=g_xnh;  Bh=g_wqh;  Bl=g_wqh; }
    else if constexpr (MODE == GKPROJ) { Ah=g_ctxh; Al=g_ctxh; Bh=g_wkvh; Bl=g_wkvh; }
    else if constexpr (MODE == GVPROJ) { Ah=g_ctxh; Al=g_ctxl;
                                         Bh=g_wkvh + 512*512; Bl=g_wkvl + 512*512; }
    else if constexpr (MODE == GSIM) {
        size_t z = blockIdx.z;
        Ah=g_qh + z*(size_t)NS*RD;  Al=Ah;
        Bh=g_kh + z*(size_t)NKV*RD; Bl=Bh;
    } else if constexpr (MODE == GAV) {
        size_t z = blockIdx.z;
        Ah=g_ath + z*(size_t)NS*LDAT; Al=g_atl + z*(size_t)NS*LDAT;
        Bh=g_vth + z*(size_t)RD*LDAT; Bl=Bh;
    } else                             { Ah=g_oh;   Al=g_ol;   Bh=g_woh;  Bl=g_wol; }

    // warp tiling: 2 (m) x 4 (n); warp tile 64m x 32n
    const int m0w = (wid & 1) * 64;
    const int n0w = (wid >> 1) * 32;
    const int lrow = tid >> 2;              // 0..63
    const int lc   = (tid & 3) * 8;         // half offset within 32

    const uint32_t smb = smem_u32(sh);
    const uint32_t aAddr = smb + (uint32_t)(((m0w + (lane & 15)) * LDS + ((lane >> 4) << 3)) * 2);
    const uint32_t bAddr = smb + (uint32_t)((ASTG + (n0w + (lane & 15)) * LDS + ((lane >> 4) << 3)) * 2);

    float acc[4][4][4] = {};
    uint4 pa0, pa1, pb0, pb1;

    auto ldslab = [&](int s) {
        const int rg = s / SPR;
        const int k0 = (s - rg * SPR) * 32;
        const __half* Ap = (rg == 1) ? Al : Ah;
        const __half* Bp = (rg == 2) ? Bl : Bh;
        pa0 = *(const uint4*)(Ap + (size_t)(m0 + lrow)      * K + k0 + lc);
        pa1 = *(const uint4*)(Ap + (size_t)(m0 + lrow + 64) * K + k0 + lc);
        const uint4 z4 = make_uint4(0u,0u,0u,0u);
        pb0 = (n0 + lrow      < Nn) ? *(const uint4*)(Bp + (size_t)(n0 + lrow)      * K + k0 + lc) : z4;
        pb1 = (n0 + lrow + 64 < Nn) ? *(const uint4*)(Bp + (size_t)(n0 + lrow + 64) * K + k0 + lc) : z4;
    };
    auto stslab = [&](int buf) {
        __half* st = sh + buf * STG;
        *(uint4*)(st + lrow * LDS + lc)        = pa0;
        *(uint4*)(st + (lrow + 64) * LDS + lc) = pa1;
        *(uint4*)(st + ASTG + lrow * LDS + lc)        = pb0;
        *(uint4*)(st + ASTG + (lrow + 64) * LDS + lc) = pb1;
    };
    auto compute = [&](int buf) {
        const uint32_t aB = aAddr + buf * (STG * 2);
        const uint32_t bB = bAddr + buf * (STG * 2);
#pragma unroll
        for (int k16 = 0; k16 < 2; k16++) {
            uint32_t a[4][4], b[2][4];
#pragma unroll
            for (int mf = 0; mf < 4; mf++) ldsm4(a[mf], aB + mf * (16*LDS*2) + k16 * 32);
#pragma unroll
            for (int nf = 0; nf < 2; nf++) ldsm4(b[nf], bB + nf * (16*LDS*2) + k16 * 32);
#pragma unroll
            for (int mf = 0; mf < 4; mf++)
#pragma unroll
                for (int j = 0; j < 4; j++)
                    mma16816(acc[mf][j], a[mf], b[j>>1][j&1], b[j>>1][(j&1)+2]);
        }
    };

    // R5-proven two-barrier pipeline
    ldslab(0);
    stslab(0);
    __syncthreads();
    for (int s = 0; s < S; s++) {
        if (s + 1 < S) ldslab(s + 1);
        compute(s & 1);
        __syncthreads();
        if (s + 1 < S) {
            stslab((s + 1) & 1);
            __syncthreads();
        }
    }

    // epilogue
    const int rbase = m0 + m0w + (lane >> 2);
    const int cbase = n0 + n0w + (lane & 3) * 2;
#pragma unroll
    for (int mf = 0; mf < 4; mf++)
#pragma unroll
    for (int half = 0; half < 2; half++) {
        const int gm = rbase + mf * 16 + half * 8;
#pragma unroll
        for (int j = 0; j < 4; j++) {
            const int gn = cbase + j * 8;
            const float v0 = acc[mf][j][half * 2 + 0];
            const float v1 = acc[mf][j][half * 2 + 1];
            if constexpr (MODE == GQPROJ) {
                int rr = gm % NR, t = gm / NR; int nn = t & (NS-1); int b = t >> 10;
                int h = gn >> 6, d = gn & 63;
                size_t off = ((size_t)((b << 3) + h) * NS + nn) * RD + rr * ND + d;
                *(uint32_t*)(g_qh + off) = pk_hi(v0, v1);
            } else if constexpr (MODE == GKPROJ) {
                int rr = gm % NR, t = gm / NR; int nn = t & (NS-1); int b = t >> 10;
                int h = gn >> 6, d = gn & 63;
                size_t off = ((size_t)((b << 3) + h) * NKV + nn + 1) * RD + rr * ND + d;
                *(uint32_t*)(g_kh + off) = pk_hi(v0, v1);
            } else if constexpr (MODE == GVPROJ) {
                int rr = gm % NR, t = gm / NR; int nn = t & (NS-1); int b = t >> 10;
                int h = gn >> 6, d = gn & 63;
                size_t off = ((size_t)((b << 3) + h) * NKV + nn + 1) * RD + rr * ND + d;
                *(float2*)(g_vf + off) = make_float2(v0, v1);
            } else if constexpr (MODE == GSIM) {
                const float QS = (0.125f / 128.0f) * 0.28867513459481287f;
                size_t z = blockIdx.z;
                float* cr = g_sim + (z * NS + gm) * (size_t)LDSIM + gn;
                if (gn + 1 < NKV)      *(float2*)cr = make_float2(v0 * QS, v1 * QS);
                else if (gn < NKV)     cr[0] = v0 * QS;
            } else if constexpr (MODE == GAV) {
                size_t z = blockIdx.z; int b = (int)(z >> 3), h = (int)(z & 7);
                int rr = gn >> 6, d = gn & 63;
                size_t off = (((size_t)b * NS + gm) * NR + rr) * NDIM + h * ND + d;
                *(uint32_t*)(g_oh + off) = pk_hi(v0, v1);
                *(uint32_t*)(g_ol + off) = pk_lo(v0, v1);
            } else {
                *(float2*)(g_out + (size_t)gm * NDIM + gn) = make_float2(v0, v1);
            }
        }
    }
}

// ---------------- fp32 -> hi/lo fp16 ----------------
__global__ void conv_hilo(const float* __restrict__ src,
                          __half* __restrict__ hi, __half* __restrict__ lo, int n4)
{
    int i = blockIdx.x * 256 + threadIdx.x;
    if (i >= n4) return;
    float4 v = ((const float4*)src)[i];
    *(uint2*)(hi + 4*(size_t)i) = make_uint2(pk_hi(v.x, v.y), pk_hi(v.z, v.w));
    if (lo)
        *(uint2*)(lo + 4*(size_t)i) = make_uint2(pk_lo(v.x, v.y), pk_lo(v.z, v.w));
}

// ---------------- LN(x) -> xn hi ----------------
__global__ void ln_in(const float* __restrict__ xin, const float* __restrict__ g)
{
    __shared__ float red1[4], red2[4];
    size_t row = blockIdx.x;
    int tid = threadIdx.x;                 // 128
    float4 v = ((const float4*)(xin + row * NDIM))[tid];
    float s = v.x + v.y + v.z + v.w;
#pragma unroll
    for (int o = 16; o; o >>= 1) s += __shfl_xor_sync(0xffffffffu, s, o);
    if ((tid & 31) == 0) red1[tid >> 5] = s;
    __syncthreads();
    float mean = (red1[0] + red1[1] + red1[2] + red1[3]) * (1.0f / NDIM);
    float d0 = v.x - mean, d1 = v.y - mean, d2 = v.z - mean, d3 = v.w - mean;
    float ss = d0*d0 + d1*d1 + d2*d2 + d3*d3;
#pragma unroll
    for (int o = 16; o; o >>= 1) ss += __shfl_xor_sync(0xffffffffu, ss, o);
    if ((tid & 31) == 0) red2[tid >> 5] = ss;
    __syncthreads();
    float var = (red2[0] + red2[1] + red2[2] + red2[3]) * (1.0f / NDIM);
    float inv = rsqrtf(var + 1e-5f);
    float4 gv = ((const float4*)g)[tid];
    float o0 = d0*inv*gv.x, o1 = d1*inv*gv.y, o2 = d2*inv*gv.z, o3 = d3*inv*gv.w;
    *(uint2*)(g_xnh + row*NDIM + tid*4) = make_uint2(pk_hi(o0,o1), pk_hi(o2,o3));
}

// ---------------- null kv ----------------
__global__ void fill_null(const float* __restrict__ nkv)
{
    int idx = blockIdx.x * 256 + threadIdx.x;
    if (idx >= BH * RD) return;
    int bh = idx / RD, rd = idx % RD, d = rd & 63;
    g_kh[(size_t)bh * NKV * RD + rd] = __float2half_rn(nkv[d]);
    g_vf[(size_t)bh * NKV * RD + rd] = nkv[64 + d];
}

// ---------------- v transpose: [bh, j, rd] fp32 -> [bh, rd, j] fp16 (hi only) ----------
__global__ void transpose_v()
{
    __shared__ float t[32][33];
    int z = blockIdx.z;
    int j0 = blockIdx.x * 32, rd0 = blockIdx.y * 32;
    const float* src = g_vf + (size_t)z * NKV * RD;
#pragma unroll
    for (int k = 0; k < 4; k++) {
        int jj = threadIdx.y + k * 8;
        int j = j0 + jj;
        t[jj][threadIdx.x] = (j < NKV) ? src[(size_t)j * RD + rd0 + threadIdx.x] : 0.f;
    }
    __syncthreads();
#pragma unroll
    for (int k = 0; k < 4; k++) {
        int dd = threadIdx.y + k * 8;
        size_t off = ((size_t)z * RD + rd0 + dd) * LDAT + j0 + threadIdx.x;
        g_vth[off] = __float2half_rn(t[threadIdx.x][dd]);
    }
}

// ---------------- pb-relax softmax -> attn hi/lo fp16 (pad zeros) ----------------
__global__ void softmax_kernel()
{
    __shared__ float red[8];
    size_t gi = blockIdx.x;
    const float* p = g_sim + gi * LDSIM;
    __half* ah = g_ath + gi * LDAT;
    __half* al = g_atl + gi * LDAT;
    int tid = threadIdx.x;  // 256
    float vals[5];
    float mx = -1e30f;
#pragma unroll
    for (int it = 0; it < 5; it++) {
        int idx = tid + it * 256;
        float v = (idx < NKV) ? p[idx] : -1e30f;
        vals[it] = v; mx = fmaxf(mx, v);
    }
#pragma unroll
    for (int o = 16; o; o >>= 1) mx = fmaxf(mx, __shfl_xor_sync(0xffffffffu, mx, o));
    if ((tid & 31) == 0) red[tid >> 5] = mx;
    __syncthreads();
    float bm = red[0];
#pragma unroll
    for (int w = 1; w < 8; w++) bm = fmaxf(bm, red[w]);
    __syncthreads();
    float s = 0.f;
#pragma unroll
    for (int it = 0; it < 5; it++) {
        int idx = tid + it * 256;
        float e = (idx < NKV) ? expf((vals[it] - bm) * 128.0f) : 0.f;
        vals[it] = e; s += e;
    }
#pragma unroll
    for (int o = 16; o; o >>= 1) s += __shfl_xor_sync(0xffffffffu, s, o);
    if ((tid & 31) == 0) red[tid >> 5] = s;
    __syncthreads();
    float bs = red[0]+red[1]+red[2]+red[3]+red[4]+red[5]+red[6]+red[7];
    float inv = 1.0f / bs;
#pragma unroll
    for (int it = 0; it < 5; it++) {
        int idx = tid + it * 256;
        if (idx < LDAT) split1(vals[it] * inv, &ah[idx], &al[idx]);
    }
}

// ---------------- final LN ----------------
__global__ void ln_final(const float* __restrict__ g, float* __restrict__ yout)
{
    __shared__ float red1[4], red2[4];
    size_t row = blockIdx.x;
    int tid = threadIdx.x;
    float4 v = ((const float4*)(g_out + row * NDIM))[tid];
    float s = v.x + v.y + v.z + v.w;
#pragma unroll
    for (int o = 16; o; o >>= 1) s += __shfl_xor_sync(0xffffffffu, s, o);
    if ((tid & 31) == 0) red1[tid >> 5] = s;
    __syncthreads();
    float mean = (red1[0] + red1[1] + red1[2] + red1[3]) * (1.0f / NDIM);
    float d0 = v.x - mean, d1 = v.y - mean, d2 = v.z - mean, d3 = v.w - mean;
    float ss = d0*d0 + d1*d1 + d2*d2 + d3*d3;
#pragma unroll
    for (int o = 16; o; o >>= 1) ss += __shfl_xor_sync(0xffffffffu, ss, o);
    if ((tid & 31) == 0) red2[tid >> 5] = ss;
    __syncthreads();
    float var = (red2[0] + red2[1] + red2[2] + red2[3]) * (1.0f / NDIM);
    float inv = rsqrtf(var + 1e-5f);
    float4 gv = ((const float4*)g)[tid];
    ((float4*)(yout + row * NDIM))[tid] =
        make_float4(d0*inv*gv.x, d1*inv*gv.y, d2*inv*gv.z, d3*inv*gv.w);
}

// ---------------- launch ----------------
extern "C" void kernel_launch(void* const* d_in, const int* in_sizes, int n_in,
                              void* d_out, int out_size)
{
    const float* x        = (const float*)d_in[0];
    const float* context  = (const float*)d_in[1];
    const float* norm_g   = (const float*)d_in[2];
    const float* to_q_w   = (const float*)d_in[3];
    const float* to_kv_w  = (const float*)d_in[4];
    const float* null_kv  = (const float*)d_in[5];
    const float* to_out_w = (const float*)d_in[6];
    const float* out_ng   = (const float*)d_in[7];
    float* out = (float*)d_out;

    static bool attr_done = false;
    if (!attr_done) {
        cudaFuncSetAttribute(gemm_hmma<GQPROJ>, cudaFuncAttributeMaxDynamicSharedMemorySize, GEMM_SMEM);
        cudaFuncSetAttribute(gemm_hmma<GKPROJ>, cudaFuncAttributeMaxDynamicSharedMemorySize, GEMM_SMEM);
        cudaFuncSetAttribute(gemm_hmma<GVPROJ>, cudaFuncAttributeMaxDynamicSharedMemorySize, GEMM_SMEM);
        cudaFuncSetAttribute(gemm_hmma<GSIM>,   cudaFuncAttributeMaxDynamicSharedMemorySize, GEMM_SMEM);
        cudaFuncSetAttribute(gemm_hmma<GAV>,    cudaFuncAttributeMaxDynamicSharedMemorySize, GEMM_SMEM);
        cudaFuncSetAttribute(gemm_hmma<GOPROJ>, cudaFuncAttributeMaxDynamicSharedMemorySize, GEMM_SMEM);
        attr_done = true;
    }

    __half *wqh, *wkvh, *wkvl, *woh, *wol, *ctxh, *ctxl;
    cudaGetSymbolAddress((void**)&wqh,  g_wqh);
    cudaGetSymbolAddress((void**)&wkvh, g_wkvh); cudaGetSymbolAddress((void**)&wkvl, g_wkvl);
    cudaGetSymbolAddress((void**)&woh,  g_woh);  cudaGetSymbolAddress((void**)&wol,  g_wol);
    cudaGetSymbolAddress((void**)&ctxh, g_ctxh); cudaGetSymbolAddress((void**)&ctxl, g_ctxl);

    // 0. conversions to hi/lo fp16
    conv_hilo<<<(NROWS*NDIM/4 + 255)/256, 256>>>(context, ctxh, ctxl, NROWS*NDIM/4);
    conv_hilo<<<(512*512/4 + 255)/256, 256>>>(to_q_w,  wqh,  nullptr, 512*512/4);
    conv_hilo<<<(1024*512/4 + 255)/256, 256>>>(to_kv_w, wkvh, wkvl, 1024*512/4);
    conv_hilo<<<(512*512/4 + 255)/256, 256>>>(to_out_w, woh,  wol,  512*512/4);
    // 1. xn = LN(x) -> hi
    ln_in<<<NROWS, 128>>>(x, norm_g);
    // 2. q = xn @ Wq^T (hi-only) -> q fp16 [bh,i,rd]
    gemm_hmma<GQPROJ><<<dim3(512/128, NROWS/128, 1), 256, GEMM_SMEM>>>();
    // 3a. k = ctx @ Wk^T (hi-only) -> k fp16 [bh,j+1,rd]
    gemm_hmma<GKPROJ><<<dim3(512/128, NROWS/128, 1), 256, GEMM_SMEM>>>();
    // 3b. v = ctx @ Wv^T (3-term) -> v fp32 [bh,j+1,rd]
    gemm_hmma<GVPROJ><<<dim3(512/128, NROWS/128, 1), 256, GEMM_SMEM>>>();
    // 4. null kv row 0
    fill_null<<<(BH*RD + 255)/256, 256>>>(null_kv);
    // 5. sim = (q @ k^T) * scale (hi-only) -> fp32 [bh,i,1040]
    gemm_hmma<GSIM><<<dim3((NKV + 127)/128, NS/128, BH), 256, GEMM_SMEM>>>();
    // 6. softmax -> attn hi/lo [bh,i,1056] (zero pad)
    softmax_kernel<<<BH * NS, 256>>>();
    // 7. v transpose -> v_t fp16 [bh,rd,1056] (zero pad)
    transpose_v<<<dim3(LDAT/32, RD/32, BH), dim3(32, 8)>>>();
    // 8. o = attn @ v (2-term) -> o hi/lo [b,n,r,(h d)]
    gemm_hmma<GAV><<<dim3(RD/128, NS/128, BH), 256, GEMM_SMEM>>>();
    // 9. out = o @ Wout^T (3-term) -> fp32 g_out
    gemm_hmma<GOPROJ><<<dim3(512/128, NROWS/128, 1), 256, GEMM_SMEM>>>();
    // 10. final LN -> d_out
    ln_final<<<NROWS, 128>>>(out_ng, out);
    (void)in_sizes; (void)n_in; (void)out_size;
}

// round 8
// speedup vs baseline: 1.7456x; 1.0255x over previous
#include <cuda_runtime.h>
#include <cuda_fp16.h>
#include <cstdint>

#define NB 4
#define NS 1024
#define NR 12
#define NDIM 512
#define NH 8
#define ND 64
#define NROWS (NB*NS*NR)        /* 49152 */
#define NKV (NS+1)              /* 1025  */
#define LDSIM 1040              /* fp32 sim ld */
#define LDAT 1056               /* fp16 attn / v_t ld (mult of 32) */
#define RD (NR*ND)              /* 768 */
#define BH (NB*NH)              /* 32 */

// smem: per stage, A 128x40 halves + B 128x40 halves (k-slab 32), 3 stages
#define LDS 40
#define ASTG (128*LDS)              /* 5120 halves */
#define STG  (2*ASTG)               /* 10240 halves per stage */
#define STAGES 3
#define GEMM_SMEM (STAGES*STG*2)    /* 61440 bytes */

// ---------------- scratch ----------------
__device__ __half g_xnh [(size_t)NROWS * NDIM];
__device__ __half g_ctxh[(size_t)NROWS * NDIM];
__device__ __half g_ctxl[(size_t)NROWS * NDIM];
__device__ __half g_wqh [512*512];
__device__ __half g_wkvh[1024*512], g_wkvl[1024*512];
__device__ __half g_woh [512*512],  g_wol [512*512];
__device__ __half g_qh  [(size_t)BH * NS * RD];
__device__ __half g_kh  [(size_t)BH * NKV * RD];
__device__ float  g_vf  [(size_t)BH * NKV * RD];
__device__ __half g_vth [(size_t)BH * RD * LDAT];
__device__ float  g_sim [(size_t)BH * NS * LDSIM];
__device__ __half g_ath [(size_t)BH * NS * LDAT];
__device__ __half g_atl [(size_t)BH * NS * LDAT];
__device__ __half g_oh  [(size_t)NROWS * NDIM];
__device__ __half g_ol  [(size_t)NROWS * NDIM];
__device__ float  g_out [(size_t)NROWS * NDIM];

// ---------------- helpers ----------------
__device__ __forceinline__ uint32_t smem_u32(const void* p) {
    uint32_t a;
    asm("{ .reg .u64 t; cvta.to.shared.u64 t, %1; cvt.u32.u64 %0, t; }" : "=r"(a) : "l"(p));
    return a;
}
__device__ __forceinline__ void ldsm4(uint32_t* r, uint32_t addr) {
    asm volatile("ldmatrix.sync.aligned.m8n8.x4.shared.b16 {%0,%1,%2,%3}, [%4];"
                 : "=r"(r[0]), "=r"(r[1]), "=r"(r[2]), "=r"(r[3]) : "r"(addr));
}
__device__ __forceinline__ void mma16816(float* c, const uint32_t* a, uint32_t b0, uint32_t b1) {
    asm volatile("mma.sync.aligned.m16n8k16.row.col.f32.f16.f16.f32 "
                 "{%0,%1,%2,%3}, {%4,%5,%6,%7}, {%8,%9}, {%0,%1,%2,%3};"
                 : "+f"(c[0]), "+f"(c[1]), "+f"(c[2]), "+f"(c[3])
                 : "r"(a[0]), "r"(a[1]), "r"(a[2]), "r"(a[3]), "r"(b0), "r"(b1));
}
__device__ __forceinline__ void cp16(uint32_t dst, const void* src, bool pred) {
    int sz = pred ? 16 : 0;
    asm volatile("cp.async.cg.shared.global [%0], [%1], 16, %2;"
                 :: "r"(dst), "l"(src), "r"(sz) : "memory");
}
#define CP_COMMIT() asm volatile("cp.async.commit_group;" ::: "memory")
__device__ __forceinline__ uint32_t pk_hi(float a, float b) {
    __half2 t = __floats2half2_rn(a, b);
    return *(uint32_t*)&t;
}
__device__ __forceinline__ uint32_t pk_lo(float a, float b) {
    float ha = __half2float(__float2half_rn(a));
    float hb = __half2float(__float2half_rn(b));
    __half2 t = __floats2half2_rn(a - ha, b - hb);
    return *(uint32_t*)&t;
}
__device__ __forceinline__ void split1(float v, __half* ph, __half* pl) {
    __half h = __float2half_rn(v);
    *ph = h; *pl = __float2half_rn(v - __half2float(h));
}

// ------- HMMA GEMM: D[m,n] = sum_k A[m,k]*B[n,k]; NREG regions along K -------
// region 0: Ah*Bh   region 1: Al*Bh   region 2: Ah*Bl
#define GQPROJ 0
#define GKPROJ 1
#define GVPROJ 2
#define GSIM   3
#define GAV    4
#define GOPROJ 5

template<int MODE>
__global__ __launch_bounds__(256, 2) void gemm_hmma()
{
    extern __shared__ __half sh[];
    const int tid = threadIdx.x, lane = tid & 31, wid = tid >> 5;
    const int m0 = blockIdx.y * 128, n0 = blockIdx.x * 128;

    constexpr int NREG = (MODE==GVPROJ || MODE==GOPROJ) ? 3 :
                         (MODE==GAV) ? 2 : 1;
    constexpr int Nn   = MODE==GSIM ? NKV : MODE==GAV ? RD : 512;
    constexpr int K    = MODE==GSIM ? RD : MODE==GAV ? LDAT : 512;
    constexpr int SPR  = K / 32;
    constexpr int S    = NREG * SPR;

    const __half *Ah, *Al, *Bh, *Bl;
    if constexpr (MODE == GQPROJ)      { Ah=g_xnh;  Al=g_xnh;  Bh=g_wqh;  Bl=g_wqh; }
    else if constexpr (MODE == GKPROJ) { Ah=g_ctxh; Al=g_ctxh; Bh=g_wkvh; Bl=g_wkvh; }
    else if constexpr (MODE == GVPROJ) { Ah=g_ctxh; Al=g_ctxl;
                                         Bh=g_wkvh + 512*512; Bl=g_wkvl + 512*512; }
    else if constexpr (MODE == GSIM) {
        size_t z = blockIdx.z;
        Ah=g_qh + z*(size_t)NS*RD;  Al=Ah;
        Bh=g_kh + z*(size_t)NKV*RD; Bl=Bh;
    } else if constexpr (MODE == GAV) {
        size_t z = blockIdx.z;
        Ah=g_ath + z*(size_t)NS*LDAT; Al=g_atl + z*(size_t)NS*LDAT;
        Bh=g_vth + z*(size_t)RD*LDAT; Bl=Bh;
    } else                             { Ah=g_oh;   Al=g_ol;   Bh=g_woh;  Bl=g_wol; }

    // warp tiling: 2 (m) x 4 (n); warp tile 64m x 32n
    const int m0w = (wid & 1) * 64;
    const int n0w = (wid >> 1) * 32;
    const int lrow = tid >> 2;              // 0..63
    const int lc   = (tid & 3) * 8;         // half offset within 32

    const uint32_t smb = smem_u32(sh);
    const uint32_t aAddr = smb + (uint32_t)(((m0w + (lane & 15)) * LDS + ((lane >> 4) << 3)) * 2);
    const uint32_t bAddr = smb + (uint32_t)((ASTG + (n0w + (lane & 15)) * LDS + ((lane >> 4) << 3)) * 2);

    float acc[4][4][4] = {};

    // async loader: one 32-deep k-slab into stage s%STAGES
    auto load_async = [&](int s) {
        const int rg = s / SPR;
        const int k0 = (s - rg * SPR) * 32;
        const __half* Ap = (rg == 1) ? Al : Ah;
        const __half* Bp = (rg == 2) ? Bl : Bh;
        const uint32_t st = smb + (uint32_t)((s % STAGES) * STG * 2);
        cp16(st + (uint32_t)((lrow * LDS + lc) * 2),
             Ap + (size_t)(m0 + lrow) * K + k0 + lc, true);
        cp16(st + (uint32_t)(((lrow + 64) * LDS + lc) * 2),
             Ap + (size_t)(m0 + lrow + 64) * K + k0 + lc, true);
        cp16(st + (uint32_t)((ASTG + lrow * LDS + lc) * 2),
             Bp + (size_t)(n0 + lrow) * K + k0 + lc, n0 + lrow < Nn);
        cp16(st + (uint32_t)((ASTG + (lrow + 64) * LDS + lc) * 2),
             Bp + (size_t)(n0 + lrow + 64) * K + k0 + lc, n0 + lrow + 64 < Nn);
        CP_COMMIT();
    };
    auto compute = [&](int buf) {
        const uint32_t aB = aAddr + buf * (STG * 2);
        const uint32_t bB = bAddr + buf * (STG * 2);
#pragma unroll
        for (int k16 = 0; k16 < 2; k16++) {
            uint32_t a[4][4], b[2][4];
#pragma unroll
            for (int mf = 0; mf < 4; mf++) ldsm4(a[mf], aB + mf * (16*LDS*2) + k16 * 32);
#pragma unroll
            for (int nf = 0; nf < 2; nf++) ldsm4(b[nf], bB + nf * (16*LDS*2) + k16 * 32);
#pragma unroll
            for (int mf = 0; mf < 4; mf++)
#pragma unroll
                for (int j = 0; j < 4; j++)
                    mma16816(acc[mf][j], a[mf], b[j>>1][j&1], b[j>>1][(j&1)+2]);
        }
    };

    // 3-stage cp.async pipeline, one barrier per slab
    load_async(0);
    if (S > 1) load_async(1);
    for (int s = 0; s < S; s++) {
        if (s + 1 < S) {
            asm volatile("cp.async.wait_group 1;" ::: "memory");
        } else {
            asm volatile("cp.async.wait_group 0;" ::: "memory");
        }
        __syncthreads();
        compute(s % STAGES);
        if (s + 2 < S) load_async(s + 2);
    }

    // epilogue
    const int rbase = m0 + m0w + (lane >> 2);
    const int cbase = n0 + n0w + (lane & 3) * 2;
#pragma unroll
    for (int mf = 0; mf < 4; mf++)
#pragma unroll
    for (int half = 0; half < 2; half++) {
        const int gm = rbase + mf * 16 + half * 8;
#pragma unroll
        for (int j = 0; j < 4; j++) {
            const int gn = cbase + j * 8;
            const float v0 = acc[mf][j][half * 2 + 0];
            const float v1 = acc[mf][j][half * 2 + 1];
            if constexpr (MODE == GQPROJ) {
                int rr = gm % NR, t = gm / NR; int nn = t & (NS-1); int b = t >> 10;
                int h = gn >> 6, d = gn & 63;
                size_t off = ((size_t)((b << 3) + h) * NS + nn) * RD + rr * ND + d;
                *(uint32_t*)(g_qh + off) = pk_hi(v0, v1);
            } else if constexpr (MODE == GKPROJ) {
                int rr = gm % NR, t = gm / NR; int nn = t & (NS-1); int b = t >> 10;
                int h = gn >> 6, d = gn & 63;
                size_t off = ((size_t)((b << 3) + h) * NKV + nn + 1) * RD + rr * ND + d;
                *(uint32_t*)(g_kh + off) = pk_hi(v0, v1);
            } else if constexpr (MODE == GVPROJ) {
                int rr = gm % NR, t = gm / NR; int nn = t & (NS-1); int b = t >> 10;
                int h = gn >> 6, d = gn & 63;
                size_t off = ((size_t)((b << 3) + h) * NKV + nn + 1) * RD + rr * ND + d;
                *(float2*)(g_vf + off) = make_float2(v0, v1);
            } else if constexpr (MODE == GSIM) {
                const float QS = (0.125f / 128.0f) * 0.28867513459481287f;
                size_t z = blockIdx.z;
                float* cr = g_sim + (z * NS + gm) * (size_t)LDSIM + gn;
                if (gn + 1 < NKV)      *(float2*)cr = make_float2(v0 * QS, v1 * QS);
                else if (gn < NKV)     cr[0] = v0 * QS;
            } else if constexpr (MODE == GAV) {
                size_t z = blockIdx.z; int b = (int)(z >> 3), h = (int)(z & 7);
                int rr = gn >> 6, d = gn & 63;
                size_t off = (((size_t)b * NS + gm) * NR + rr) * NDIM + h * ND + d;
                *(uint32_t*)(g_oh + off) = pk_hi(v0, v1);
                *(uint32_t*)(g_ol + off) = pk_lo(v0, v1);
            } else {
                *(float2*)(g_out + (size_t)gm * NDIM + gn) = make_float2(v0, v1);
            }
        }
    }
}

// ---------------- fp32 -> hi/lo fp16 ----------------
__global__ void conv_hilo(const float* __restrict__ src,
                          __half* __restrict__ hi, __half* __restrict__ lo, int n4)
{
    int i = blockIdx.x * 256 + threadIdx.x;
    if (i >= n4) return;
    float4 v = ((const float4*)src)[i];
    *(uint2*)(hi + 4*(size_t)i) = make_uint2(pk_hi(v.x, v.y), pk_hi(v.z, v.w));
    if (lo)
        *(uint2*)(lo + 4*(size_t)i) = make_uint2(pk_lo(v.x, v.y), pk_lo(v.z, v.w));
}

// ---------------- LN(x) -> xn hi ----------------
__global__ void ln_in(const float* __restrict__ xin, const float* __restrict__ g)
{
    __shared__ float red1[4], red2[4];
    size_t row = blockIdx.x;
    int tid = threadIdx.x;                 // 128
    float4 v = ((const float4*)(xin + row * NDIM))[tid];
    float s = v.x + v.y + v.z + v.w;
#pragma unroll
    for (int o = 16; o; o >>= 1) s += __shfl_xor_sync(0xffffffffu, s, o);
    if ((tid & 31) == 0) red1[tid >> 5] = s;
    __syncthreads();
    float mean = (red1[0] + red1[1] + red1[2] + red1[3]) * (1.0f / NDIM);
    float d0 = v.x - mean, d1 = v.y - mean, d2 = v.z - mean, d3 = v.w - mean;
    float ss = d0*d0 + d1*d1 + d2*d2 + d3*d3;
#pragma unroll
    for (int o = 16; o; o >>= 1) ss += __shfl_xor_sync(0xffffffffu, ss, o);
    if ((tid & 31) == 0) red2[tid >> 5] = ss;
    __syncthreads();
    float var = (red2[0] + red2[1] + red2[2] + red2[3]) * (1.0f / NDIM);
    float inv = rsqrtf(var + 1e-5f);
    float4 gv = ((const float4*)g)[tid];
    float o0 = d0*inv*gv.x, o1 = d1*inv*gv.y, o2 = d2*inv*gv.z, o3 = d3*inv*gv.w;
    *(uint2*)(g_xnh + row*NDIM + tid*4) = make_uint2(pk_hi(o0,o1), pk_hi(o2,o3));
}

// ---------------- null kv ----------------
__global__ void fill_null(const float* __restrict__ nkv)
{
    int idx = blockIdx.x * 256 + threadIdx.x;
    if (idx >= BH * RD) return;
    int bh = idx / RD, rd = idx % RD, d = rd & 63;
    g_kh[(size_t)bh * NKV * RD + rd] = __float2half_rn(nkv[d]);
    g_vf[(size_t)bh * NKV * RD + rd] = nkv[64 + d];
}

// ---------------- v transpose: [bh, j, rd] fp32 -> [bh, rd, j] fp16 (hi only) ----------
__global__ void transpose_v()
{
    __shared__ float t[32][33];
    int z = blockIdx.z;
    int j0 = blockIdx.x * 32, rd0 = blockIdx.y * 32;
    const float* src = g_vf + (size_t)z * NKV * RD;
#pragma unroll
    for (int k = 0; k < 4; k++) {
        int jj = threadIdx.y + k * 8;
        int j = j0 + jj;
        t[jj][threadIdx.x] = (j < NKV) ? src[(size_t)j * RD + rd0 + threadIdx.x] : 0.f;
    }
    __syncthreads();
#pragma unroll
    for (int k = 0; k < 4; k++) {
        int dd = threadIdx.y + k * 8;
        size_t off = ((size_t)z * RD + rd0 + dd) * LDAT + j0 + threadIdx.x;
        g_vth[off] = __float2half_rn(t[threadIdx.x][dd]);
    }
}

// ---------------- pb-relax softmax -> attn hi/lo fp16 (pad zeros) ----------------
__global__ void softmax_kernel()
{
    __shared__ float red[8];
    size_t gi = blockIdx.x;
    const float* p = g_sim + gi * LDSIM;
    __half* ah = g_ath + gi * LDAT;
    __half* al = g_atl + gi * LDAT;
    int tid = threadIdx.x;  // 256
    float vals[5];
    float mx = -1e30f;
#pragma unroll
    for (int it = 0; it < 5; it++) {
        int idx = tid + it * 256;
        float v = (idx < NKV) ? p[idx] : -1e30f;
        vals[it] = v; mx = fmaxf(mx, v);
    }
#pragma unroll
    for (int o = 16; o; o >>= 1) mx = fmaxf(mx, __shfl_xor_sync(0xffffffffu, mx, o));
    if ((tid & 31) == 0) red[tid >> 5] = mx;
    __syncthreads();
    float bm = red[0];
#pragma unroll
    for (int w = 1; w < 8; w++) bm = fmaxf(bm, red[w]);
    __syncthreads();
    float s = 0.f;
#pragma unroll
    for (int it = 0; it < 5; it++) {
        int idx = tid + it * 256;
        float e = (idx < NKV) ? expf((vals[it] - bm) * 128.0f) : 0.f;
        vals[it] = e; s += e;
    }
#pragma unroll
    for (int o = 16; o; o >>= 1) s += __shfl_xor_sync(0xffffffffu, s, o);
    if ((tid & 31) == 0) red[tid >> 5] = s;
    __syncthreads();
    float bs = red[0]+red[1]+red[2]+red[3]+red[4]+red[5]+red[6]+red[7];
    float inv = 1.0f / bs;
#pragma unroll
    for (int it = 0; it < 5; it++) {
        int idx = tid + it * 256;
        if (idx < LDAT) split1(vals[it] * inv, &ah[idx], &al[idx]);
    }
}

// ---------------- final LN ----------------
__global__ void ln_final(const float* __restrict__ g, float* __restrict__ yout)
{
    __shared__ float red1[4], red2[4];
    size_t row = blockIdx.x;
    int tid = threadIdx.x;
    float4 v = ((const float4*)(g_out + row * NDIM))[tid];
    float s = v.x + v.y + v.z + v.w;
#pragma unroll
    for (int o = 16; o; o >>= 1) s += __shfl_xor_sync(0xffffffffu, s, o);
    if ((tid & 31) == 0) red1[tid >> 5] = s;
    __syncthreads();
    float mean = (red1[0] + red1[1] + red1[2] + red1[3]) * (1.0f / NDIM);
    float d0 = v.x - mean, d1 = v.y - mean, d2 = v.z - mean, d3 = v.w - mean;
    float ss = d0*d0 + d1*d1 + d2*d2 + d3*d3;
#pragma unroll
    for (int o = 16; o; o >>= 1) ss += __shfl_xor_sync(0xffffffffu, ss, o);
    if ((tid & 31) == 0) red2[tid >> 5] = ss;
    __syncthreads();
    float var = (red2[0] + red2[1] + red2[2] + red2[3]) * (1.0f / NDIM);
    float inv = rsqrtf(var + 1e-5f);
    float4 gv = ((const float4*)g)[tid];
    ((float4*)(yout + row * NDIM))[tid] =
        make_float4(d0*inv*gv.x, d1*inv*gv.y, d2*inv*gv.z, d3*inv*gv.w);
}

// ---------------- launch ----------------
extern "C" void kernel_launch(void* const* d_in, const int* in_sizes, int n_in,
                              void* d_out, int out_size)
{
    const float* x        = (const float*)d_in[0];
    const float* context  = (const float*)d_in[1];
    const float* norm_g   = (const float*)d_in[2];
    const float* to_q_w   = (const float*)d_in[3];
    const float* to_kv_w  = (const float*)d_in[4];
    const float* null_kv  = (const float*)d_in[5];
    const float* to_out_w = (const float*)d_in[6];
    const float* out_ng   = (const float*)d_in[7];
    float* out = (float*)d_out;

    static bool attr_done = false;
    if (!attr_done) {
        cudaFuncSetAttribute(gemm_hmma<GQPROJ>, cudaFuncAttributeMaxDynamicSharedMemorySize, GEMM_SMEM);
        cudaFuncSetAttribute(gemm_hmma<GKPROJ>, cudaFuncAttributeMaxDynamicSharedMemorySize, GEMM_SMEM);
        cudaFuncSetAttribute(gemm_hmma<GVPROJ>, cudaFuncAttributeMaxDynamicSharedMemorySize, GEMM_SMEM);
        cudaFuncSetAttribute(gemm_hmma<GSIM>,   cudaFuncAttributeMaxDynamicSharedMemorySize, GEMM_SMEM);
        cudaFuncSetAttribute(gemm_hmma<GAV>,    cudaFuncAttributeMaxDynamicSharedMemorySize, GEMM_SMEM);
        cudaFuncSetAttribute(gemm_hmma<GOPROJ>, cudaFuncAttributeMaxDynamicSharedMemorySize, GEMM_SMEM);
        attr_done = true;
    }

    __half *wqh, *wkvh, *wkvl, *woh, *wol, *ctxh, *ctxl;
    cudaGetSymbolAddress((void**)&wqh,  g_wqh);
    cudaGetSymbolAddress((void**)&wkvh, g_wkvh); cudaGetSymbolAddress((void**)&wkvl, g_wkvl);
    cudaGetSymbolAddress((void**)&woh,  g_woh);  cudaGetSymbolAddress((void**)&wol,  g_wol);
    cudaGetSymbolAddress((void**)&ctxh, g_ctxh); cudaGetSymbolAddress((void**)&ctxl, g_ctxl);

    // 0. conversions to hi/lo fp16
    conv_hilo<<<(NROWS*NDIM/4 + 255)/256, 256>>>(context, ctxh, ctxl, NROWS*NDIM/4);
    conv_hilo<<<(512*512/4 + 255)/256, 256>>>(to_q_w,  wqh,  nullptr, 512*512/4);
    conv_hilo<<<(1024*512/4 + 255)/256, 256>>>(to_kv_w, wkvh, wkvl, 1024*512/4);
    conv_hilo<<<(512*512/4 + 255)/256, 256>>>(to_out_w, woh,  wol,  512*512/4);
    // 1. xn = LN(x) -> hi
    ln_in<<<NROWS, 128>>>(x, norm_g);
    // 2. q = xn @ Wq^T (hi-only) -> q fp16 [bh,i,rd]
    gemm_hmma<GQPROJ><<<dim3(512/128, NROWS/128, 1), 256, GEMM_SMEM>>>();
    // 3a. k = ctx @ Wk^T (hi-only) -> k fp16 [bh,j+1,rd]
    gemm_hmma<GKPROJ><<<dim3(512/128, NROWS/128, 1), 256, GEMM_SMEM>>>();
    // 3b. v = ctx @ Wv^T (3-term) -> v fp32 [bh,j+1,rd]
    gemm_hmma<GVPROJ><<<dim3(512/128, NROWS/128, 1), 256, GEMM_SMEM>>>();
    // 4. null kv row 0
    fill_null<<<(BH*RD + 255)/256, 256>>>(null_kv);
    // 5. sim = (q @ k^T) * scale (hi-only) -> fp32 [bh,i,1040]
    gemm_hmma<GSIM><<<dim3((NKV + 127)/128, NS/128, BH), 256, GEMM_SMEM>>>();
    // 6. softmax -> attn hi/lo [bh,i,1056] (zero pad)
    softmax_kernel<<<BH * NS, 256>>>();
    // 7. v transpose -> v_t fp16 [bh,rd,1056] (zero pad)
    transpose_v<<<dim3(LDAT/32, RD/32, BH), dim3(32, 8)>>>();
    // 8. o = attn @ v (2-term) -> o hi/lo [b,n,r,(h d)]
    gemm_hmma<GAV><<<dim3(RD/128, NS/128, BH), 256, GEMM_SMEM>>>();
    // 9. out = o @ Wout^T (3-term) -> fp32 g_out
    gemm_hmma<GOPROJ><<<dim3(512/128, NROWS/128, 1), 256, GEMM_SMEM>>>();
    // 10. final LN -> d_out
    ln_final<<<NROWS, 128>>>(out_ng, out);
    (void)in_sizes; (void)n_in; (void)out_size;
}

// round 9
// speedup vs baseline: 1.9363x; 1.1092x over previous
#include <cuda_runtime.h>
#include <cuda_fp16.h>
#include <cstdint>

#define NB 4
#define NS 1024
#define NR 12
#define NDIM 512
#define NH 8
#define ND 64
#define NROWS (NB*NS*NR)        /* 49152 */
#define NKV (NS+1)              /* 1025  */
#define LDSIM 1040              /* fp32 sim ld */
#define LDAT 1056               /* fp16 attn / v_t ld (mult of 32) */
#define RD (NR*ND)              /* 768 */
#define BH (NB*NH)              /* 32 */

// smem: per stage, A 128x40 halves + B 128x40 halves (k-slab 32), 3 stages
#define LDS 40
#define ASTG (128*LDS)              /* 5120 halves */
#define STG  (2*ASTG)               /* 10240 halves per stage */
#define STAGES 3
#define GEMM_SMEM (STAGES*STG*2)    /* 61440 bytes */

// ---------------- scratch ----------------
__device__ __half g_xnh [(size_t)NROWS * NDIM];
__device__ __half g_ctxh[(size_t)NROWS * NDIM];
__device__ __half g_ctxl[(size_t)NROWS * NDIM];
__device__ __half g_wqh [512*512];
__device__ __half g_wkvh[1024*512];
__device__ __half g_woh [512*512];
__device__ __half g_qh  [(size_t)BH * NS * RD];
__device__ __half g_kh  [(size_t)BH * NS * RD];      // no null row (handled in softmax)
__device__ __half g_vhf [(size_t)BH * NKV * RD];     // fp16 v, null at row 0
__device__ __half g_vth [(size_t)BH * RD * LDAT];
__device__ float  g_sim [(size_t)BH * NS * LDSIM];   // col 0 unused (softmax computes it)
__device__ __half g_ath [(size_t)BH * NS * LDAT];
__device__ __half g_atl [(size_t)BH * NS * LDAT];
__device__ __half g_oh  [(size_t)NROWS * NDIM];
__device__ __half g_ol  [(size_t)NROWS * NDIM];
__device__ float  g_out [(size_t)NROWS * NDIM];

// ---------------- helpers ----------------
__device__ __forceinline__ uint32_t smem_u32(const void* p) {
    uint32_t a;
    asm("{ .reg .u64 t; cvta.to.shared.u64 t, %1; cvt.u32.u64 %0, t; }" : "=r"(a) : "l"(p));
    return a;
}
__device__ __forceinline__ void ldsm4(uint32_t* r, uint32_t addr) {
    asm volatile("ldmatrix.sync.aligned.m8n8.x4.shared.b16 {%0,%1,%2,%3}, [%4];"
                 : "=r"(r[0]), "=r"(r[1]), "=r"(r[2]), "=r"(r[3]) : "r"(addr));
}
__device__ __forceinline__ void mma16816(float* c, const uint32_t* a, uint32_t b0, uint32_t b1) {
    asm volatile("mma.sync.aligned.m16n8k16.row.col.f32.f16.f16.f32 "
                 "{%0,%1,%2,%3}, {%4,%5,%6,%7}, {%8,%9}, {%0,%1,%2,%3};"
                 : "+f"(c[0]), "+f"(c[1]), "+f"(c[2]), "+f"(c[3])
                 : "r"(a[0]), "r"(a[1]), "r"(a[2]), "r"(a[3]), "r"(b0), "r"(b1));
}
__device__ __forceinline__ void cp16(uint32_t dst, const void* src, bool pred) {
    int sz = pred ? 16 : 0;
    asm volatile("cp.async.cg.shared.global [%0], [%1], 16, %2;"
                 :: "r"(dst), "l"(src), "r"(sz) : "memory");
}
#define CP_COMMIT() asm volatile("cp.async.commit_group;" ::: "memory")
__device__ __forceinline__ uint32_t pk_hi(float a, float b) {
    __half2 t = __floats2half2_rn(a, b);
    return *(uint32_t*)&t;
}
__device__ __forceinline__ uint32_t pk_lo(float a, float b) {
    float ha = __half2float(__float2half_rn(a));
    float hb = __half2float(__float2half_rn(b));
    __half2 t = __floats2half2_rn(a - ha, b - hb);
    return *(uint32_t*)&t;
}
__device__ __forceinline__ void split1(float v, __half* ph, __half* pl) {
    __half h = __float2half_rn(v);
    *ph = h; *pl = __float2half_rn(v - __half2float(h));
}

// ------- HMMA GEMM: D[m,n] = sum_k A[m,k]*B[n,k]; NREG regions along K -------
// region 0: Ah*Bh   region 1: Al*Bh   region 2: Ah*Bl
#define GQPROJ 0
#define GKPROJ 1
#define GVPROJ 2
#define GSIM   3
#define GAV    4
#define GOPROJ 5

template<int MODE>
__global__ __launch_bounds__(256, 2) void gemm_hmma()
{
    extern __shared__ __half sh[];
    const int tid = threadIdx.x, lane = tid & 31, wid = tid >> 5;
    const int m0 = blockIdx.y * 128, n0 = blockIdx.x * 128;

    constexpr int NREG = (MODE==GVPROJ || MODE==GAV || MODE==GOPROJ) ? 2 : 1;
    constexpr int Nn   = MODE==GSIM ? NS : MODE==GAV ? RD : 512;
    constexpr int K    = MODE==GSIM ? RD : MODE==GAV ? LDAT : 512;
    constexpr int SPR  = K / 32;
    constexpr int S    = NREG * SPR;

    const __half *Ah, *Al, *Bh;
    if constexpr (MODE == GQPROJ)      { Ah=g_xnh;  Al=g_xnh;  Bh=g_wqh; }
    else if constexpr (MODE == GKPROJ) { Ah=g_ctxh; Al=g_ctxh; Bh=g_wkvh; }
    else if constexpr (MODE == GVPROJ) { Ah=g_ctxh; Al=g_ctxl; Bh=g_wkvh + 512*512; }
    else if constexpr (MODE == GSIM) {
        size_t z = blockIdx.z;
        Ah=g_qh + z*(size_t)NS*RD;  Al=Ah;
        Bh=g_kh + z*(size_t)NS*RD;
    } else if constexpr (MODE == GAV) {
        size_t z = blockIdx.z;
        Ah=g_ath + z*(size_t)NS*LDAT; Al=g_atl + z*(size_t)NS*LDAT;
        Bh=g_vth + z*(size_t)RD*LDAT;
    } else                             { Ah=g_oh;   Al=g_ol;   Bh=g_woh; }

    // warp tiling: 2 (m) x 4 (n); warp tile 64m x 32n
    const int m0w = (wid & 1) * 64;
    const int n0w = (wid >> 1) * 32;
    const int lrow = tid >> 2;              // 0..63
    const int lc   = (tid & 3) * 8;         // half offset within 32

    const uint32_t smb = smem_u32(sh);
    const uint32_t aAddr = smb + (uint32_t)(((m0w + (lane & 15)) * LDS + ((lane >> 4) << 3)) * 2);
    const uint32_t bAddr = smb + (uint32_t)((ASTG + (n0w + (lane & 15)) * LDS + ((lane >> 4) << 3)) * 2);

    float acc[4][4][4] = {};

    // async loader: one 32-deep k-slab into stage s%STAGES
    auto load_async = [&](int s) {
        const int rg = s / SPR;
        const int k0 = (s - rg * SPR) * 32;
        const __half* Ap = (rg == 1) ? Al : Ah;
        const __half* Bp = Bh;
        const uint32_t st = smb + (uint32_t)((s % STAGES) * STG * 2);
        cp16(st + (uint32_t)((lrow * LDS + lc) * 2),
             Ap + (size_t)(m0 + lrow) * K + k0 + lc, true);
        cp16(st + (uint32_t)(((lrow + 64) * LDS + lc) * 2),
             Ap + (size_t)(m0 + lrow + 64) * K + k0 + lc, true);
        cp16(st + (uint32_t)((ASTG + lrow * LDS + lc) * 2),
             Bp + (size_t)(n0 + lrow) * K + k0 + lc, n0 + lrow < Nn);
        cp16(st + (uint32_t)((ASTG + (lrow + 64) * LDS + lc) * 2),
             Bp + (size_t)(n0 + lrow + 64) * K + k0 + lc, n0 + lrow + 64 < Nn);
        CP_COMMIT();
    };
    auto compute = [&](int buf) {
        const uint32_t aB = aAddr + buf * (STG * 2);
        const uint32_t bB = bAddr + buf * (STG * 2);
#pragma unroll
        for (int k16 = 0; k16 < 2; k16++) {
            uint32_t a[4][4], b[2][4];
#pragma unroll
            for (int mf = 0; mf < 4; mf++) ldsm4(a[mf], aB + mf * (16*LDS*2) + k16 * 32);
#pragma unroll
            for (int nf = 0; nf < 2; nf++) ldsm4(b[nf], bB + nf * (16*LDS*2) + k16 * 32);
#pragma unroll
            for (int mf = 0; mf < 4; mf++)
#pragma unroll
                for (int j = 0; j < 4; j++)
                    mma16816(acc[mf][j], a[mf], b[j>>1][j&1], b[j>>1][(j&1)+2]);
        }
    };

    // 3-stage cp.async pipeline, one barrier per slab
    load_async(0);
    if (S > 1) load_async(1);
    for (int s = 0; s < S; s++) {
        if (s + 1 < S) {
            asm volatile("cp.async.wait_group 1;" ::: "memory");
        } else {
            asm volatile("cp.async.wait_group 0;" ::: "memory");
        }
        __syncthreads();
        compute(s % STAGES);
        if (s + 2 < S) load_async(s + 2);
    }

    // epilogue
    const int rbase = m0 + m0w + (lane >> 2);
    const int cbase = n0 + n0w + (lane & 3) * 2;
#pragma unroll
    for (int mf = 0; mf < 4; mf++)
#pragma unroll
    for (int half = 0; half < 2; half++) {
        const int gm = rbase + mf * 16 + half * 8;
#pragma unroll
        for (int j = 0; j < 4; j++) {
            const int gn = cbase + j * 8;
            const float v0 = acc[mf][j][half * 2 + 0];
            const float v1 = acc[mf][j][half * 2 + 1];
            if constexpr (MODE == GQPROJ) {
                int rr = gm % NR, t = gm / NR; int nn = t & (NS-1); int b = t >> 10;
                int h = gn >> 6, d = gn & 63;
                size_t off = ((size_t)((b << 3) + h) * NS + nn) * RD + rr * ND + d;
                *(uint32_t*)(g_qh + off) = pk_hi(v0, v1);
            } else if constexpr (MODE == GKPROJ) {
                int rr = gm % NR, t = gm / NR; int nn = t & (NS-1); int b = t >> 10;
                int h = gn >> 6, d = gn & 63;
                size_t off = ((size_t)((b << 3) + h) * NS + nn) * RD + rr * ND + d;
                *(uint32_t*)(g_kh + off) = pk_hi(v0, v1);
            } else if constexpr (MODE == GVPROJ) {
                int rr = gm % NR, t = gm / NR; int nn = t & (NS-1); int b = t >> 10;
                int h = gn >> 6, d = gn & 63;
                size_t off = ((size_t)((b << 3) + h) * NKV + nn + 1) * RD + rr * ND + d;
                *(uint32_t*)(g_vhf + off) = pk_hi(v0, v1);
            } else if constexpr (MODE == GSIM) {
                // columns shifted by +1 (col 0 = null token, computed in softmax)
                const float QS = (0.125f / 128.0f) * 0.28867513459481287f;
                size_t z = blockIdx.z;
                float* cr = g_sim + (z * NS + gm) * (size_t)LDSIM + gn + 1;
                cr[0] = v0 * QS;
                cr[1] = v1 * QS;
            } else if constexpr (MODE == GAV) {
                size_t z = blockIdx.z; int b = (int)(z >> 3), h = (int)(z & 7);
                int rr = gn >> 6, d = gn & 63;
                size_t off = (((size_t)b * NS + gm) * NR + rr) * NDIM + h * ND + d;
                *(uint32_t*)(g_oh + off) = pk_hi(v0, v1);
                *(uint32_t*)(g_ol + off) = pk_lo(v0, v1);
            } else {
                *(float2*)(g_out + (size_t)gm * NDIM + gn) = make_float2(v0, v1);
            }
        }
    }
}

// ---------------- fp32 -> hi/lo fp16 ----------------
__global__ void conv_hilo(const float* __restrict__ src,
                          __half* __restrict__ hi, __half* __restrict__ lo, int n4)
{
    int i = blockIdx.x * 256 + threadIdx.x;
    if (i >= n4) return;
    float4 v = ((const float4*)src)[i];
    *(uint2*)(hi + 4*(size_t)i) = make_uint2(pk_hi(v.x, v.y), pk_hi(v.z, v.w));
    if (lo)
        *(uint2*)(lo + 4*(size_t)i) = make_uint2(pk_lo(v.x, v.y), pk_lo(v.z, v.w));
}

// ---------------- LN(x) -> xn hi ----------------
__global__ void ln_in(const float* __restrict__ xin, const float* __restrict__ g)
{
    __shared__ float red1[4], red2[4];
    size_t row = blockIdx.x;
    int tid = threadIdx.x;                 // 128
    float4 v = ((const float4*)(xin + row * NDIM))[tid];
    float s = v.x + v.y + v.z + v.w;
#pragma unroll
    for (int o = 16; o; o >>= 1) s += __shfl_xor_sync(0xffffffffu, s, o);
    if ((tid & 31) == 0) red1[tid >> 5] = s;
    __syncthreads();
    float mean = (red1[0] + red1[1] + red1[2] + red1[3]) * (1.0f / NDIM);
    float d0 = v.x - mean, d1 = v.y - mean, d2 = v.z - mean, d3 = v.w - mean;
    float ss = d0*d0 + d1*d1 + d2*d2 + d3*d3;
#pragma unroll
    for (int o = 16; o; o >>= 1) ss += __shfl_xor_sync(0xffffffffu, ss, o);
    if ((tid & 31) == 0) red2[tid >> 5] = ss;
    __syncthreads();
    float var = (red2[0] + red2[1] + red2[2] + red2[3]) * (1.0f / NDIM);
    float inv = rsqrtf(var + 1e-5f);
    float4 gv = ((const float4*)g)[tid];
    float o0 = d0*inv*gv.x, o1 = d1*inv*gv.y, o2 = d2*inv*gv.z, o3 = d3*inv*gv.w;
    *(uint2*)(g_xnh + row*NDIM + tid*4) = make_uint2(pk_hi(o0,o1), pk_hi(o2,o3));
}

// ---------------- null v ----------------
__global__ void fill_null(const float* __restrict__ nkv)
{
    int idx = blockIdx.x * 256 + threadIdx.x;
    if (idx >= BH * RD) return;
    int bh = idx / RD, rd = idx % RD, d = rd & 63;
    g_vhf[(size_t)bh * NKV * RD + rd] = __float2half_rn(nkv[64 + d]);
}

// ---------------- v transpose: [bh, j, rd] fp16 -> [bh, rd, j] fp16 ----------
__global__ void transpose_v()
{
    __shared__ __half t[32][34];
    int z = blockIdx.z;
    int j0 = blockIdx.x * 32, rd0 = blockIdx.y * 32;
    const __half* src = g_vhf + (size_t)z * NKV * RD;
#pragma unroll
    for (int k = 0; k < 4; k++) {
        int jj = threadIdx.y + k * 8;
        int j = j0 + jj;
        t[jj][threadIdx.x] = (j < NKV) ? src[(size_t)j * RD + rd0 + threadIdx.x]
                                       : __float2half_rn(0.f);
    }
    __syncthreads();
#pragma unroll
    for (int k = 0; k < 4; k++) {
        int dd = threadIdx.y + k * 8;
        size_t off = ((size_t)z * RD + rd0 + dd) * LDAT + j0 + threadIdx.x;
        g_vth[off] = t[threadIdx.x][dd];
    }
}

// ---- pb-relax softmax; computes null-token sim (col 0) itself -> attn hi/lo ----
__global__ void softmax_kernel(const float* __restrict__ nkv)
{
    __shared__ float red[8];
    __shared__ float s0sh;
    size_t gi = blockIdx.x;
    const float* p = g_sim + gi * LDSIM;
    __half* ah = g_ath + gi * LDAT;
    __half* al = g_atl + gi * LDAT;
    int tid = threadIdx.x;  // 256

    // null-token similarity: dot(q_row, null_k broadcast over r) * QS
    {
        const float QS = (0.125f / 128.0f) * 0.28867513459481287f;
        const __half* qrow = g_qh + gi * RD;
        float part = 0.f;
#pragma unroll
        for (int it = 0; it < 3; it++) {
            int idx = tid + it * 256;
            part += __half2float(qrow[idx]) * nkv[idx & 63];
        }
#pragma unroll
        for (int o = 16; o; o >>= 1) part += __shfl_xor_sync(0xffffffffu, part, o);
        if ((tid & 31) == 0) red[tid >> 5] = part;
        __syncthreads();
        if (tid == 0)
            s0sh = (red[0]+red[1]+red[2]+red[3]+red[4]+red[5]+red[6]+red[7]) * QS;
        __syncthreads();
    }
    const float s0 = s0sh;

    float vals[5];
    float mx = -1e30f;
#pragma unroll
    for (int it = 0; it < 5; it++) {
        int idx = tid + it * 256;
        float v = (idx < NKV) ? ((idx == 0) ? s0 : p[idx]) : -1e30f;
        vals[it] = v; mx = fmaxf(mx, v);
    }
#pragma unroll
    for (int o = 16; o; o >>= 1) mx = fmaxf(mx, __shfl_xor_sync(0xffffffffu, mx, o));
    if ((tid & 31) == 0) red[tid >> 5] = mx;
    __syncthreads();
    float bm = red[0];
#pragma unroll
    for (int w = 1; w < 8; w++) bm = fmaxf(bm, red[w]);
    __syncthreads();
    float s = 0.f;
#pragma unroll
    for (int it = 0; it < 5; it++) {
        int idx = tid + it * 256;
        float e = (idx < NKV) ? expf((vals[it] - bm) * 128.0f) : 0.f;
        vals[it] = e; s += e;
    }
#pragma unroll
    for (int o = 16; o; o >>= 1) s += __shfl_xor_sync(0xffffffffu, s, o);
    if ((tid & 31) == 0) red[tid >> 5] = s;
    __syncthreads();
    float bs = red[0]+red[1]+red[2]+red[3]+red[4]+red[5]+red[6]+red[7];
    float inv = 1.0f / bs;
#pragma unroll
    for (int it = 0; it < 5; it++) {
        int idx = tid + it * 256;
        if (idx < LDAT) split1(vals[it] * inv, &ah[idx], &al[idx]);
    }
}

// ---------------- final LN ----------------
__global__ void ln_final(const float* __restrict__ g, float* __restrict__ yout)
{
    __shared__ float red1[4], red2[4];
    size_t row = blockIdx.x;
    int tid = threadIdx.x;
    float4 v = ((const float4*)(g_out + row * NDIM))[tid];
    float s = v.x + v.y + v.z + v.w;
#pragma unroll
    for (int o = 16; o; o >>= 1) s += __shfl_xor_sync(0xffffffffu, s, o);
    if ((tid & 31) == 0) red1[tid >> 5] = s;
    __syncthreads();
    float mean = (red1[0] + red1[1] + red1[2] + red1[3]) * (1.0f / NDIM);
    float d0 = v.x - mean, d1 = v.y - mean, d2 = v.z - mean, d3 = v.w - mean;
    float ss = d0*d0 + d1*d1 + d2*d2 + d3*d3;
#pragma unroll
    for (int o = 16; o; o >>= 1) ss += __shfl_xor_sync(0xffffffffu, ss, o);
    if ((tid & 31) == 0) red2[tid >> 5] = ss;
    __syncthreads();
    float var = (red2[0] + red2[1] + red2[2] + red2[3]) * (1.0f / NDIM);
    float inv = rsqrtf(var + 1e-5f);
    float4 gv = ((const float4*)g)[tid];
    ((float4*)(yout + row * NDIM))[tid] =
        make_float4(d0*inv*gv.x, d1*inv*gv.y, d2*inv*gv.z, d3*inv*gv.w);
}

// ---------------- launch ----------------
extern "C" void kernel_launch(void* const* d_in, const int* in_sizes, int n_in,
                              void* d_out, int out_size)
{
    const float* x        = (const float*)d_in[0];
    const float* context  = (const float*)d_in[1];
    const float* norm_g   = (const float*)d_in[2];
    const float* to_q_w   = (const float*)d_in[3];
    const float* to_kv_w  = (const float*)d_in[4];
    const float* null_kv  = (const float*)d_in[5];
    const float* to_out_w = (const float*)d_in[6];
    const float* out_ng   = (const float*)d_in[7];
    float* out = (float*)d_out;

    static bool attr_done = false;
    if (!attr_done) {
        cudaFuncSetAttribute(gemm_hmma<GQPROJ>, cudaFuncAttributeMaxDynamicSharedMemorySize, GEMM_SMEM);
        cudaFuncSetAttribute(gemm_hmma<GKPROJ>, cudaFuncAttributeMaxDynamicSharedMemorySize, GEMM_SMEM);
        cudaFuncSetAttribute(gemm_hmma<GVPROJ>, cudaFuncAttributeMaxDynamicSharedMemorySize, GEMM_SMEM);
        cudaFuncSetAttribute(gemm_hmma<GSIM>,   cudaFuncAttributeMaxDynamicSharedMemorySize, GEMM_SMEM);
        cudaFuncSetAttribute(gemm_hmma<GAV>,    cudaFuncAttributeMaxDynamicSharedMemorySize, GEMM_SMEM);
        cudaFuncSetAttribute(gemm_hmma<GOPROJ>, cudaFuncAttributeMaxDynamicSharedMemorySize, GEMM_SMEM);
        attr_done = true;
    }

    __half *wqh, *wkvh, *woh, *ctxh, *ctxl;
    cudaGetSymbolAddress((void**)&wqh,  g_wqh);
    cudaGetSymbolAddress((void**)&wkvh, g_wkvh);
    cudaGetSymbolAddress((void**)&woh,  g_woh);
    cudaGetSymbolAddress((void**)&ctxh, g_ctxh); cudaGetSymbolAddress((void**)&ctxl, g_ctxl);

    // 0. conversions to fp16 (ctx hi+lo; weights hi-only)
    conv_hilo<<<(NROWS*NDIM/4 + 255)/256, 256>>>(context, ctxh, ctxl, NROWS*NDIM/4);
    conv_hilo<<<(512*512/4 + 255)/256, 256>>>(to_q_w,  wqh,  nullptr, 512*512/4);
    conv_hilo<<<(1024*512/4 + 255)/256, 256>>>(to_kv_w, wkvh, nullptr, 1024*512/4);
    conv_hilo<<<(512*512/4 + 255)/256, 256>>>(to_out_w, woh,  nullptr, 512*512/4);
    // 1. xn = LN(x) -> hi
    ln_in<<<NROWS, 128>>>(x, norm_g);
    // 2. q = xn @ Wq^T (hi-only) -> q fp16 [bh,i,rd]
    gemm_hmma<GQPROJ><<<dim3(512/128, NROWS/128, 1), 256, GEMM_SMEM>>>();
    // 3a. k = ctx @ Wk^T (hi-only) -> k fp16 [bh,j,rd] (no null row)
    gemm_hmma<GKPROJ><<<dim3(512/128, NROWS/128, 1), 256, GEMM_SMEM>>>();
    // 3b. v = ctx @ Wv^T (2-term) -> v fp16 [bh,j+1,rd]
    gemm_hmma<GVPROJ><<<dim3(512/128, NROWS/128, 1), 256, GEMM_SMEM>>>();
    // 4. null v row 0
    fill_null<<<(BH*RD + 255)/256, 256>>>(null_kv);
    // 5. sim[:,1:] = (q @ k^T) * scale (hi-only) -> fp32 [bh,i,1040]
    gemm_hmma<GSIM><<<dim3(NS/128, NS/128, BH), 256, GEMM_SMEM>>>();
    // 6. softmax (computes sim col 0 itself) -> attn hi/lo [bh,i,1056]
    softmax_kernel<<<BH * NS, 256>>>(null_kv);
    // 7. v transpose -> v_t fp16 [bh,rd,1056] (zero pad)
    transpose_v<<<dim3(LDAT/32, RD/32, BH), dim3(32, 8)>>>();
    // 8. o = attn @ v (2-term) -> o hi/lo [b,n,r,(h d)]
    gemm_hmma<GAV><<<dim3(RD/128, NS/128, BH), 256, GEMM_SMEM>>>();
    // 9. out = o @ Wout^T (2-term) -> fp32 g_out
    gemm_hmma<GOPROJ><<<dim3(512/128, NROWS/128, 1), 256, GEMM_SMEM>>>();
    // 10. final LN -> d_out
    ln_final<<<NROWS, 128>>>(out_ng, out);
    (void)in_sizes; (void)n_in; (void)out_size;
}

// round 10
// speedup vs baseline: 2.4993x; 1.2908x over previous
#include <cuda_runtime.h>
#include <cuda_fp16.h>
#include <cstdint>

#define NB 4
#define NS 1024
#define NR 12
#define NDIM 512
#define NH 8
#define ND 64
#define NROWS (NB*NS*NR)        /* 49152 */
#define NKV (NS+1)              /* 1025  */
#define LDSIM 1040              /* fp32 sim ld */
#define LDAT 1056               /* fp16 attn / v_t ld (mult of 32) */
#define RD (NR*ND)              /* 768 */
#define BH (NB*NH)              /* 32 */

// smem: per stage, A 128x40 halves + B 128x40 halves (k-slab 32), 3 stages
#define LDS 40
#define ASTG (128*LDS)              /* 5120 halves */
#define STG  (2*ASTG)               /* 10240 halves per stage */
#define STAGES 3
#define GEMM_SMEM (STAGES*STG*2)    /* 61440 bytes */

// ---------------- scratch ----------------
__device__ __half g_xnh [(size_t)NROWS * NDIM];
__device__ __half g_ctxh[(size_t)NROWS * NDIM];
__device__ __half g_ctxl[(size_t)NROWS * NDIM];
__device__ __half g_wqh [512*512];
__device__ __half g_wkvh[1024*512];
__device__ __half g_woh [512*512];
__device__ __half g_qh  [(size_t)BH * NS * RD];
__device__ __half g_kh  [(size_t)BH * NS * RD];      // no null row (handled in softmax)
__device__ __half g_vhf [(size_t)BH * NKV * RD];     // fp16 v, null at row 0
__device__ __half g_vth [(size_t)BH * RD * LDAT];
__device__ float  g_sim [(size_t)BH * NS * LDSIM];   // col 0 unused (softmax computes it)
__device__ __half g_ath [(size_t)BH * NS * LDAT];
__device__ __half g_oh  [(size_t)NROWS * NDIM];
__device__ float  g_out [(size_t)NROWS * NDIM];

// ---------------- helpers ----------------
__device__ __forceinline__ uint32_t smem_u32(const void* p) {
    uint32_t a;
    asm("{ .reg .u64 t; cvta.to.shared.u64 t, %1; cvt.u32.u64 %0, t; }" : "=r"(a) : "l"(p));
    return a;
}
__device__ __forceinline__ void ldsm4(uint32_t* r, uint32_t addr) {
    asm volatile("ldmatrix.sync.aligned.m8n8.x4.shared.b16 {%0,%1,%2,%3}, [%4];"
                 : "=r"(r[0]), "=r"(r[1]), "=r"(r[2]), "=r"(r[3]) : "r"(addr));
}
__device__ __forceinline__ void mma16816(float* c, const uint32_t* a, uint32_t b0, uint32_t b1) {
    asm volatile("mma.sync.aligned.m16n8k16.row.col.f32.f16.f16.f32 "
                 "{%0,%1,%2,%3}, {%4,%5,%6,%7}, {%8,%9}, {%0,%1,%2,%3};"
                 : "+f"(c[0]), "+f"(c[1]), "+f"(c[2]), "+f"(c[3])
                 : "r"(a[0]), "r"(a[1]), "r"(a[2]), "r"(a[3]), "r"(b0), "r"(b1));
}
__device__ __forceinline__ void cp16(uint32_t dst, const void* src, bool pred) {
    int sz = pred ? 16 : 0;
    asm volatile("cp.async.cg.shared.global [%0], [%1], 16, %2;"
                 :: "r"(dst), "l"(src), "r"(sz) : "memory");
}
#define CP_COMMIT() asm volatile("cp.async.commit_group;" ::: "memory")
__device__ __forceinline__ uint32_t pk_hi(float a, float b) {
    __half2 t = __floats2half2_rn(a, b);
    return *(uint32_t*)&t;
}
__device__ __forceinline__ uint32_t pk_lo(float a, float b) {
    float ha = __half2float(__float2half_rn(a));
    float hb = __half2float(__float2half_rn(b));
    __half2 t = __floats2half2_rn(a - ha, b - hb);
    return *(uint32_t*)&t;
}

// ------- HMMA GEMM: D[m,n] = sum_k A[m,k]*B[n,k]; NREG regions along K -------
// region 0: Ah*Bh   region 1: Al*Bh
#define GQPROJ 0
#define GKPROJ 1
#define GVPROJ 2
#define GSIM   3
#define GAV    4
#define GOPROJ 5

template<int MODE>
__global__ __launch_bounds__(256, 2) void gemm_hmma()
{
    extern __shared__ __half sh[];
    const int tid = threadIdx.x, lane = tid & 31, wid = tid >> 5;
    const int m0 = blockIdx.y * 128, n0 = blockIdx.x * 128;

    constexpr int NREG = (MODE==GVPROJ) ? 2 : 1;
    constexpr int Nn   = MODE==GSIM ? NS : MODE==GAV ? RD : 512;
    constexpr int K    = MODE==GSIM ? RD : MODE==GAV ? LDAT : 512;
    constexpr int SPR  = K / 32;
    constexpr int S    = NREG * SPR;

    const __half *Ah, *Al, *Bh;
    if constexpr (MODE == GQPROJ)      { Ah=g_xnh;  Al=g_xnh;  Bh=g_wqh; }
    else if constexpr (MODE == GKPROJ) { Ah=g_ctxh; Al=g_ctxh; Bh=g_wkvh; }
    else if constexpr (MODE == GVPROJ) { Ah=g_ctxh; Al=g_ctxl; Bh=g_wkvh + 512*512; }
    else if constexpr (MODE == GSIM) {
        size_t z = blockIdx.z;
        Ah=g_qh + z*(size_t)NS*RD;  Al=Ah;
        Bh=g_kh + z*(size_t)NS*RD;
    } else if constexpr (MODE == GAV) {
        size_t z = blockIdx.z;
        Ah=g_ath + z*(size_t)NS*LDAT; Al=Ah;
        Bh=g_vth + z*(size_t)RD*LDAT;
    } else                             { Ah=g_oh;   Al=g_oh;   Bh=g_woh; }

    // warp tiling: 2 (m) x 4 (n); warp tile 64m x 32n
    const int m0w = (wid & 1) * 64;
    const int n0w = (wid >> 1) * 32;
    const int lrow = tid >> 2;              // 0..63
    const int lc   = (tid & 3) * 8;         // half offset within 32

    const uint32_t smb = smem_u32(sh);
    const uint32_t aAddr = smb + (uint32_t)(((m0w + (lane & 15)) * LDS + ((lane >> 4) << 3)) * 2);
    const uint32_t bAddr = smb + (uint32_t)((ASTG + (n0w + (lane & 15)) * LDS + ((lane >> 4) << 3)) * 2);

    float acc[4][4][4] = {};

    // async loader: one 32-deep k-slab into stage s%STAGES
    auto load_async = [&](int s) {
        const int rg = s / SPR;
        const int k0 = (s - rg * SPR) * 32;
        const __half* Ap = (rg == 1) ? Al : Ah;
        const __half* Bp = Bh;
        const uint32_t st = smb + (uint32_t)((s % STAGES) * STG * 2);
        cp16(st + (uint32_t)((lrow * LDS + lc) * 2),
             Ap + (size_t)(m0 + lrow) * K + k0 + lc, true);
        cp16(st + (uint32_t)(((lrow + 64) * LDS + lc) * 2),
             Ap + (size_t)(m0 + lrow + 64) * K + k0 + lc, true);
        cp16(st + (uint32_t)((ASTG + lrow * LDS + lc) * 2),
             Bp + (size_t)(n0 + lrow) * K + k0 + lc, n0 + lrow < Nn);
        cp16(st + (uint32_t)((ASTG + (lrow + 64) * LDS + lc) * 2),
             Bp + (size_t)(n0 + lrow + 64) * K + k0 + lc, n0 + lrow + 64 < Nn);
        CP_COMMIT();
    };
    auto compute = [&](int buf) {
        const uint32_t aB = aAddr + buf * (STG * 2);
        const uint32_t bB = bAddr + buf * (STG * 2);
#pragma unroll
        for (int k16 = 0; k16 < 2; k16++) {
            uint32_t a[4][4], b[2][4];
#pragma unroll
            for (int mf = 0; mf < 4; mf++) ldsm4(a[mf], aB + mf * (16*LDS*2) + k16 * 32);
#pragma unroll
            for (int nf = 0; nf < 2; nf++) ldsm4(b[nf], bB + nf * (16*LDS*2) + k16 * 32);
#pragma unroll
            for (int mf = 0; mf < 4; mf++)
#pragma unroll
                for (int j = 0; j < 4; j++)
                    mma16816(acc[mf][j], a[mf], b[j>>1][j&1], b[j>>1][(j&1)+2]);
        }
    };

    // 3-stage cp.async pipeline, one barrier per slab
    load_async(0);
    if (S > 1) load_async(1);
    for (int s = 0; s < S; s++) {
        if (s + 1 < S) {
            asm volatile("cp.async.wait_group 1;" ::: "memory");
        } else {
            asm volatile("cp.async.wait_group 0;" ::: "memory");
        }
        __syncthreads();
        compute(s % STAGES);
        if (s + 2 < S) load_async(s + 2);
    }

    // epilogue
    const int rbase = m0 + m0w + (lane >> 2);
    const int cbase = n0 + n0w + (lane & 3) * 2;
#pragma unroll
    for (int mf = 0; mf < 4; mf++)
#pragma unroll
    for (int half = 0; half < 2; half++) {
        const int gm = rbase + mf * 16 + half * 8;
#pragma unroll
        for (int j = 0; j < 4; j++) {
            const int gn = cbase + j * 8;
            const float v0 = acc[mf][j][half * 2 + 0];
            const float v1 = acc[mf][j][half * 2 + 1];
            if constexpr (MODE == GQPROJ) {
                int rr = gm % NR, t = gm / NR; int nn = t & (NS-1); int b = t >> 10;
                int h = gn >> 6, d = gn & 63;
                size_t off = ((size_t)((b << 3) + h) * NS + nn) * RD + rr * ND + d;
                *(uint32_t*)(g_qh + off) = pk_hi(v0, v1);
            } else if constexpr (MODE == GKPROJ) {
                int rr = gm % NR, t = gm / NR; int nn = t & (NS-1); int b = t >> 10;
                int h = gn >> 6, d = gn & 63;
                size_t off = ((size_t)((b << 3) + h) * NS + nn) * RD + rr * ND + d;
                *(uint32_t*)(g_kh + off) = pk_hi(v0, v1);
            } else if constexpr (MODE == GVPROJ) {
                int rr = gm % NR, t = gm / NR; int nn = t & (NS-1); int b = t >> 10;
                int h = gn >> 6, d = gn & 63;
                size_t off = ((size_t)((b << 3) + h) * NKV + nn + 1) * RD + rr * ND + d;
                *(uint32_t*)(g_vhf + off) = pk_hi(v0, v1);
            } else if constexpr (MODE == GSIM) {
                // columns shifted by +1 (col 0 = null token, computed in softmax)
                const float QS = (0.125f / 128.0f) * 0.28867513459481287f;
                size_t z = blockIdx.z;
                float* cr = g_sim + (z * NS + gm) * (size_t)LDSIM + gn + 1;
                cr[0] = v0 * QS;
                cr[1] = v1 * QS;
            } else if constexpr (MODE == GAV) {
                size_t z = blockIdx.z; int b = (int)(z >> 3), h = (int)(z & 7);
                int rr = gn >> 6, d = gn & 63;
                size_t off = (((size_t)b * NS + gm) * NR + rr) * NDIM + h * ND + d;
                *(uint32_t*)(g_oh + off) = pk_hi(v0, v1);
            } else {
                *(float2*)(g_out + (size_t)gm * NDIM + gn) = make_float2(v0, v1);
            }
        }
    }
}

// ---------------- fp32 -> hi/lo fp16 ----------------
__global__ void conv_hilo(const float* __restrict__ src,
                          __half* __restrict__ hi, __half* __restrict__ lo, int n4)
{
    int i = blockIdx.x * 256 + threadIdx.x;
    if (i >= n4) return;
    float4 v = ((const float4*)src)[i];
    *(uint2*)(hi + 4*(size_t)i) = make_uint2(pk_hi(v.x, v.y), pk_hi(v.z, v.w));
    if (lo)
        *(uint2*)(lo + 4*(size_t)i) = make_uint2(pk_lo(v.x, v.y), pk_lo(v.z, v.w));
}

// ---------------- LN(x) -> xn hi ----------------
__global__ void ln_in(const float* __restrict__ xin, const float* __restrict__ g)
{
    __shared__ float red1[4], red2[4];
    size_t row = blockIdx.x;
    int tid = threadIdx.x;                 // 128
    float4 v = ((const float4*)(xin + row * NDIM))[tid];
    float s = v.x + v.y + v.z + v.w;
#pragma unroll
    for (int o = 16; o; o >>= 1) s += __shfl_xor_sync(0xffffffffu, s, o);
    if ((tid & 31) == 0) red1[tid >> 5] = s;
    __syncthreads();
    float mean = (red1[0] + red1[1] + red1[2] + red1[3]) * (1.0f / NDIM);
    float d0 = v.x - mean, d1 = v.y - mean, d2 = v.z - mean, d3 = v.w - mean;
    float ss = d0*d0 + d1*d1 + d2*d2 + d3*d3;
#pragma unroll
    for (int o = 16; o; o >>= 1) ss += __shfl_xor_sync(0xffffffffu, ss, o);
    if ((tid & 31) == 0) red2[tid >> 5] = ss;
    __syncthreads();
    float var = (red2[0] + red2[1] + red2[2] + red2[3]) * (1.0f / NDIM);
    float inv = rsqrtf(var + 1e-5f);
    float4 gv = ((const float4*)g)[tid];
    float o0 = d0*inv*gv.x, o1 = d1*inv*gv.y, o2 = d2*inv*gv.z, o3 = d3*inv*gv.w;
    *(uint2*)(g_xnh + row*NDIM + tid*4) = make_uint2(pk_hi(o0,o1), pk_hi(o2,o3));
}

// ---------------- null v ----------------
__global__ void fill_null(const float* __restrict__ nkv)
{
    int idx = blockIdx.x * 256 + threadIdx.x;
    if (idx >= BH * RD) return;
    int bh = idx / RD, rd = idx % RD, d = rd & 63;
    g_vhf[(size_t)bh * NKV * RD + rd] = __float2half_rn(nkv[64 + d]);
}

// ---------------- v transpose: [bh, j, rd] fp16 -> [bh, rd, j] fp16 ----------
__global__ void transpose_v()
{
    __shared__ __half t[32][34];
    int z = blockIdx.z;
    int j0 = blockIdx.x * 32, rd0 = blockIdx.y * 32;
    const __half* src = g_vhf + (size_t)z * NKV * RD;
#pragma unroll
    for (int k = 0; k < 4; k++) {
        int jj = threadIdx.y + k * 8;
        int j = j0 + jj;
        t[jj][threadIdx.x] = (j < NKV) ? src[(size_t)j * RD + rd0 + threadIdx.x]
                                       : __float2half_rn(0.f);
    }
    __syncthreads();
#pragma unroll
    for (int k = 0; k < 4; k++) {
        int dd = threadIdx.y + k * 8;
        size_t off = ((size_t)z * RD + rd0 + dd) * LDAT + j0 + threadIdx.x;
        g_vth[off] = t[threadIdx.x][dd];
    }
}

// ---- pb-relax softmax; computes null-token sim (col 0) itself -> attn fp16 ----
__global__ void softmax_kernel(const float* __restrict__ nkv)
{
    __shared__ float red[8];
    __shared__ float s0sh;
    size_t gi = blockIdx.x;
    const float* p = g_sim + gi * LDSIM;
    __half* ah = g_ath + gi * LDAT;
    int tid = threadIdx.x;  // 256

    // null-token similarity: dot(q_row, null_k broadcast over r) * QS
    {
        const float QS = (0.125f / 128.0f) * 0.28867513459481287f;
        const __half* qrow = g_qh + gi * RD;
        float part = 0.f;
#pragma unroll
        for (int it = 0; it < 3; it++) {
            int idx = tid + it * 256;
            part += __half2float(qrow[idx]) * nkv[idx & 63];
        }
#pragma unroll
        for (int o = 16; o; o >>= 1) part += __shfl_xor_sync(0xffffffffu, part, o);
        if ((tid & 31) == 0) red[tid >> 5] = part;
        __syncthreads();
        if (tid == 0)
            s0sh = (red[0]+red[1]+red[2]+red[3]+red[4]+red[5]+red[6]+red[7]) * QS;
        __syncthreads();
    }
    const float s0 = s0sh;

    float vals[5];
    float mx = -1e30f;
#pragma unroll
    for (int it = 0; it < 5; it++) {
        int idx = tid + it * 256;
        float v = (idx < NKV) ? ((idx == 0) ? s0 : p[idx]) : -1e30f;
        vals[it] = v; mx = fmaxf(mx, v);
    }
#pragma unroll
    for (int o = 16; o; o >>= 1) mx = fmaxf(mx, __shfl_xor_sync(0xffffffffu, mx, o));
    if ((tid & 31) == 0) red[tid >> 5] = mx;
    __syncthreads();
    float bm = red[0];
#pragma unroll
    for (int w = 1; w < 8; w++) bm = fmaxf(bm, red[w]);
    __syncthreads();
    float s = 0.f;
#pragma unroll
    for (int it = 0; it < 5; it++) {
        int idx = tid + it * 256;
        float e = (idx < NKV) ? expf((vals[it] - bm) * 128.0f) : 0.f;
        vals[it] = e; s += e;
    }
#pragma unroll
    for (int o = 16; o; o >>= 1) s += __shfl_xor_sync(0xffffffffu, s, o);
    if ((tid & 31) == 0) red[tid >> 5] = s;
    __syncthreads();
    float bs = red[0]+red[1]+red[2]+red[3]+red[4]+red[5]+red[6]+red[7];
    float inv = 1.0f / bs;
#pragma unroll
    for (int it = 0; it < 5; it++) {
        int idx = tid + it * 256;
        if (idx < LDAT) ah[idx] = __float2half_rn(vals[it] * inv);
    }
}

// ---------------- final LN ----------------
__global__ void ln_final(const float* __restrict__ g, float* __restrict__ yout)
{
    __shared__ float red1[4], red2[4];
    size_t row = blockIdx.x;
    int tid = threadIdx.x;
    float4 v = ((const float4*)(g_out + row * NDIM))[tid];
    float s = v.x + v.y + v.z + v.w;
#pragma unroll
    for (int o = 16; o; o >>= 1) s += __shfl_xor_sync(0xffffffffu, s, o);
    if ((tid & 31) == 0) red1[tid >> 5] = s;
    __syncthreads();
    float mean = (red1[0] + red1[1] + red1[2] + red1[3]) * (1.0f / NDIM);
    float d0 = v.x - mean, d1 = v.y - mean, d2 = v.z - mean, d3 = v.w - mean;
    float ss = d0*d0 + d1*d1 + d2*d2 + d3*d3;
#pragma unroll
    for (int o = 16; o; o >>= 1) ss += __shfl_xor_sync(0xffffffffu, ss, o);
    if ((tid & 31) == 0) red2[tid >> 5] = ss;
    __syncthreads();
    float var = (red2[0] + red2[1] + red2[2] + red2[3]) * (1.0f / NDIM);
    float inv = rsqrtf(var + 1e-5f);
    float4 gv = ((const float4*)g)[tid];
    ((float4*)(yout + row * NDIM))[tid] =
        make_float4(d0*inv*gv.x, d1*inv*gv.y, d2*inv*gv.z, d3*inv*gv.w);
}

// ---------------- launch ----------------
extern "C" void kernel_launch(void* const* d_in, const int* in_sizes, int n_in,
                              void* d_out, int out_size)
{
    const float* x        = (const float*)d_in[0];
    const float* context  = (const float*)d_in[1];
    const float* norm_g   = (const float*)d_in[2];
    const float* to_q_w   = (const float*)d_in[3];
    const float* to_kv_w  = (const float*)d_in[4];
    const float* null_kv  = (const float*)d_in[5];
    const float* to_out_w = (const float*)d_in[6];
    const float* out_ng   = (const float*)d_in[7];
    float* out = (float*)d_out;

    static bool attr_done = false;
    if (!attr_done) {
        cudaFuncSetAttribute(gemm_hmma<GQPROJ>, cudaFuncAttributeMaxDynamicSharedMemorySize, GEMM_SMEM);
        cudaFuncSetAttribute(gemm_hmma<GKPROJ>, cudaFuncAttributeMaxDynamicSharedMemorySize, GEMM_SMEM);
        cudaFuncSetAttribute(gemm_hmma<GVPROJ>, cudaFuncAttributeMaxDynamicSharedMemorySize, GEMM_SMEM);
        cudaFuncSetAttribute(gemm_hmma<GSIM>,   cudaFuncAttributeMaxDynamicSharedMemorySize, GEMM_SMEM);
        cudaFuncSetAttribute(gemm_hmma<GAV>,    cudaFuncAttributeMaxDynamicSharedMemorySize, GEMM_SMEM);
        cudaFuncSetAttribute(gemm_hmma<GOPROJ>, cudaFuncAttributeMaxDynamicSharedMemorySize, GEMM_SMEM);
        attr_done = true;
    }

    __half *wqh, *wkvh, *woh, *ctxh, *ctxl;
    cudaGetSymbolAddress((void**)&wqh,  g_wqh);
    cudaGetSymbolAddress((void**)&wkvh, g_wkvh);
    cudaGetSymbolAddress((void**)&woh,  g_woh);
    cudaGetSymbolAddress((void**)&ctxh, g_ctxh); cudaGetSymbolAddress((void**)&ctxl, g_ctxl);

    // 0. conversions to fp16 (ctx hi+lo; weights hi-only)
    conv_hilo<<<(NROWS*NDIM/4 + 255)/256, 256>>>(context, ctxh, ctxl, NROWS*NDIM/4);
    conv_hilo<<<(512*512/4 + 255)/256, 256>>>(to_q_w,  wqh,  nullptr, 512*512/4);
    conv_hilo<<<(1024*512/4 + 255)/256, 256>>>(to_kv_w, wkvh, nullptr, 1024*512/4);
    conv_hilo<<<(512*512/4 + 255)/256, 256>>>(to_out_w, woh,  nullptr, 512*512/4);
    // 1. xn = LN(x) -> hi
    ln_in<<<NROWS, 128>>>(x, norm_g);
    // 2. q = xn @ Wq^T (hi-only) -> q fp16 [bh,i,rd]
    gemm_hmma<GQPROJ><<<dim3(512/128, NROWS/128, 1), 256, GEMM_SMEM>>>();
    // 3a. k = ctx @ Wk^T (hi-only) -> k fp16 [bh,j,rd] (no null row)
    gemm_hmma<GKPROJ><<<dim3(512/128, NROWS/128, 1), 256, GEMM_SMEM>>>();
    // 3b. v = ctx @ Wv^T (2-term) -> v fp16 [bh,j+1,rd]
    gemm_hmma<GVPROJ><<<dim3(512/128, NROWS/128, 1), 256, GEMM_SMEM>>>();
    // 4. null v row 0
    fill_null<<<(BH*RD + 255)/256, 256>>>(null_kv);
    // 5. sim[:,1:] = (q @ k^T) * scale (hi-only) -> fp32 [bh,i,1040]
    gemm_hmma<GSIM><<<dim3(NS/128, NS/128, BH), 256, GEMM_SMEM>>>();
    // 6. softmax (computes sim col 0 itself) -> attn fp16 [bh,i,1056]
    softmax_kernel<<<BH * NS, 256>>>(null_kv);
    // 7. v transpose -> v_t fp16 [bh,rd,1056] (zero pad)
    transpose_v<<<dim3(LDAT/32, RD/32, BH), dim3(32, 8)>>>();
    // 8. o = attn @ v (1-term) -> o fp16 [b,n,r,(h d)]
    gemm_hmma<GAV><<<dim3(RD/128, NS/128, BH), 256, GEMM_SMEM>>>();
    // 9. out = o @ Wout^T (1-term) -> fp32 g_out
    gemm_hmma<GOPROJ><<<dim3(512/128, NROWS/128, 1), 256, GEMM_SMEM>>>();
    // 10. final LN -> d_out
    ln_final<<<NROWS, 128>>>(out_ng, out);
    (void)in_sizes; (void)n_in; (void)out_size;
}

// round 11
// speedup vs baseline: 2.8400x; 1.1363x over previous
#include <cuda_runtime.h>
#include <cuda_fp16.h>
#include <cstdint>

#define NB 4
#define NS 1024
#define NR 12
#define NDIM 512
#define NH 8
#define ND 64
#define NROWS (NB*NS*NR)        /* 49152 */
#define NKV (NS+1)              /* 1025  */
#define LDAT 1056               /* fp16 attn / v_t ld (mult of 32) */
#define RD (NR*ND)              /* 768 */
#define BH (NB*NH)              /* 32 */

// smem: per stage, A 128x40 halves + B 128x40 halves (k-slab 32), 3 stages
#define LDS 40
#define ASTG (128*LDS)              /* 5120 halves */
#define STG  (2*ASTG)               /* 10240 halves per stage */
#define STAGES 3
#define GEMM_SMEM (STAGES*STG*2)    /* 61440 bytes */

// ---------------- scratch ----------------
__device__ __half g_xnh [(size_t)NROWS * NDIM];
__device__ __half g_ctxh[(size_t)NROWS * NDIM];
__device__ __half g_wqh [512*512];
__device__ __half g_wkvh[1024*512];
__device__ __half g_woh [512*512];
__device__ __half g_qh  [(size_t)BH * NS * RD];
__device__ __half g_kh  [(size_t)BH * NS * RD];      // no null row (handled in softmax)
__device__ __half g_vhf [(size_t)BH * NKV * RD];     // fp16 v, null at row 0
__device__ __half g_vth [(size_t)BH * RD * LDAT];
__device__ __half g_simh[(size_t)BH * NS * NS];      // fp16 sim, cols j=1..1024 at 0..1023
__device__ __half g_ath [(size_t)BH * NS * LDAT];
__device__ __half g_oh  [(size_t)NROWS * NDIM];
__device__ float  g_out [(size_t)NROWS * NDIM];

// ---------------- helpers ----------------
__device__ __forceinline__ uint32_t smem_u32(const void* p) {
    uint32_t a;
    asm("{ .reg .u64 t; cvta.to.shared.u64 t, %1; cvt.u32.u64 %0, t; }" : "=r"(a) : "l"(p));
    return a;
}
__device__ __forceinline__ void ldsm4(uint32_t* r, uint32_t addr) {
    asm volatile("ldmatrix.sync.aligned.m8n8.x4.shared.b16 {%0,%1,%2,%3}, [%4];"
                 : "=r"(r[0]), "=r"(r[1]), "=r"(r[2]), "=r"(r[3]) : "r"(addr));
}
__device__ __forceinline__ void mma16816(float* c, const uint32_t* a, uint32_t b0, uint32_t b1) {
    asm volatile("mma.sync.aligned.m16n8k16.row.col.f32.f16.f16.f32 "
                 "{%0,%1,%2,%3}, {%4,%5,%6,%7}, {%8,%9}, {%0,%1,%2,%3};"
                 : "+f"(c[0]), "+f"(c[1]), "+f"(c[2]), "+f"(c[3])
                 : "r"(a[0]), "r"(a[1]), "r"(a[2]), "r"(a[3]), "r"(b0), "r"(b1));
}
__device__ __forceinline__ void cp16(uint32_t dst, const void* src, bool pred) {
    int sz = pred ? 16 : 0;
    asm volatile("cp.async.cg.shared.global [%0], [%1], 16, %2;"
                 :: "r"(dst), "l"(src), "r"(sz) : "memory");
}
#define CP_COMMIT() asm volatile("cp.async.commit_group;" ::: "memory")
__device__ __forceinline__ uint32_t pk_hi(float a, float b) {
    __half2 t = __floats2half2_rn(a, b);
    return *(uint32_t*)&t;
}

// ------- HMMA GEMM: D[m,n] = sum_k A[m,k]*B[n,k]; all single-region fp16 -------
#define GQPROJ 0
#define GKPROJ 1
#define GVPROJ 2
#define GSIM   3
#define GAV    4
#define GOPROJ 5

template<int MODE>
__global__ __launch_bounds__(256, 2) void gemm_hmma()
{
    extern __shared__ __half sh[];
    const int tid = threadIdx.x, lane = tid & 31, wid = tid >> 5;
    const int m0 = blockIdx.y * 128, n0 = blockIdx.x * 128;

    constexpr int Nn   = MODE==GSIM ? NS : MODE==GAV ? RD : 512;
    constexpr int K    = MODE==GSIM ? RD : MODE==GAV ? LDAT : 512;
    constexpr int S    = K / 32;

    const __half *Ah, *Bh;
    if constexpr (MODE == GQPROJ)      { Ah=g_xnh;  Bh=g_wqh; }
    else if constexpr (MODE == GKPROJ) { Ah=g_ctxh; Bh=g_wkvh; }
    else if constexpr (MODE == GVPROJ) { Ah=g_ctxh; Bh=g_wkvh + 512*512; }
    else if constexpr (MODE == GSIM) {
        size_t z = blockIdx.z;
        Ah=g_qh + z*(size_t)NS*RD;
        Bh=g_kh + z*(size_t)NS*RD;
    } else if constexpr (MODE == GAV) {
        size_t z = blockIdx.z;
        Ah=g_ath + z*(size_t)NS*LDAT;
        Bh=g_vth + z*(size_t)RD*LDAT;
    } else                             { Ah=g_oh;   Bh=g_woh; }

    // warp tiling: 2 (m) x 4 (n); warp tile 64m x 32n
    const int m0w = (wid & 1) * 64;
    const int n0w = (wid >> 1) * 32;
    const int lrow = tid >> 2;              // 0..63
    const int lc   = (tid & 3) * 8;         // half offset within 32

    const uint32_t smb = smem_u32(sh);
    const uint32_t aAddr = smb + (uint32_t)(((m0w + (lane & 15)) * LDS + ((lane >> 4) << 3)) * 2);
    const uint32_t bAddr = smb + (uint32_t)((ASTG + (n0w + (lane & 15)) * LDS + ((lane >> 4) << 3)) * 2);

    float acc[4][4][4] = {};

    // async loader: one 32-deep k-slab into stage s%STAGES
    auto load_async = [&](int s) {
        const int k0 = s * 32;
        const uint32_t st = smb + (uint32_t)((s % STAGES) * STG * 2);
        cp16(st + (uint32_t)((lrow * LDS + lc) * 2),
             Ah + (size_t)(m0 + lrow) * K + k0 + lc, true);
        cp16(st + (uint32_t)(((lrow + 64) * LDS + lc) * 2),
             Ah + (size_t)(m0 + lrow + 64) * K + k0 + lc, true);
        cp16(st + (uint32_t)((ASTG + lrow * LDS + lc) * 2),
             Bh + (size_t)(n0 + lrow) * K + k0 + lc, n0 + lrow < Nn);
        cp16(st + (uint32_t)((ASTG + (lrow + 64) * LDS + lc) * 2),
             Bh + (size_t)(n0 + lrow + 64) * K + k0 + lc, n0 + lrow + 64 < Nn);
        CP_COMMIT();
    };
    auto compute = [&](int buf) {
        const uint32_t aB = aAddr + buf * (STG * 2);
        const uint32_t bB = bAddr + buf * (STG * 2);
#pragma unroll
        for (int k16 = 0; k16 < 2; k16++) {
            uint32_t a[4][4], b[2][4];
#pragma unroll
            for (int mf = 0; mf < 4; mf++) ldsm4(a[mf], aB + mf * (16*LDS*2) + k16 * 32);
#pragma unroll
            for (int nf = 0; nf < 2; nf++) ldsm4(b[nf], bB + nf * (16*LDS*2) + k16 * 32);
#pragma unroll
            for (int mf = 0; mf < 4; mf++)
#pragma unroll
                for (int j = 0; j < 4; j++)
                    mma16816(acc[mf][j], a[mf], b[j>>1][j&1], b[j>>1][(j&1)+2]);
        }
    };

    // 3-stage cp.async pipeline, one barrier per slab
    load_async(0);
    if (S > 1) load_async(1);
    for (int s = 0; s < S; s++) {
        if (s + 1 < S) {
            asm volatile("cp.async.wait_group 1;" ::: "memory");
        } else {
            asm volatile("cp.async.wait_group 0;" ::: "memory");
        }
        __syncthreads();
        compute(s % STAGES);
        if (s + 2 < S) load_async(s + 2);
    }

    // epilogue
    const int rbase = m0 + m0w + (lane >> 2);
    const int cbase = n0 + n0w + (lane & 3) * 2;
#pragma unroll
    for (int mf = 0; mf < 4; mf++)
#pragma unroll
    for (int half = 0; half < 2; half++) {
        const int gm = rbase + mf * 16 + half * 8;
#pragma unroll
        for (int j = 0; j < 4; j++) {
            const int gn = cbase + j * 8;
            const float v0 = acc[mf][j][half * 2 + 0];
            const float v1 = acc[mf][j][half * 2 + 1];
            if constexpr (MODE == GQPROJ) {
                int rr = gm % NR, t = gm / NR; int nn = t & (NS-1); int b = t >> 10;
                int h = gn >> 6, d = gn & 63;
                size_t off = ((size_t)((b << 3) + h) * NS + nn) * RD + rr * ND + d;
                *(uint32_t*)(g_qh + off) = pk_hi(v0, v1);
            } else if constexpr (MODE == GKPROJ) {
                int rr = gm % NR, t = gm / NR; int nn = t & (NS-1); int b = t >> 10;
                int h = gn >> 6, d = gn & 63;
                size_t off = ((size_t)((b << 3) + h) * NS + nn) * RD + rr * ND + d;
                *(uint32_t*)(g_kh + off) = pk_hi(v0, v1);
            } else if constexpr (MODE == GVPROJ) {
                int rr = gm % NR, t = gm / NR; int nn = t & (NS-1); int b = t >> 10;
                int h = gn >> 6, d = gn & 63;
                size_t off = ((size_t)((b << 3) + h) * NKV + nn + 1) * RD + rr * ND + d;
                *(uint32_t*)(g_vhf + off) = pk_hi(v0, v1);
            } else if constexpr (MODE == GSIM) {
                // fp16 scaled sim; column gn holds token j = gn+1 (null handled in softmax)
                const float QS = (0.125f / 128.0f) * 0.28867513459481287f;
                size_t z = blockIdx.z;
                __half* cr = g_simh + (z * NS + gm) * (size_t)NS + gn;
                *(uint32_t*)cr = pk_hi(v0 * QS, v1 * QS);
            } else if constexpr (MODE == GAV) {
                size_t z = blockIdx.z; int b = (int)(z >> 3), h = (int)(z & 7);
                int rr = gn >> 6, d = gn & 63;
                size_t off = (((size_t)b * NS + gm) * NR + rr) * NDIM + h * ND + d;
                *(uint32_t*)(g_oh + off) = pk_hi(v0, v1);
            } else {
                *(float2*)(g_out + (size_t)gm * NDIM + gn) = make_float2(v0, v1);
            }
        }
    }
}

// ---------------- fp32 -> fp16 ----------------
__global__ void conv_h(const float* __restrict__ src, __half* __restrict__ hi, int n4)
{
    int i = blockIdx.x * 256 + threadIdx.x;
    if (i >= n4) return;
    float4 v = ((const float4*)src)[i];
    *(uint2*)(hi + 4*(size_t)i) = make_uint2(pk_hi(v.x, v.y), pk_hi(v.z, v.w));
}

// ---------------- LN(x) -> xn fp16 ----------------
__global__ void ln_in(const float* __restrict__ xin, const float* __restrict__ g)
{
    __shared__ float red1[4], red2[4];
    size_t row = blockIdx.x;
    int tid = threadIdx.x;                 // 128
    float4 v = ((const float4*)(xin + row * NDIM))[tid];
    float s = v.x + v.y + v.z + v.w;
#pragma unroll
    for (int o = 16; o; o >>= 1) s += __shfl_xor_sync(0xffffffffu, s, o);
    if ((tid & 31) == 0) red1[tid >> 5] = s;
    __syncthreads();
    float mean = (red1[0] + red1[1] + red1[2] + red1[3]) * (1.0f / NDIM);
    float d0 = v.x - mean, d1 = v.y - mean, d2 = v.z - mean, d3 = v.w - mean;
    float ss = d0*d0 + d1*d1 + d2*d2 + d3*d3;
#pragma unroll
    for (int o = 16; o; o >>= 1) ss += __shfl_xor_sync(0xffffffffu, ss, o);
    if ((tid & 31) == 0) red2[tid >> 5] = ss;
    __syncthreads();
    float var = (red2[0] + red2[1] + red2[2] + red2[3]) * (1.0f / NDIM);
    float inv = rsqrtf(var + 1e-5f);
    float4 gv = ((const float4*)g)[tid];
    float o0 = d0*inv*gv.x, o1 = d1*inv*gv.y, o2 = d2*inv*gv.z, o3 = d3*inv*gv.w;
    *(uint2*)(g_xnh + row*NDIM + tid*4) = make_uint2(pk_hi(o0,o1), pk_hi(o2,o3));
}

// ---------------- null v ----------------
__global__ void fill_null(const float* __restrict__ nkv)
{
    int idx = blockIdx.x * 256 + threadIdx.x;
    if (idx >= BH * RD) return;
    int bh = idx / RD, rd = idx % RD, d = rd & 63;
    g_vhf[(size_t)bh * NKV * RD + rd] = __float2half_rn(nkv[64 + d]);
}

// ---------------- v transpose: [bh, j, rd] fp16 -> [bh, rd, j] fp16 ----------
__global__ void transpose_v()
{
    __shared__ __half t[32][34];
    int z = blockIdx.z;
    int j0 = blockIdx.x * 32, rd0 = blockIdx.y * 32;
    const __half* src = g_vhf + (size_t)z * NKV * RD;
#pragma unroll
    for (int k = 0; k < 4; k++) {
        int jj = threadIdx.y + k * 8;
        int j = j0 + jj;
        t[jj][threadIdx.x] = (j < NKV) ? src[(size_t)j * RD + rd0 + threadIdx.x]
                                       : __float2half_rn(0.f);
    }
    __syncthreads();
#pragma unroll
    for (int k = 0; k < 4; k++) {
        int dd = threadIdx.y + k * 8;
        size_t off = ((size_t)z * RD + rd0 + dd) * LDAT + j0 + threadIdx.x;
        g_vth[off] = t[threadIdx.x][dd];
    }
}

// ---- pb-relax softmax; computes null-token sim (col 0) itself -> attn fp16 ----
__global__ void softmax_kernel(const float* __restrict__ nkv)
{
    __shared__ float red[8];
    __shared__ float s0sh;
    size_t gi = blockIdx.x;
    const __half* p = g_simh + gi * NS;   // token j at p[j-1]
    __half* ah = g_ath + gi * LDAT;
    int tid = threadIdx.x;  // 256

    // null-token similarity: dot(q_row, null_k broadcast over r) * QS
    {
        const float QS = (0.125f / 128.0f) * 0.28867513459481287f;
        const __half* qrow = g_qh + gi * RD;
        float part = 0.f;
#pragma unroll
        for (int it = 0; it < 3; it++) {
            int idx = tid + it * 256;
            part += __half2float(qrow[idx]) * nkv[idx & 63];
        }
#pragma unroll
        for (int o = 16; o; o >>= 1) part += __shfl_xor_sync(0xffffffffu, part, o);
        if ((tid & 31) == 0) red[tid >> 5] = part;
        __syncthreads();
        if (tid == 0)
            s0sh = (red[0]+red[1]+red[2]+red[3]+red[4]+red[5]+red[6]+red[7]) * QS;
        __syncthreads();
    }
    const float s0 = s0sh;

    float vals[5];
    float mx = -1e30f;
#pragma unroll
    for (int it = 0; it < 5; it++) {
        int idx = tid + it * 256;
        float v = -1e30f;
        if (idx == 0)            v = s0;
        else if (idx < NKV)      v = __half2float(p[idx - 1]);
        vals[it] = v; mx = fmaxf(mx, v);
    }
#pragma unroll
    for (int o = 16; o; o >>= 1) mx = fmaxf(mx, __shfl_xor_sync(0xffffffffu, mx, o));
    if ((tid & 31) == 0) red[tid >> 5] = mx;
    __syncthreads();
    float bm = red[0];
#pragma unroll
    for (int w = 1; w < 8; w++) bm = fmaxf(bm, red[w]);
    __syncthreads();
    float s = 0.f;
#pragma unroll
    for (int it = 0; it < 5; it++) {
        int idx = tid + it * 256;
        float e = (idx < NKV) ? expf((vals[it] - bm) * 128.0f) : 0.f;
        vals[it] = e; s += e;
    }
#pragma unroll
    for (int o = 16; o; o >>= 1) s += __shfl_xor_sync(0xffffffffu, s, o);
    if ((tid & 31) == 0) red[tid >> 5] = s;
    __syncthreads();
    float bs = red[0]+red[1]+red[2]+red[3]+red[4]+red[5]+red[6]+red[7];
    float inv = 1.0f / bs;
#pragma unroll
    for (int it = 0; it < 5; it++) {
        int idx = tid + it * 256;
        if (idx < LDAT) ah[idx] = __float2half_rn(vals[it] * inv);
    }
}

// ---------------- final LN ----------------
__global__ void ln_final(const float* __restrict__ g, float* __restrict__ yout)
{
    __shared__ float red1[4], red2[4];
    size_t row = blockIdx.x;
    int tid = threadIdx.x;
    float4 v = ((const float4*)(g_out + row * NDIM))[tid];
    float s = v.x + v.y + v.z + v.w;
#pragma unroll
    for (int o = 16; o; o >>= 1) s += __shfl_xor_sync(0xffffffffu, s, o);
    if ((tid & 31) == 0) red1[tid >> 5] = s;
    __syncthreads();
    float mean = (red1[0] + red1[1] + red1[2] + red1[3]) * (1.0f / NDIM);
    float d0 = v.x - mean, d1 = v.y - mean, d2 = v.z - mean, d3 = v.w - mean;
    float ss = d0*d0 + d1*d1 + d2*d2 + d3*d3;
#pragma unroll
    for (int o = 16; o; o >>= 1) ss += __shfl_xor_sync(0xffffffffu, ss, o);
    if ((tid & 31) == 0) red2[tid >> 5] = ss;
    __syncthreads();
    float var = (red2[0] + red2[1] + red2[2] + red2[3]) * (1.0f / NDIM);
    float inv = rsqrtf(var + 1e-5f);
    float4 gv = ((const float4*)g)[tid];
    ((float4*)(yout + row * NDIM))[tid] =
        make_float4(d0*inv*gv.x, d1*inv*gv.y, d2*inv*gv.z, d3*inv*gv.w);
}

// ---------------- launch ----------------
extern "C" void kernel_launch(void* const* d_in, const int* in_sizes, int n_in,
                              void* d_out, int out_size)
{
    const float* x        = (const float*)d_in[0];
    const float* context  = (const float*)d_in[1];
    const float* norm_g   = (const float*)d_in[2];
    const float* to_q_w   = (const float*)d_in[3];
    const float* to_kv_w  = (const float*)d_in[4];
    const float* null_kv  = (const float*)d_in[5];
    const float* to_out_w = (const float*)d_in[6];
    const float* out_ng   = (const float*)d_in[7];
    float* out = (float*)d_out;

    static bool attr_done = false;
    if (!attr_done) {
        cudaFuncSetAttribute(gemm_hmma<GQPROJ>, cudaFuncAttributeMaxDynamicSharedMemorySize, GEMM_SMEM);
        cudaFuncSetAttribute(gemm_hmma<GKPROJ>, cudaFuncAttributeMaxDynamicSharedMemorySize, GEMM_SMEM);
        cudaFuncSetAttribute(gemm_hmma<GVPROJ>, cudaFuncAttributeMaxDynamicSharedMemorySize, GEMM_SMEM);
        cudaFuncSetAttribute(gemm_hmma<GSIM>,   cudaFuncAttributeMaxDynamicSharedMemorySize, GEMM_SMEM);
        cudaFuncSetAttribute(gemm_hmma<GAV>,    cudaFuncAttributeMaxDynamicSharedMemorySize, GEMM_SMEM);
        cudaFuncSetAttribute(gemm_hmma<GOPROJ>, cudaFuncAttributeMaxDynamicSharedMemorySize, GEMM_SMEM);
        attr_done = true;
    }

    __half *wqh, *wkvh, *woh, *ctxh;
    cudaGetSymbolAddress((void**)&wqh,  g_wqh);
    cudaGetSymbolAddress((void**)&wkvh, g_wkvh);
    cudaGetSymbolAddress((void**)&woh,  g_woh);
    cudaGetSymbolAddress((void**)&ctxh, g_ctxh);

    // 0. conversions to fp16 (hi only everywhere)
    conv_h<<<(NROWS*NDIM/4 + 255)/256, 256>>>(context, ctxh, NROWS*NDIM/4);
    conv_h<<<(512*512/4 + 255)/256, 256>>>(to_q_w,  wqh,  512*512/4);
    conv_h<<<(1024*512/4 + 255)/256, 256>>>(to_kv_w, wkvh, 1024*512/4);
    conv_h<<<(512*512/4 + 255)/256, 256>>>(to_out_w, woh,  512*512/4);
    // 1. xn = LN(x) -> fp16
    ln_in<<<NROWS, 128>>>(x, norm_g);
    // 2. q = xn @ Wq^T -> q fp16 [bh,i,rd]
    gemm_hmma<GQPROJ><<<dim3(512/128, NROWS/128, 1), 256, GEMM_SMEM>>>();
    // 3a. k = ctx @ Wk^T -> k fp16 [bh,j,rd] (no null row)
    gemm_hmma<GKPROJ><<<dim3(512/128, NROWS/128, 1), 256, GEMM_SMEM>>>();
    // 3b. v = ctx @ Wv^T -> v fp16 [bh,j+1,rd]
    gemm_hmma<GVPROJ><<<dim3(512/128, NROWS/128, 1), 256, GEMM_SMEM>>>();
    // 4. null v row 0
    fill_null<<<(BH*RD + 255)/256, 256>>>(null_kv);
    // 5. sim[:,1:] = (q @ k^T) * scale -> fp16 [bh,i,1024]
    gemm_hmma<GSIM><<<dim3(NS/128, NS/128, BH), 256, GEMM_SMEM>>>();
    // 6. softmax (computes sim col 0 itself) -> attn fp16 [bh,i,1056]
    softmax_kernel<<<BH * NS, 256>>>(null_kv);
    // 7. v transpose -> v_t fp16 [bh,rd,1056] (zero pad)
    transpose_v<<<dim3(LDAT/32, RD/32, BH), dim3(32, 8)>>>();
    // 8. o = attn @ v -> o fp16 [b,n,r,(h d)]
    gemm_hmma<GAV><<<dim3(RD/128, NS/128, BH), 256, GEMM_SMEM>>>();
    // 9. out = o @ Wout^T -> fp32 g_out
    gemm_hmma<GOPROJ><<<dim3(512/128, NROWS/128, 1), 256, GEMM_SMEM>>>();
    // 10. final LN -> d_out
    ln_final<<<NROWS, 128>>>(out_ng, out);
    (void)in_sizes; (void)n_in; (void)out_size;
}

// round 12
// speedup vs baseline: 3.0344x; 1.0684x over previous
#include <cuda_runtime.h>
#include <cuda_fp16.h>
#include <cstdint>

#define NB 4
#define NS 1024
#define NR 12
#define NDIM 512
#define NH 8
#define ND 64
#define NROWS (NB*NS*NR)        /* 49152 */
#define NKV (NS+1)              /* 1025  */
#define RD (NR*ND)              /* 768 */
#define BH (NB*NH)              /* 32 */

// smem: per stage 10240 halves; A 128x40; B either 128x40 (NT) or 32x136 (trans)
#define LDS 40
#define LDSB 136
#define ASTG (128*LDS)              /* 5120 halves */
#define STG  (2*ASTG)               /* 10240 halves per stage */
#define STAGES 3
#define GEMM_SMEM (STAGES*STG*2)    /* 61440 bytes */

// ---------------- scratch ----------------
__device__ __half g_xnh [(size_t)NROWS * NDIM];
__device__ __half g_ctxh[(size_t)NROWS * NDIM];
__device__ __half g_wqh [512*512];
__device__ __half g_wkvh[1024*512];
__device__ __half g_woh [512*512];
__device__ __half g_qh  [(size_t)BH * NS * RD];
__device__ __half g_kh  [(size_t)BH * NS * RD];      // no null row (handled in softmax)
__device__ __half g_vhf [(size_t)BH * NS * RD];      // fp16 v [bh, j, rd], j=0..1023
__device__ __half g_simh[(size_t)BH * NS * NS];      // sim cols j=1..1024; softmax rewrites attn in place
__device__ float  g_a0  [(size_t)BH * NS];           // null-token attn weight
__device__ __half g_oh  [(size_t)NROWS * NDIM];
__device__ float  g_out [(size_t)NROWS * NDIM];

// ---------------- helpers ----------------
__device__ __forceinline__ uint32_t smem_u32(const void* p) {
    uint32_t a;
    asm("{ .reg .u64 t; cvta.to.shared.u64 t, %1; cvt.u32.u64 %0, t; }" : "=r"(a) : "l"(p));
    return a;
}
__device__ __forceinline__ void ldsm4(uint32_t* r, uint32_t addr) {
    asm volatile("ldmatrix.sync.aligned.m8n8.x4.shared.b16 {%0,%1,%2,%3}, [%4];"
                 : "=r"(r[0]), "=r"(r[1]), "=r"(r[2]), "=r"(r[3]) : "r"(addr));
}
__device__ __forceinline__ void ldsm4t(uint32_t* r, uint32_t addr) {
    asm volatile("ldmatrix.sync.aligned.m8n8.x4.trans.shared.b16 {%0,%1,%2,%3}, [%4];"
                 : "=r"(r[0]), "=r"(r[1]), "=r"(r[2]), "=r"(r[3]) : "r"(addr));
}
__device__ __forceinline__ void mma16816(float* c, const uint32_t* a, uint32_t b0, uint32_t b1) {
    asm volatile("mma.sync.aligned.m16n8k16.row.col.f32.f16.f16.f32 "
                 "{%0,%1,%2,%3}, {%4,%5,%6,%7}, {%8,%9}, {%0,%1,%2,%3};"
                 : "+f"(c[0]), "+f"(c[1]), "+f"(c[2]), "+f"(c[3])
                 : "r"(a[0]), "r"(a[1]), "r"(a[2]), "r"(a[3]), "r"(b0), "r"(b1));
}
__device__ __forceinline__ void cp16(uint32_t dst, const void* src, bool pred) {
    int sz = pred ? 16 : 0;
    asm volatile("cp.async.cg.shared.global [%0], [%1], 16, %2;"
                 :: "r"(dst), "l"(src), "r"(sz) : "memory");
}
#define CP_COMMIT() asm volatile("cp.async.commit_group;" ::: "memory")
__device__ __forceinline__ uint32_t pk_hi(float a, float b) {
    __half2 t = __floats2half2_rn(a, b);
    return *(uint32_t*)&t;
}

// ------- HMMA GEMM: D[m,n] = sum_k A[m,k]*B[n,k] (NT) or A*B[k,n] (GAV, trans-B) -------
#define GQPROJ 0
#define GKVPROJ 1
#define GSIM   2
#define GAV    3
#define GOPROJ 4

template<int MODE>
__global__ __launch_bounds__(256, 2) void gemm_hmma(const float* __restrict__ aux)
{
    extern __shared__ __half sh[];
    const int tid = threadIdx.x, lane = tid & 31, wid = tid >> 5;
    const int m0 = blockIdx.y * 128, n0 = blockIdx.x * 128;

    constexpr bool TRB = (MODE == GAV);                 // B stored [k, n]
    constexpr int Nn   = MODE==GSIM ? NS : MODE==GAV ? RD : MODE==GKVPROJ ? 1024 : 512;
    constexpr int K    = MODE==GSIM ? RD : MODE==GAV ? NS : 512;
    constexpr int S    = K / 32;

    const __half *Ah, *Bh;
    if constexpr (MODE == GQPROJ)       { Ah=g_xnh;  Bh=g_wqh; }
    else if constexpr (MODE == GKVPROJ) { Ah=g_ctxh; Bh=g_wkvh; }
    else if constexpr (MODE == GSIM) {
        size_t z = blockIdx.z;
        Ah=g_qh + z*(size_t)NS*RD;
        Bh=g_kh + z*(size_t)NS*RD;
    } else if constexpr (MODE == GAV) {
        size_t z = blockIdx.z;
        Ah=g_simh + z*(size_t)NS*NS;                    // attn in place, cols j-1
        Bh=g_vhf  + z*(size_t)NS*RD;                    // [j, rd]
    } else                              { Ah=g_oh;   Bh=g_woh; }

    // warp tiling: 2 (m) x 4 (n); warp tile 64m x 32n
    const int m0w = (wid & 1) * 64;
    const int n0w = (wid >> 1) * 32;
    const int lrow = tid >> 2;              // 0..63
    const int lc   = (tid & 3) * 8;         // half offset within 32

    const uint32_t smb = smem_u32(sh);
    const uint32_t aAddr = smb + (uint32_t)(((m0w + (lane & 15)) * LDS + ((lane >> 4) << 3)) * 2);
    // NT-B fragment address (row = n, 8 k-halves per lane)
    const uint32_t bAddrNT = smb + (uint32_t)((ASTG + (n0w + (lane & 15)) * LDS + ((lane >> 4) << 3)) * 2);
    // trans-B fragment address (row = k, 8 n-halves per lane)
    const uint32_t bAddrT  = smb + (uint32_t)((ASTG
                         + ((lane & 7) + ((lane >> 4) << 3)) * LDSB
                         + n0w + ((lane >> 3) & 1) * 8) * 2);

    float acc[4][4][4] = {};

    // async loader: one 32-deep k-slab into stage s%STAGES
    auto load_async = [&](int s) {
        const int k0 = s * 32;
        const uint32_t st = smb + (uint32_t)((s % STAGES) * STG * 2);
        cp16(st + (uint32_t)((lrow * LDS + lc) * 2),
             Ah + (size_t)(m0 + lrow) * K + k0 + lc, true);
        cp16(st + (uint32_t)(((lrow + 64) * LDS + lc) * 2),
             Ah + (size_t)(m0 + lrow + 64) * K + k0 + lc, true);
        if constexpr (TRB) {
            // B tile [32 k-rows x 128 n-cols], rows of RD halves in gmem
            const int r0 = tid >> 4, c0 = (tid & 15) * 8;          // idx = tid
            const int r1 = (tid + 256) >> 4, c1 = ((tid + 256) & 15) * 8;
            cp16(st + (uint32_t)((ASTG + r0 * LDSB + c0) * 2),
                 Bh + (size_t)(k0 + r0) * RD + n0 + c0, true);
            cp16(st + (uint32_t)((ASTG + r1 * LDSB + c1) * 2),
                 Bh + (size_t)(k0 + r1) * RD + n0 + c1, true);
        } else {
            cp16(st + (uint32_t)((ASTG + lrow * LDS + lc) * 2),
                 Bh + (size_t)(n0 + lrow) * K + k0 + lc, n0 + lrow < Nn);
            cp16(st + (uint32_t)((ASTG + (lrow + 64) * LDS + lc) * 2),
                 Bh + (size_t)(n0 + lrow + 64) * K + k0 + lc, n0 + lrow + 64 < Nn);
        }
        CP_COMMIT();
    };
    auto compute = [&](int buf) {
        const uint32_t aB = aAddr + buf * (STG * 2);
#pragma unroll
        for (int k16 = 0; k16 < 2; k16++) {
            uint32_t a[4][4], b[2][4];
#pragma unroll
            for (int mf = 0; mf < 4; mf++) ldsm4(a[mf], aB + mf * (16*LDS*2) + k16 * 32);
            if constexpr (TRB) {
                const uint32_t bB = bAddrT + buf * (STG * 2) + k16 * (16*LDSB*2);
#pragma unroll
                for (int nf = 0; nf < 2; nf++) ldsm4t(b[nf], bB + nf * 32);
            } else {
                const uint32_t bB = bAddrNT + buf * (STG * 2) + k16 * 32;
#pragma unroll
                for (int nf = 0; nf < 2; nf++) ldsm4(b[nf], bB + nf * (16*LDS*2));
            }
#pragma unroll
            for (int mf = 0; mf < 4; mf++)
#pragma unroll
                for (int j = 0; j < 4; j++)
                    mma16816(acc[mf][j], a[mf], b[j>>1][j&1], b[j>>1][(j&1)+2]);
        }
    };

    // 3-stage cp.async pipeline, one barrier per slab
    load_async(0);
    if (S > 1) load_async(1);
    for (int s = 0; s < S; s++) {
        if (s + 1 < S) {
            asm volatile("cp.async.wait_group 1;" ::: "memory");
        } else {
            asm volatile("cp.async.wait_group 0;" ::: "memory");
        }
        __syncthreads();
        compute(s % STAGES);
        if (s + 2 < S) load_async(s + 2);
    }

    // epilogue
    const int rbase = m0 + m0w + (lane >> 2);
    const int cbase = n0 + n0w + (lane & 3) * 2;
#pragma unroll
    for (int mf = 0; mf < 4; mf++)
#pragma unroll
    for (int half = 0; half < 2; half++) {
        const int gm = rbase + mf * 16 + half * 8;
        float a0v = 0.f;
        if constexpr (MODE == GAV)
            a0v = g_a0[blockIdx.z * (size_t)NS + gm];
#pragma unroll
        for (int j = 0; j < 4; j++) {
            const int gn = cbase + j * 8;
            float v0 = acc[mf][j][half * 2 + 0];
            float v1 = acc[mf][j][half * 2 + 1];
            if constexpr (MODE == GQPROJ) {
                int rr = gm % NR, t = gm / NR; int nn = t & (NS-1); int b = t >> 10;
                int h = gn >> 6, d = gn & 63;
                size_t off = ((size_t)((b << 3) + h) * NS + nn) * RD + rr * ND + d;
                *(uint32_t*)(g_qh + off) = pk_hi(v0, v1);
            } else if constexpr (MODE == GKVPROJ) {
                int rr = gm % NR, t = gm / NR; int nn = t & (NS-1); int b = t >> 10;
                if (gn < 512) {
                    int h = gn >> 6, d = gn & 63;
                    size_t off = ((size_t)((b << 3) + h) * NS + nn) * RD + rr * ND + d;
                    *(uint32_t*)(g_kh + off) = pk_hi(v0, v1);
                } else {
                    int e = gn - 512; int h = e >> 6, d = e & 63;
                    size_t off = ((size_t)((b << 3) + h) * NS + nn) * RD + rr * ND + d;
                    *(uint32_t*)(g_vhf + off) = pk_hi(v0, v1);
                }
            } else if constexpr (MODE == GSIM) {
                // fp16 scaled sim; column gn holds token j = gn+1 (null handled in softmax)
                const float QS = (0.125f / 128.0f) * 0.28867513459481287f;
                size_t z = blockIdx.z;
                __half* cr = g_simh + (z * NS + gm) * (size_t)NS + gn;
                *(uint32_t*)cr = pk_hi(v0 * QS, v1 * QS);
            } else if constexpr (MODE == GAV) {
                size_t z = blockIdx.z; int b = (int)(z >> 3), h = (int)(z & 7);
                int rr = gn >> 6, d = gn & 63;
                // null-token rank-1 term in fp32
                v0 += a0v * aux[64 + d];
                v1 += a0v * aux[64 + d + 1];
                size_t off = (((size_t)b * NS + gm) * NR + rr) * NDIM + h * ND + d;
                *(uint32_t*)(g_oh + off) = pk_hi(v0, v1);
            } else {
                *(float2*)(g_out + (size_t)gm * NDIM + gn) = make_float2(v0, v1);
            }
        }
    }
}

// ---------------- fp32 -> fp16 ----------------
__global__ void conv_h(const float* __restrict__ src, __half* __restrict__ hi, int n4)
{
    int i = blockIdx.x * 256 + threadIdx.x;
    if (i >= n4) return;
    float4 v = ((const float4*)src)[i];
    *(uint2*)(hi + 4*(size_t)i) = make_uint2(pk_hi(v.x, v.y), pk_hi(v.z, v.w));
}

// ---------------- LN(x) -> xn fp16 ----------------
__global__ void ln_in(const float* __restrict__ xin, const float* __restrict__ g)
{
    __shared__ float red1[4], red2[4];
    size_t row = blockIdx.x;
    int tid = threadIdx.x;                 // 128
    float4 v = ((const float4*)(xin + row * NDIM))[tid];
    float s = v.x + v.y + v.z + v.w;
#pragma unroll
    for (int o = 16; o; o >>= 1) s += __shfl_xor_sync(0xffffffffu, s, o);
    if ((tid & 31) == 0) red1[tid >> 5] = s;
    __syncthreads();
    float mean = (red1[0] + red1[1] + red1[2] + red1[3]) * (1.0f / NDIM);
    float d0 = v.x - mean, d1 = v.y - mean, d2 = v.z - mean, d3 = v.w - mean;
    float ss = d0*d0 + d1*d1 + d2*d2 + d3*d3;
#pragma unroll
    for (int o = 16; o; o >>= 1) ss += __shfl_xor_sync(0xffffffffu, ss, o);
    if ((tid & 31) == 0) red2[tid >> 5] = ss;
    __syncthreads();
    float var = (red2[0] + red2[1] + red2[2] + red2[3]) * (1.0f / NDIM);
    float inv = rsqrtf(var + 1e-5f);
    float4 gv = ((const float4*)g)[tid];
    float o0 = d0*inv*gv.x, o1 = d1*inv*gv.y, o2 = d2*inv*gv.z, o3 = d3*inv*gv.w;
    *(uint2*)(g_xnh + row*NDIM + tid*4) = make_uint2(pk_hi(o0,o1), pk_hi(o2,o3));
}

// ---- pb-relax softmax in place; computes null-token sim itself, stores a0 ----
__global__ void softmax_kernel(const float* __restrict__ nkv)
{
    __shared__ float red[8];
    __shared__ float s0sh;
    size_t gi = blockIdx.x;
    __half* p = g_simh + gi * NS;         // token j at p[j-1]; rewritten with attn
    int tid = threadIdx.x;  // 256

    // null-token similarity: dot(q_row, null_k broadcast over r) * QS
    {
        const float QS = (0.125f / 128.0f) * 0.28867513459481287f;
        const __half* qrow = g_qh + gi * RD;
        float part = 0.f;
#pragma unroll
        for (int it = 0; it < 3; it++) {
            int idx = tid + it * 256;
            part += __half2float(qrow[idx]) * nkv[idx & 63];
        }
#pragma unroll
        for (int o = 16; o; o >>= 1) part += __shfl_xor_sync(0xffffffffu, part, o);
        if ((tid & 31) == 0) red[tid >> 5] = part;
        __syncthreads();
        if (tid == 0)
            s0sh = (red[0]+red[1]+red[2]+red[3]+red[4]+red[5]+red[6]+red[7]) * QS;
        __syncthreads();
    }
    const float s0 = s0sh;

    float vals[5];
    float mx = -1e30f;
#pragma unroll
    for (int it = 0; it < 5; it++) {
        int idx = tid + it * 256;
        float v = -1e30f;
        if (idx == 0)            v = s0;
        else if (idx < NKV)      v = __half2float(p[idx - 1]);
        vals[it] = v; mx = fmaxf(mx, v);
    }
#pragma unroll
    for (int o = 16; o; o >>= 1) mx = fmaxf(mx, __shfl_xor_sync(0xffffffffu, mx, o));
    if ((tid & 31) == 0) red[tid >> 5] = mx;
    __syncthreads();
    float bm = red[0];
#pragma unroll
    for (int w = 1; w < 8; w++) bm = fmaxf(bm, red[w]);
    __syncthreads();
    float s = 0.f;
#pragma unroll
    for (int it = 0; it < 5; it++) {
        int idx = tid + it * 256;
        float e = (idx < NKV) ? expf((vals[it] - bm) * 128.0f) : 0.f;
        vals[it] = e; s += e;
    }
#pragma unroll
    for (int o = 16; o; o >>= 1) s += __shfl_xor_sync(0xffffffffu, s, o);
    if ((tid & 31) == 0) red[tid >> 5] = s;
    __syncthreads();
    float bs = red[0]+red[1]+red[2]+red[3]+red[4]+red[5]+red[6]+red[7];
    float inv = 1.0f / bs;
    __syncthreads();   // all reads of p done (vals cached) before in-place writes
#pragma unroll
    for (int it = 0; it < 5; it++) {
        int idx = tid + it * 256;
        if (idx == 0)            g_a0[gi] = vals[it] * inv;
        else if (idx < NKV)      p[idx - 1] = __float2half_rn(vals[it] * inv);
    }
}

// ---------------- final LN ----------------
__global__ void ln_final(const float* __restrict__ g, float* __restrict__ yout)
{
    __shared__ float red1[4], red2[4];
    size_t row = blockIdx.x;
    int tid = threadIdx.x;
    float4 v = ((const float4*)(g_out + row * NDIM))[tid];
    float s = v.x + v.y + v.z + v.w;
#pragma unroll
    for (int o = 16; o; o >>= 1) s += __shfl_xor_sync(0xffffffffu, s, o);
    if ((tid & 31) == 0) red1[tid >> 5] = s;
    __syncthreads();
    float mean = (red1[0] + red1[1] + red1[2] + red1[3]) * (1.0f / NDIM);
    float d0 = v.x - mean, d1 = v.y - mean, d2 = v.z - mean, d3 = v.w - mean;
    float ss = d0*d0 + d1*d1 + d2*d2 + d3*d3;
#pragma unroll
    for (int o = 16; o; o >>= 1) ss += __shfl_xor_sync(0xffffffffu, ss, o);
    if ((tid & 31) == 0) red2[tid >> 5] = ss;
    __syncthreads();
    float var = (red2[0] + red2[1] + red2[2] + red2[3]) * (1.0f / NDIM);
    float inv = rsqrtf(var + 1e-5f);
    float4 gv = ((const float4*)g)[tid];
    ((float4*)(yout + row * NDIM))[tid] =
        make_float4(d0*inv*gv.x, d1*inv*gv.y, d2*inv*gv.z, d3*inv*gv.w);
}

// ---------------- launch ----------------
extern "C" void kernel_launch(void* const* d_in, const int* in_sizes, int n_in,
                              void* d_out, int out_size)
{
    const float* x        = (const float*)d_in[0];
    const float* context  = (const float*)d_in[1];
    const float* norm_g   = (const float*)d_in[2];
    const float* to_q_w   = (const float*)d_in[3];
    const float* to_kv_w  = (const float*)d_in[4];
    const float* null_kv  = (const float*)d_in[5];
    const float* to_out_w = (const float*)d_in[6];
    const float* out_ng   = (const float*)d_in[7];
    float* out = (float*)d_out;

    static bool attr_done = false;
    if (!attr_done) {
        cudaFuncSetAttribute(gemm_hmma<GQPROJ>,  cudaFuncAttributeMaxDynamicSharedMemorySize, GEMM_SMEM);
        cudaFuncSetAttribute(gemm_hmma<GKVPROJ>, cudaFuncAttributeMaxDynamicSharedMemorySize, GEMM_SMEM);
        cudaFuncSetAttribute(gemm_hmma<GSIM>,    cudaFuncAttributeMaxDynamicSharedMemorySize, GEMM_SMEM);
        cudaFuncSetAttribute(gemm_hmma<GAV>,     cudaFuncAttributeMaxDynamicSharedMemorySize, GEMM_SMEM);
        cudaFuncSetAttribute(gemm_hmma<GOPROJ>,  cudaFuncAttributeMaxDynamicSharedMemorySize, GEMM_SMEM);
        attr_done = true;
    }

    __half *wqh, *wkvh, *woh, *ctxh;
    cudaGetSymbolAddress((void**)&wqh,  g_wqh);
    cudaGetSymbolAddress((void**)&wkvh, g_wkvh);
    cudaGetSymbolAddress((void**)&woh,  g_woh);
    cudaGetSymbolAddress((void**)&ctxh, g_ctxh);

    // 0. conversions to fp16
    conv_h<<<(NROWS*NDIM/4 + 255)/256, 256>>>(context, ctxh, NROWS*NDIM/4);
    conv_h<<<(512*512/4 + 255)/256, 256>>>(to_q_w,  wqh,  512*512/4);
    conv_h<<<(1024*512/4 + 255)/256, 256>>>(to_kv_w, wkvh, 1024*512/4);
    conv_h<<<(512*512/4 + 255)/256, 256>>>(to_out_w, woh,  512*512/4);
    // 1. xn = LN(x) -> fp16
    ln_in<<<NROWS, 128>>>(x, norm_g);
    // 2. q = xn @ Wq^T -> q fp16 [bh,i,rd]
    gemm_hmma<GQPROJ><<<dim3(512/128, NROWS/128, 1), 256, GEMM_SMEM>>>(nullptr);
    // 3. kv = ctx @ Wkv^T -> k fp16 [bh,j,rd], v fp16 [bh,j,rd]
    gemm_hmma<GKVPROJ><<<dim3(1024/128, NROWS/128, 1), 256, GEMM_SMEM>>>(nullptr);
    // 4. sim[:,1:] = (q @ k^T) * scale -> fp16 [bh,i,1024]
    gemm_hmma<GSIM><<<dim3(NS/128, NS/128, BH), 256, GEMM_SMEM>>>(nullptr);
    // 5. softmax in place (computes null col itself, stores a0)
    softmax_kernel<<<BH * NS, 256>>>(null_kv);
    // 6. o = attn @ v (trans-B from [j,rd]) + a0*null_v -> o fp16 [b,n,r,(h d)]
    gemm_hmma<GAV><<<dim3(RD/128, NS/128, BH), 256, GEMM_SMEM>>>(null_kv);
    // 7. out = o @ Wout^T -> fp32 g_out
    gemm_hmma<GOPROJ><<<dim3(512/128, NROWS/128, 1), 256, GEMM_SMEM>>>(nullptr);
    // 8. final LN -> d_out
    ln_final<<<NROWS, 128>>>(out_ng, out);
    (void)in_sizes; (void)n_in; (void)out_size;
}

// round 13
// speedup vs baseline: 3.0615x; 1.0089x over previous
#include <cuda_runtime.h>
#include <cuda_fp16.h>
#include <cstdint>

#define NB 4
#define NS 1024
#define NR 12
#define NDIM 512
#define NH 8
#define ND 64
#define NROWS (NB*NS*NR)        /* 49152 */
#define NKV (NS+1)              /* 1025  */
#define RD (NR*ND)              /* 768 */
#define BH (NB*NH)              /* 32 */

// smem: per stage 10240 halves; A 128x40; B either 128x40 (NT) or 32x136 (trans)
#define LDS 40
#define LDSB 136
#define ASTG (128*LDS)              /* 5120 halves */
#define STG  (2*ASTG)               /* 10240 halves per stage */
#define STAGES 3
#define GEMM_SMEM (STAGES*STG*2)    /* 61440 bytes */

// ---------------- scratch ----------------
__device__ __half g_xnh [(size_t)NROWS * NDIM];
__device__ __half g_ctxh[(size_t)NROWS * NDIM];
__device__ __half g_wqh [512*512];
__device__ __half g_wkvh[1024*512];
__device__ __half g_woh [512*512];
__device__ __half g_qh  [(size_t)BH * NS * RD];
__device__ __half g_kh  [(size_t)BH * NS * RD];      // no null row (handled in softmax)
__device__ __half g_vhf [(size_t)BH * NS * RD];      // fp16 v [bh, j, rd], j=0..1023
__device__ __half g_simh[(size_t)BH * NS * NS];      // sim cols j=1..1024; softmax rewrites attn in place
__device__ float  g_a0  [(size_t)BH * NS];           // null-token attn weight
__device__ __half g_oh  [(size_t)NROWS * NDIM];
__device__ __half g_outh[(size_t)NROWS * NDIM];      // pre-LN out, fp16

// ---------------- helpers ----------------
__device__ __forceinline__ uint32_t smem_u32(const void* p) {
    uint32_t a;
    asm("{ .reg .u64 t; cvta.to.shared.u64 t, %1; cvt.u32.u64 %0, t; }" : "=r"(a) : "l"(p));
    return a;
}
__device__ __forceinline__ void ldsm4(uint32_t* r, uint32_t addr) {
    asm volatile("ldmatrix.sync.aligned.m8n8.x4.shared.b16 {%0,%1,%2,%3}, [%4];"
                 : "=r"(r[0]), "=r"(r[1]), "=r"(r[2]), "=r"(r[3]) : "r"(addr));
}
__device__ __forceinline__ void ldsm4t(uint32_t* r, uint32_t addr) {
    asm volatile("ldmatrix.sync.aligned.m8n8.x4.trans.shared.b16 {%0,%1,%2,%3}, [%4];"
                 : "=r"(r[0]), "=r"(r[1]), "=r"(r[2]), "=r"(r[3]) : "r"(addr));
}
__device__ __forceinline__ void mma16816(float* c, const uint32_t* a, uint32_t b0, uint32_t b1) {
    asm volatile("mma.sync.aligned.m16n8k16.row.col.f32.f16.f16.f32 "
                 "{%0,%1,%2,%3}, {%4,%5,%6,%7}, {%8,%9}, {%0,%1,%2,%3};"
                 : "+f"(c[0]), "+f"(c[1]), "+f"(c[2]), "+f"(c[3])
                 : "r"(a[0]), "r"(a[1]), "r"(a[2]), "r"(a[3]), "r"(b0), "r"(b1));
}
__device__ __forceinline__ void cp16(uint32_t dst, const void* src, bool pred) {
    int sz = pred ? 16 : 0;
    asm volatile("cp.async.cg.shared.global [%0], [%1], 16, %2;"
                 :: "r"(dst), "l"(src), "r"(sz) : "memory");
}
#define CP_COMMIT() asm volatile("cp.async.commit_group;" ::: "memory")
__device__ __forceinline__ uint32_t pk_hi(float a, float b) {
    __half2 t = __floats2half2_rn(a, b);
    return *(uint32_t*)&t;
}

// ------- HMMA GEMM: D[m,n] = sum_k A[m,k]*B[n,k] (NT) or A*B[k,n] (GAV, trans-B) -------
#define GQPROJ 0
#define GKVPROJ 1
#define GSIM   2
#define GAV    3
#define GOPROJ 4

template<int MODE>
__global__ __launch_bounds__(256, 2) void gemm_hmma(const float* __restrict__ aux)
{
    extern __shared__ __half sh[];
    const int tid = threadIdx.x, lane = tid & 31, wid = tid >> 5;
    const int m0 = blockIdx.y * 128, n0 = blockIdx.x * 128;

    constexpr bool TRB = (MODE == GAV);                 // B stored [k, n]
    constexpr int Nn   = MODE==GSIM ? NS : MODE==GAV ? RD : MODE==GKVPROJ ? 1024 : 512;
    constexpr int K    = MODE==GSIM ? RD : MODE==GAV ? NS : 512;
    constexpr int S    = K / 32;

    const __half *Ah, *Bh;
    if constexpr (MODE == GQPROJ)       { Ah=g_xnh;  Bh=g_wqh; }
    else if constexpr (MODE == GKVPROJ) { Ah=g_ctxh; Bh=g_wkvh; }
    else if constexpr (MODE == GSIM) {
        size_t z = blockIdx.z;
        Ah=g_qh + z*(size_t)NS*RD;
        Bh=g_kh + z*(size_t)NS*RD;
    } else if constexpr (MODE == GAV) {
        size_t z = blockIdx.z;
        Ah=g_simh + z*(size_t)NS*NS;                    // attn in place, cols j-1
        Bh=g_vhf  + z*(size_t)NS*RD;                    // [j, rd]
    } else                              { Ah=g_oh;   Bh=g_woh; }

    // warp tiling: 2 (m) x 4 (n); warp tile 64m x 32n
    const int m0w = (wid & 1) * 64;
    const int n0w = (wid >> 1) * 32;
    const int lrow = tid >> 2;              // 0..63
    const int lc   = (tid & 3) * 8;         // half offset within 32

    const uint32_t smb = smem_u32(sh);
    const uint32_t aAddr = smb + (uint32_t)(((m0w + (lane & 15)) * LDS + ((lane >> 4) << 3)) * 2);
    // NT-B fragment address (row = n, 8 k-halves per lane)
    const uint32_t bAddrNT = smb + (uint32_t)((ASTG + (n0w + (lane & 15)) * LDS + ((lane >> 4) << 3)) * 2);
    // trans-B fragment address (row = k, 8 n-halves per lane)
    const uint32_t bAddrT  = smb + (uint32_t)((ASTG
                         + ((lane & 7) + ((lane >> 4) << 3)) * LDSB
                         + n0w + ((lane >> 3) & 1) * 8) * 2);

    float acc[4][4][4] = {};

    // async loader: one 32-deep k-slab into stage s%STAGES
    auto load_async = [&](int s) {
        const int k0 = s * 32;
        const uint32_t st = smb + (uint32_t)((s % STAGES) * STG * 2);
        cp16(st + (uint32_t)((lrow * LDS + lc) * 2),
             Ah + (size_t)(m0 + lrow) * K + k0 + lc, true);
        cp16(st + (uint32_t)(((lrow + 64) * LDS + lc) * 2),
             Ah + (size_t)(m0 + lrow + 64) * K + k0 + lc, true);
        if constexpr (TRB) {
            // B tile [32 k-rows x 128 n-cols], rows of RD halves in gmem
            const int r0 = tid >> 4, c0 = (tid & 15) * 8;          // idx = tid
            const int r1 = (tid + 256) >> 4, c1 = ((tid + 256) & 15) * 8;
            cp16(st + (uint32_t)((ASTG + r0 * LDSB + c0) * 2),
                 Bh + (size_t)(k0 + r0) * RD + n0 + c0, true);
            cp16(st + (uint32_t)((ASTG + r1 * LDSB + c1) * 2),
                 Bh + (size_t)(k0 + r1) * RD + n0 + c1, true);
        } else {
            cp16(st + (uint32_t)((ASTG + lrow * LDS + lc) * 2),
                 Bh + (size_t)(n0 + lrow) * K + k0 + lc, n0 + lrow < Nn);
            cp16(st + (uint32_t)((ASTG + (lrow + 64) * LDS + lc) * 2),
                 Bh + (size_t)(n0 + lrow + 64) * K + k0 + lc, n0 + lrow + 64 < Nn);
        }
        CP_COMMIT();
    };
    auto compute = [&](int buf) {
        const uint32_t aB = aAddr + buf * (STG * 2);
#pragma unroll
        for (int k16 = 0; k16 < 2; k16++) {
            uint32_t a[4][4], b[2][4];
#pragma unroll
            for (int mf = 0; mf < 4; mf++) ldsm4(a[mf], aB + mf * (16*LDS*2) + k16 * 32);
            if constexpr (TRB) {
                const uint32_t bB = bAddrT + buf * (STG * 2) + k16 * (16*LDSB*2);
#pragma unroll
                for (int nf = 0; nf < 2; nf++) ldsm4t(b[nf], bB + nf * 32);
            } else {
                const uint32_t bB = bAddrNT + buf * (STG * 2) + k16 * 32;
#pragma unroll
                for (int nf = 0; nf < 2; nf++) ldsm4(b[nf], bB + nf * (16*LDS*2));
            }
#pragma unroll
            for (int mf = 0; mf < 4; mf++)
#pragma unroll
                for (int j = 0; j < 4; j++)
                    mma16816(acc[mf][j], a[mf], b[j>>1][j&1], b[j>>1][(j&1)+2]);
        }
    };

    // 3-stage cp.async pipeline, one barrier per slab
    load_async(0);
    if (S > 1) load_async(1);
    for (int s = 0; s < S; s++) {
        if (s + 1 < S) {
            asm volatile("cp.async.wait_group 1;" ::: "memory");
        } else {
            asm volatile("cp.async.wait_group 0;" ::: "memory");
        }
        __syncthreads();
        compute(s % STAGES);
        if (s + 2 < S) load_async(s + 2);
    }

    // epilogue
    const int rbase = m0 + m0w + (lane >> 2);
    const int cbase = n0 + n0w + (lane & 3) * 2;
#pragma unroll
    for (int mf = 0; mf < 4; mf++)
#pragma unroll
    for (int half = 0; half < 2; half++) {
        const int gm = rbase + mf * 16 + half * 8;
        float a0v = 0.f;
        if constexpr (MODE == GAV)
            a0v = g_a0[blockIdx.z * (size_t)NS + gm];
#pragma unroll
        for (int j = 0; j < 4; j++) {
            const int gn = cbase + j * 8;
            float v0 = acc[mf][j][half * 2 + 0];
            float v1 = acc[mf][j][half * 2 + 1];
            if constexpr (MODE == GQPROJ) {
                int rr = gm % NR, t = gm / NR; int nn = t & (NS-1); int b = t >> 10;
                int h = gn >> 6, d = gn & 63;
                size_t off = ((size_t)((b << 3) + h) * NS + nn) * RD + rr * ND + d;
                *(uint32_t*)(g_qh + off) = pk_hi(v0, v1);
            } else if constexpr (MODE == GKVPROJ) {
                int rr = gm % NR, t = gm / NR; int nn = t & (NS-1); int b = t >> 10;
                if (gn < 512) {
                    int h = gn >> 6, d = gn & 63;
                    size_t off = ((size_t)((b << 3) + h) * NS + nn) * RD + rr * ND + d;
                    *(uint32_t*)(g_kh + off) = pk_hi(v0, v1);
                } else {
                    int e = gn - 512; int h = e >> 6, d = e & 63;
                    size_t off = ((size_t)((b << 3) + h) * NS + nn) * RD + rr * ND + d;
                    *(uint32_t*)(g_vhf + off) = pk_hi(v0, v1);
                }
            } else if constexpr (MODE == GSIM) {
                // fp16 scaled sim; column gn holds token j = gn+1 (null handled in softmax)
                const float QS = (0.125f / 128.0f) * 0.28867513459481287f;
                size_t z = blockIdx.z;
                __half* cr = g_simh + (z * NS + gm) * (size_t)NS + gn;
                *(uint32_t*)cr = pk_hi(v0 * QS, v1 * QS);
            } else if constexpr (MODE == GAV) {
                size_t z = blockIdx.z; int b = (int)(z >> 3), h = (int)(z & 7);
                int rr = gn >> 6, d = gn & 63;
                // null-token rank-1 term in fp32
                v0 += a0v * aux[64 + d];
                v1 += a0v * aux[64 + d + 1];
                size_t off = (((size_t)b * NS + gm) * NR + rr) * NDIM + h * ND + d;
                *(uint32_t*)(g_oh + off) = pk_hi(v0, v1);
            } else {
                *(uint32_t*)(g_outh + (size_t)gm * NDIM + gn) = pk_hi(v0, v1);
            }
        }
    }
}

// ---------------- fp32 -> fp16 ----------------
__global__ void conv_h(const float* __restrict__ src, __half* __restrict__ hi, int n4)
{
    int i = blockIdx.x * 256 + threadIdx.x;
    if (i >= n4) return;
    float4 v = ((const float4*)src)[i];
    *(uint2*)(hi + 4*(size_t)i) = make_uint2(pk_hi(v.x, v.y), pk_hi(v.z, v.w));
}

// ---------------- LN(x) -> xn fp16 ----------------
__global__ void ln_in(const float* __restrict__ xin, const float* __restrict__ g)
{
    __shared__ float red1[4], red2[4];
    size_t row = blockIdx.x;
    int tid = threadIdx.x;                 // 128
    float4 v = ((const float4*)(xin + row * NDIM))[tid];
    float s = v.x + v.y + v.z + v.w;
#pragma unroll
    for (int o = 16; o; o >>= 1) s += __shfl_xor_sync(0xffffffffu, s, o);
    if ((tid & 31) == 0) red1[tid >> 5] = s;
    __syncthreads();
    float mean = (red1[0] + red1[1] + red1[2] + red1[3]) * (1.0f / NDIM);
    float d0 = v.x - mean, d1 = v.y - mean, d2 = v.z - mean, d3 = v.w - mean;
    float ss = d0*d0 + d1*d1 + d2*d2 + d3*d3;
#pragma unroll
    for (int o = 16; o; o >>= 1) ss += __shfl_xor_sync(0xffffffffu, ss, o);
    if ((tid & 31) == 0) red2[tid >> 5] = ss;
    __syncthreads();
    float var = (red2[0] + red2[1] + red2[2] + red2[3]) * (1.0f / NDIM);
    float inv = rsqrtf(var + 1e-5f);
    float4 gv = ((const float4*)g)[tid];
    float o0 = d0*inv*gv.x, o1 = d1*inv*gv.y, o2 = d2*inv*gv.z, o3 = d3*inv*gv.w;
    *(uint2*)(g_xnh + row*NDIM + tid*4) = make_uint2(pk_hi(o0,o1), pk_hi(o2,o3));
}

// ---- pb-relax softmax in place; computes null-token sim itself, stores a0 ----
__global__ void softmax_kernel(const float* __restrict__ nkv)
{
    __shared__ float red[8];
    __shared__ float s0sh;
    size_t gi = blockIdx.x;
    __half* p = g_simh + gi * NS;         // token j at p[j-1]; rewritten with attn
    int tid = threadIdx.x;  // 256

    // null-token similarity: dot(q_row, null_k broadcast over r) * QS
    {
        const float QS = (0.125f / 128.0f) * 0.28867513459481287f;
        const __half* qrow = g_qh + gi * RD;
        float part = 0.f;
#pragma unroll
        for (int it = 0; it < 3; it++) {
            int idx = tid + it * 256;
            part += __half2float(qrow[idx]) * nkv[idx & 63];
        }
#pragma unroll
        for (int o = 16; o; o >>= 1) part += __shfl_xor_sync(0xffffffffu, part, o);
        if ((tid & 31) == 0) red[tid >> 5] = part;
        __syncthreads();
        if (tid == 0)
            s0sh = (red[0]+red[1]+red[2]+red[3]+red[4]+red[5]+red[6]+red[7]) * QS;
        __syncthreads();
    }
    const float s0 = s0sh;

    float vals[5];
    float mx = -1e30f;
#pragma unroll
    for (int it = 0; it < 5; it++) {
        int idx = tid + it * 256;
        float v = -1e30f;
        if (idx == 0)            v = s0;
        else if (idx < NKV)      v = __half2float(p[idx - 1]);
        vals[it] = v; mx = fmaxf(mx, v);
    }
#pragma unroll
    for (int o = 16; o; o >>= 1) mx = fmaxf(mx, __shfl_xor_sync(0xffffffffu, mx, o));
    if ((tid & 31) == 0) red[tid >> 5] = mx;
    __syncthreads();
    float bm = red[0];
#pragma unroll
    for (int w = 1; w < 8; w++) bm = fmaxf(bm, red[w]);
    __syncthreads();
    float s = 0.f;
#pragma unroll
    for (int it = 0; it < 5; it++) {
        int idx = tid + it * 256;
        float e = (idx < NKV) ? expf((vals[it] - bm) * 128.0f) : 0.f;
        vals[it] = e; s += e;
    }
#pragma unroll
    for (int o = 16; o; o >>= 1) s += __shfl_xor_sync(0xffffffffu, s, o);
    if ((tid & 31) == 0) red[tid >> 5] = s;
    __syncthreads();
    float bs = red[0]+red[1]+red[2]+red[3]+red[4]+red[5]+red[6]+red[7];
    float inv = 1.0f / bs;
#pragma unroll
    for (int it = 0; it < 5; it++) {
        int idx = tid + it * 256;
        if (idx == 0)            g_a0[gi] = vals[it] * inv;
        else if (idx < NKV)      p[idx - 1] = __float2half_rn(vals[it] * inv);
    }
}

// ---------------- final LN (reads fp16 pre-LN out) ----------------
__global__ void ln_final(const float* __restrict__ g, float* __restrict__ yout)
{
    __shared__ float red1[4], red2[4];
    size_t row = blockIdx.x;
    int tid = threadIdx.x;                 // 128 threads x 4 vals
    uint2 pv = *(const uint2*)(g_outh + row * NDIM + tid * 4);
    __half2 h0 = *(__half2*)&pv.x, h1 = *(__half2*)&pv.y;
    float vx = __half2float(h0.x), vy = __half2float(h0.y);
    float vz = __half2float(h1.x), vw = __half2float(h1.y);
    float s = vx + vy + vz + vw;
#pragma unroll
    for (int o = 16; o; o >>= 1) s += __shfl_xor_sync(0xffffffffu, s, o);
    if ((tid & 31) == 0) red1[tid >> 5] = s;
    __syncthreads();
    float mean = (red1[0] + red1[1] + red1[2] + red1[3]) * (1.0f / NDIM);
    float d0 = vx - mean, d1 = vy - mean, d2 = vz - mean, d3 = vw - mean;
    float ss = d0*d0 + d1*d1 + d2*d2 + d3*d3;
#pragma unroll
    for (int o = 16; o; o >>= 1) ss += __shfl_xor_sync(0xffffffffu, ss, o);
    if ((tid & 31) == 0) red2[tid >> 5] = ss;
    __syncthreads();
    float var = (red2[0] + red2[1] + red2[2] + red2[3]) * (1.0f / NDIM);
    float inv = rsqrtf(var + 1e-5f);
    float4 gv = ((const float4*)g)[tid];
    ((float4*)(yout + row * NDIM))[tid] =
        make_float4(d0*inv*gv.x, d1*inv*gv.y, d2*inv*gv.z, d3*inv*gv.w);
}

// ---------------- launch ----------------
extern "C" void kernel_launch(void* const* d_in, const int* in_sizes, int n_in,
                              void* d_out, int out_size)
{
    const float* x        = (const float*)d_in[0];
    const float* context  = (const float*)d_in[1];
    const float* norm_g   = (const float*)d_in[2];
    const float* to_q_w   = (const float*)d_in[3];
    const float* to_kv_w  = (const float*)d_in[4];
    const float* null_kv  = (const float*)d_in[5];
    const float* to_out_w = (const float*)d_in[6];
    const float* out_ng   = (const float*)d_in[7];
    float* out = (float*)d_out;

    static bool attr_done = false;
    if (!attr_done) {
        cudaFuncSetAttribute(gemm_hmma<GQPROJ>,  cudaFuncAttributeMaxDynamicSharedMemorySize, GEMM_SMEM);
        cudaFuncSetAttribute(gemm_hmma<GKVPROJ>, cudaFuncAttributeMaxDynamicSharedMemorySize, GEMM_SMEM);
        cudaFuncSetAttribute(gemm_hmma<GSIM>,    cudaFuncAttributeMaxDynamicSharedMemorySize, GEMM_SMEM);
        cudaFuncSetAttribute(gemm_hmma<GAV>,     cudaFuncAttributeMaxDynamicSharedMemorySize, GEMM_SMEM);
        cudaFuncSetAttribute(gemm_hmma<GOPROJ>,  cudaFuncAttributeMaxDynamicSharedMemorySize, GEMM_SMEM);
        attr_done = true;
    }

    __half *wqh, *wkvh, *woh, *ctxh;
    cudaGetSymbolAddress((void**)&wqh,  g_wqh);
    cudaGetSymbolAddress((void**)&wkvh, g_wkvh);
    cudaGetSymbolAddress((void**)&woh,  g_woh);
    cudaGetSymbolAddress((void**)&ctxh, g_ctxh);

    // 0. conversions to fp16
    conv_h<<<(NROWS*NDIM/4 + 255)/256, 256>>>(context, ctxh, NROWS*NDIM/4);
    conv_h<<<(512*512/4 + 255)/256, 256>>>(to_q_w,  wqh,  512*512/4);
    conv_h<<<(1024*512/4 + 255)/256, 256>>>(to_kv_w, wkvh, 1024*512/4);
    conv_h<<<(512*512/4 + 255)/256, 256>>>(to_out_w, woh,  512*512/4);
    // 1. xn = LN(x) -> fp16
    ln_in<<<NROWS, 128>>>(x, norm_g);
    // 2. q = xn @ Wq^T -> q fp16 [bh,i,rd]
    gemm_hmma<GQPROJ><<<dim3(512/128, NROWS/128, 1), 256, GEMM_SMEM>>>(nullptr);
    // 3. kv = ctx @ Wkv^T -> k fp16 [bh,j,rd], v fp16 [bh,j,rd]
    gemm_hmma<GKVPROJ><<<dim3(1024/128, NROWS/128, 1), 256, GEMM_SMEM>>>(nullptr);
    // 4. sim[:,1:] = (q @ k^T) * scale -> fp16 [bh,i,1024]
    gemm_hmma<GSIM><<<dim3(NS/128, NS/128, BH), 256, GEMM_SMEM>>>(nullptr);
    // 5. softmax in place (computes null col itself, stores a0)
    softmax_kernel<<<BH * NS, 256>>>(null_kv);
    // 6. o = attn @ v (trans-B from [j,rd]) + a0*null_v -> o fp16 [b,n,r,(h d)]
    gemm_hmma<GAV><<<dim3(RD/128, NS/128, BH), 256, GEMM_SMEM>>>(null_kv);
    // 7. out = o @ Wout^T -> fp16 g_outh
    gemm_hmma<GOPROJ><<<dim3(512/128, NROWS/128, 1), 256, GEMM_SMEM>>>(nullptr);
    // 8. final LN -> d_out
    ln_final<<<NROWS, 128>>>(out_ng, out);
    (void)in_sizes; (void)n_in; (void)out_size;
}

// round 14
// speedup vs baseline: 3.1161x; 1.0178x over previous
#include <cuda_runtime.h>
#include <cuda_fp16.h>
#include <cstdint>

#define NB 4
#define NS 1024
#define NR 12
#define NDIM 512
#define NH 8
#define ND 64
#define NROWS (NB*NS*NR)        /* 49152 */
#define NKV (NS+1)              /* 1025  */
#define RD (NR*ND)              /* 768 */
#define BH (NB*NH)              /* 32 */

// smem: per stage 10240 halves; A 128x40; B either 128x40 (NT) or 32x136 (trans)
#define LDS 40
#define LDSB 136
#define ASTG (128*LDS)              /* 5120 halves */
#define STG  (2*ASTG)               /* 10240 halves per stage */
#define STAGES 3
#define GEMM_SMEM (STAGES*STG*2)    /* 61440 bytes */

// ---------------- scratch ----------------
__device__ __half g_xnh [(size_t)NROWS * NDIM];
__device__ __half g_ctxh[(size_t)NROWS * NDIM];
__device__ __half g_wqh [512*512];
__device__ __half g_wkvh[1024*512];
__device__ __half g_woh [512*512];
__device__ __half g_qh  [(size_t)BH * NS * RD];
__device__ __half g_kh  [(size_t)BH * NS * RD];      // no null row (handled in softmax)
__device__ __half g_vhf [(size_t)BH * NS * RD];      // fp16 v [bh, j, rd], j=0..1023
__device__ __half g_simh[(size_t)BH * NS * NS];      // sim cols j=1..1024; softmax rewrites attn in place
__device__ float  g_a0  [(size_t)BH * NS];           // null-token attn weight
__device__ __half g_oh  [(size_t)NROWS * NDIM];
__device__ __half g_outh[(size_t)NROWS * NDIM];      // pre-LN out, fp16

// ---------------- helpers ----------------
__device__ __forceinline__ uint32_t smem_u32(const void* p) {
    uint32_t a;
    asm("{ .reg .u64 t; cvta.to.shared.u64 t, %1; cvt.u32.u64 %0, t; }" : "=r"(a) : "l"(p));
    return a;
}
__device__ __forceinline__ void ldsm4(uint32_t* r, uint32_t addr) {
    asm volatile("ldmatrix.sync.aligned.m8n8.x4.shared.b16 {%0,%1,%2,%3}, [%4];"
                 : "=r"(r[0]), "=r"(r[1]), "=r"(r[2]), "=r"(r[3]) : "r"(addr));
}
__device__ __forceinline__ void ldsm4t(uint32_t* r, uint32_t addr) {
    asm volatile("ldmatrix.sync.aligned.m8n8.x4.trans.shared.b16 {%0,%1,%2,%3}, [%4];"
                 : "=r"(r[0]), "=r"(r[1]), "=r"(r[2]), "=r"(r[3]) : "r"(addr));
}
__device__ __forceinline__ void mma16816(float* c, const uint32_t* a, uint32_t b0, uint32_t b1) {
    asm volatile("mma.sync.aligned.m16n8k16.row.col.f32.f16.f16.f32 "
                 "{%0,%1,%2,%3}, {%4,%5,%6,%7}, {%8,%9}, {%0,%1,%2,%3};"
                 : "+f"(c[0]), "+f"(c[1]), "+f"(c[2]), "+f"(c[3])
                 : "r"(a[0]), "r"(a[1]), "r"(a[2]), "r"(a[3]), "r"(b0), "r"(b1));
}
__device__ __forceinline__ void cp16(uint32_t dst, const void* src, bool pred) {
    int sz = pred ? 16 : 0;
    asm volatile("cp.async.cg.shared.global [%0], [%1], 16, %2;"
                 :: "r"(dst), "l"(src), "r"(sz) : "memory");
}
#define CP_COMMIT() asm volatile("cp.async.commit_group;" ::: "memory")
__device__ __forceinline__ uint32_t pk_hi(float a, float b) {
    __half2 t = __floats2half2_rn(a, b);
    return *(uint32_t*)&t;
}

// ------- HMMA GEMM: D[m,n] = sum_k A[m,k]*B[n,k] (NT) or A*B[k,n] (GAV, trans-B) -------
#define GQPROJ 0
#define GKVPROJ 1
#define GSIM   2
#define GAV    3
#define GOPROJ 4

template<int MODE>
__global__ __launch_bounds__(256, 2) void gemm_hmma(const float* __restrict__ aux)
{
    extern __shared__ __half sh[];
    const int tid = threadIdx.x, lane = tid & 31, wid = tid >> 5;
    const int m0 = blockIdx.y * 128, n0 = blockIdx.x * 128;

    constexpr bool TRB = (MODE == GAV);                 // B stored [k, n]
    constexpr int Nn   = MODE==GSIM ? NS : MODE==GAV ? RD : MODE==GKVPROJ ? 1024 : 512;
    constexpr int K    = MODE==GSIM ? RD : MODE==GAV ? NS : 512;
    constexpr int S    = K / 32;

    const __half *Ah, *Bh;
    if constexpr (MODE == GQPROJ)       { Ah=g_xnh;  Bh=g_wqh; }
    else if constexpr (MODE == GKVPROJ) { Ah=g_ctxh; Bh=g_wkvh; }
    else if constexpr (MODE == GSIM) {
        size_t z = blockIdx.z;
        Ah=g_qh + z*(size_t)NS*RD;
        Bh=g_kh + z*(size_t)NS*RD;
    } else if constexpr (MODE == GAV) {
        size_t z = blockIdx.z;
        Ah=g_simh + z*(size_t)NS*NS;                    // attn in place, cols j-1
        Bh=g_vhf  + z*(size_t)NS*RD;                    // [j, rd]
    } else                              { Ah=g_oh;   Bh=g_woh; }

    // warp tiling: 2 (m) x 4 (n); warp tile 64m x 32n
    const int m0w = (wid & 1) * 64;
    const int n0w = (wid >> 1) * 32;
    const int lrow = tid >> 2;              // 0..63
    const int lc   = (tid & 3) * 8;         // half offset within 32

    const uint32_t smb = smem_u32(sh);
    const uint32_t aAddr = smb + (uint32_t)(((m0w + (lane & 15)) * LDS + ((lane >> 4) << 3)) * 2);
    // NT-B fragment address (row = n, 8 k-halves per lane)
    const uint32_t bAddrNT = smb + (uint32_t)((ASTG + (n0w + (lane & 15)) * LDS + ((lane >> 4) << 3)) * 2);
    // trans-B fragment address (row = k, 8 n-halves per lane)
    const uint32_t bAddrT  = smb + (uint32_t)((ASTG
                         + ((lane & 7) + ((lane >> 4) << 3)) * LDSB
                         + n0w + ((lane >> 3) & 1) * 8) * 2);

    float acc[4][4][4] = {};

    // async loader: one 32-deep k-slab into stage s%STAGES
    auto load_async = [&](int s) {
        const int k0 = s * 32;
        const uint32_t st = smb + (uint32_t)((s % STAGES) * STG * 2);
        cp16(st + (uint32_t)((lrow * LDS + lc) * 2),
             Ah + (size_t)(m0 + lrow) * K + k0 + lc, true);
        cp16(st + (uint32_t)(((lrow + 64) * LDS + lc) * 2),
             Ah + (size_t)(m0 + lrow + 64) * K + k0 + lc, true);
        if constexpr (TRB) {
            // B tile [32 k-rows x 128 n-cols], rows of RD halves in gmem
            const int r0 = tid >> 4, c0 = (tid & 15) * 8;          // idx = tid
            const int r1 = (tid + 256) >> 4, c1 = ((tid + 256) & 15) * 8;
            cp16(st + (uint32_t)((ASTG + r0 * LDSB + c0) * 2),
                 Bh + (size_t)(k0 + r0) * RD + n0 + c0, true);
            cp16(st + (uint32_t)((ASTG + r1 * LDSB + c1) * 2),
                 Bh + (size_t)(k0 + r1) * RD + n0 + c1, true);
        } else {
            cp16(st + (uint32_t)((ASTG + lrow * LDS + lc) * 2),
                 Bh + (size_t)(n0 + lrow) * K + k0 + lc, n0 + lrow < Nn);
            cp16(st + (uint32_t)((ASTG + (lrow + 64) * LDS + lc) * 2),
                 Bh + (size_t)(n0 + lrow + 64) * K + k0 + lc, n0 + lrow + 64 < Nn);
        }
        CP_COMMIT();
    };
    auto compute = [&](int buf) {
        const uint32_t aB = aAddr + buf * (STG * 2);
#pragma unroll
        for (int k16 = 0; k16 < 2; k16++) {
            uint32_t a[4][4], b[2][4];
#pragma unroll
            for (int mf = 0; mf < 4; mf++) ldsm4(a[mf], aB + mf * (16*LDS*2) + k16 * 32);
            if constexpr (TRB) {
                const uint32_t bB = bAddrT + buf * (STG * 2) + k16 * (16*LDSB*2);
#pragma unroll
                for (int nf = 0; nf < 2; nf++) ldsm4t(b[nf], bB + nf * 32);
            } else {
                const uint32_t bB = bAddrNT + buf * (STG * 2) + k16 * 32;
#pragma unroll
                for (int nf = 0; nf < 2; nf++) ldsm4(b[nf], bB + nf * (16*LDS*2));
            }
#pragma unroll
            for (int mf = 0; mf < 4; mf++)
#pragma unroll
                for (int j = 0; j < 4; j++)
                    mma16816(acc[mf][j], a[mf], b[j>>1][j&1], b[j>>1][(j&1)+2]);
        }
    };

    // 3-stage cp.async pipeline, one barrier per slab
    load_async(0);
    if (S > 1) load_async(1);
    for (int s = 0; s < S; s++) {
        if (s + 1 < S) {
            asm volatile("cp.async.wait_group 1;" ::: "memory");
        } else {
            asm volatile("cp.async.wait_group 0;" ::: "memory");
        }
        __syncthreads();
        compute(s % STAGES);
        if (s + 2 < S) load_async(s + 2);
    }

    // epilogue
    const int rbase = m0 + m0w + (lane >> 2);
    const int cbase = n0 + n0w + (lane & 3) * 2;
#pragma unroll
    for (int mf = 0; mf < 4; mf++)
#pragma unroll
    for (int half = 0; half < 2; half++) {
        const int gm = rbase + mf * 16 + half * 8;
        float a0v = 0.f;
        if constexpr (MODE == GAV)
            a0v = g_a0[blockIdx.z * (size_t)NS + gm];
#pragma unroll
        for (int j = 0; j < 4; j++) {
            const int gn = cbase + j * 8;
            float v0 = acc[mf][j][half * 2 + 0];
            float v1 = acc[mf][j][half * 2 + 1];
            if constexpr (MODE == GQPROJ) {
                int rr = gm % NR, t = gm / NR; int nn = t & (NS-1); int b = t >> 10;
                int h = gn >> 6, d = gn & 63;
                size_t off = ((size_t)((b << 3) + h) * NS + nn) * RD + rr * ND + d;
                *(uint32_t*)(g_qh + off) = pk_hi(v0, v1);
            } else if constexpr (MODE == GKVPROJ) {
                int rr = gm % NR, t = gm / NR; int nn = t & (NS-1); int b = t >> 10;
                if (gn < 512) {
                    int h = gn >> 6, d = gn & 63;
                    size_t off = ((size_t)((b << 3) + h) * NS + nn) * RD + rr * ND + d;
                    *(uint32_t*)(g_kh + off) = pk_hi(v0, v1);
                } else {
                    int e = gn - 512; int h = e >> 6, d = e & 63;
                    size_t off = ((size_t)((b << 3) + h) * NS + nn) * RD + rr * ND + d;
                    *(uint32_t*)(g_vhf + off) = pk_hi(v0, v1);
                }
            } else if constexpr (MODE == GSIM) {
                // fp16 scaled sim; column gn holds token j = gn+1 (null handled in softmax)
                const float QS = (0.125f / 128.0f) * 0.28867513459481287f;
                size_t z = blockIdx.z;
                __half* cr = g_simh + (z * NS + gm) * (size_t)NS + gn;
                *(uint32_t*)cr = pk_hi(v0 * QS, v1 * QS);
            } else if constexpr (MODE == GAV) {
                size_t z = blockIdx.z; int b = (int)(z >> 3), h = (int)(z & 7);
                int rr = gn >> 6, d = gn & 63;
                // null-token rank-1 term in fp32
                v0 += a0v * aux[64 + d];
                v1 += a0v * aux[64 + d + 1];
                size_t off = (((size_t)b * NS + gm) * NR + rr) * NDIM + h * ND + d;
                *(uint32_t*)(g_oh + off) = pk_hi(v0, v1);
            } else {
                *(uint32_t*)(g_outh + (size_t)gm * NDIM + gn) = pk_hi(v0, v1);
            }
        }
    }
}

// ---------------- fp32 -> fp16 ----------------
__global__ void conv_h(const float* __restrict__ src, __half* __restrict__ hi, int n4)
{
    int i = blockIdx.x * 256 + threadIdx.x;
    if (i >= n4) return;
    float4 v = ((const float4*)src)[i];
    *(uint2*)(hi + 4*(size_t)i) = make_uint2(pk_hi(v.x, v.y), pk_hi(v.z, v.w));
}

// ---------------- LN(x) -> xn fp16 ----------------
__global__ void ln_in(const float* __restrict__ xin, const float* __restrict__ g)
{
    __shared__ float red1[4], red2[4];
    size_t row = blockIdx.x;
    int tid = threadIdx.x;                 // 128
    float4 v = ((const float4*)(xin + row * NDIM))[tid];
    float s = v.x + v.y + v.z + v.w;
#pragma unroll
    for (int o = 16; o; o >>= 1) s += __shfl_xor_sync(0xffffffffu, s, o);
    if ((tid & 31) == 0) red1[tid >> 5] = s;
    __syncthreads();
    float mean = (red1[0] + red1[1] + red1[2] + red1[3]) * (1.0f / NDIM);
    float d0 = v.x - mean, d1 = v.y - mean, d2 = v.z - mean, d3 = v.w - mean;
    float ss = d0*d0 + d1*d1 + d2*d2 + d3*d3;
#pragma unroll
    for (int o = 16; o; o >>= 1) ss += __shfl_xor_sync(0xffffffffu, ss, o);
    if ((tid & 31) == 0) red2[tid >> 5] = ss;
    __syncthreads();
    float var = (red2[0] + red2[1] + red2[2] + red2[3]) * (1.0f / NDIM);
    float inv = rsqrtf(var + 1e-5f);
    float4 gv = ((const float4*)g)[tid];
    float o0 = d0*inv*gv.x, o1 = d1*inv*gv.y, o2 = d2*inv*gv.z, o3 = d3*inv*gv.w;
    *(uint2*)(g_xnh + row*NDIM + tid*4) = make_uint2(pk_hi(o0,o1), pk_hi(o2,o3));
}

// ---- pb-relax softmax in place (vectorized); computes null sim itself, stores a0 ----
__global__ void softmax_kernel(const float* __restrict__ nkv)
{
    __shared__ float red[8];
    __shared__ float s0sh;
    size_t gi = blockIdx.x;
    __half* p = g_simh + gi * NS;         // token j at p[j-1]; rewritten with attn
    int tid = threadIdx.x;  // 256; each thread owns 4 contiguous cols

    // null-token similarity: dot(q_row, null_k broadcast over r) * QS
    {
        const float QS = (0.125f / 128.0f) * 0.28867513459481287f;
        const __half* qrow = g_qh + gi * RD;
        float part = 0.f;
#pragma unroll
        for (int it = 0; it < 3; it++) {
            int idx = tid + it * 256;
            part += __half2float(qrow[idx]) * nkv[idx & 63];
        }
#pragma unroll
        for (int o = 16; o; o >>= 1) part += __shfl_xor_sync(0xffffffffu, part, o);
        if ((tid & 31) == 0) red[tid >> 5] = part;
        __syncthreads();
        if (tid == 0)
            s0sh = (red[0]+red[1]+red[2]+red[3]+red[4]+red[5]+red[6]+red[7]) * QS;
        __syncthreads();
    }
    const float s0 = s0sh;

    // load 4 contiguous cols
    uint2 pv = *(const uint2*)(p + tid * 4);
    __half2 h0 = *(__half2*)&pv.x, h1 = *(__half2*)&pv.y;
    float v0 = __half2float(h0.x), v1 = __half2float(h0.y);
    float v2 = __half2float(h1.x), v3 = __half2float(h1.y);

    float mx = fmaxf(fmaxf(v0, v1), fmaxf(v2, v3));
    if (tid == 0) mx = fmaxf(mx, s0);
#pragma unroll
    for (int o = 16; o; o >>= 1) mx = fmaxf(mx, __shfl_xor_sync(0xffffffffu, mx, o));
    if ((tid & 31) == 0) red[tid >> 5] = mx;
    __syncthreads();
    float bm = red[0];
#pragma unroll
    for (int w = 1; w < 8; w++) bm = fmaxf(bm, red[w]);
    __syncthreads();

    float e0 = expf((v0 - bm) * 128.0f);
    float e1 = expf((v1 - bm) * 128.0f);
    float e2 = expf((v2 - bm) * 128.0f);
    float e3 = expf((v3 - bm) * 128.0f);
    float es0 = 0.f;
    if (tid == 0) es0 = expf((s0 - bm) * 128.0f);
    float s = e0 + e1 + e2 + e3 + es0;
#pragma unroll
    for (int o = 16; o; o >>= 1) s += __shfl_xor_sync(0xffffffffu, s, o);
    if ((tid & 31) == 0) red[tid >> 5] = s;
    __syncthreads();
    float bs = red[0]+red[1]+red[2]+red[3]+red[4]+red[5]+red[6]+red[7];
    float inv = 1.0f / bs;

    uint2 ov = make_uint2(pk_hi(e0 * inv, e1 * inv), pk_hi(e2 * inv, e3 * inv));
    *(uint2*)(p + tid * 4) = ov;
    if (tid == 0) g_a0[gi] = es0 * inv;
}

// ---------------- final LN (reads fp16 pre-LN out) ----------------
__global__ void ln_final(const float* __restrict__ g, float* __restrict__ yout)
{
    __shared__ float red1[4], red2[4];
    size_t row = blockIdx.x;
    int tid = threadIdx.x;                 // 128 threads x 4 vals
    uint2 pv = *(const uint2*)(g_outh + row * NDIM + tid * 4);
    __half2 h0 = *(__half2*)&pv.x, h1 = *(__half2*)&pv.y;
    float vx = __half2float(h0.x), vy = __half2float(h0.y);
    float vz = __half2float(h1.x), vw = __half2float(h1.y);
    float s = vx + vy + vz + vw;
#pragma unroll
    for (int o = 16; o; o >>= 1) s += __shfl_xor_sync(0xffffffffu, s, o);
    if ((tid & 31) == 0) red1[tid >> 5] = s;
    __syncthreads();
    float mean = (red1[0] + red1[1] + red1[2] + red1[3]) * (1.0f / NDIM);
    float d0 = vx - mean, d1 = vy - mean, d2 = vz - mean, d3 = vw - mean;
    float ss = d0*d0 + d1*d1 + d2*d2 + d3*d3;
#pragma unroll
    for (int o = 16; o; o >>= 1) ss += __shfl_xor_sync(0xffffffffu, ss, o);
    if ((tid & 31) == 0) red2[tid >> 5] = ss;
    __syncthreads();
    float var = (red2[0] + red2[1] + red2[2] + red2[3]) * (1.0f / NDIM);
    float inv = rsqrtf(var + 1e-5f);
    float4 gv = ((const float4*)g)[tid];
    ((float4*)(yout + row * NDIM))[tid] =
        make_float4(d0*inv*gv.x, d1*inv*gv.y, d2*inv*gv.z, d3*inv*gv.w);
}

// ---------------- launch ----------------
extern "C" void kernel_launch(void* const* d_in, const int* in_sizes, int n_in,
                              void* d_out, int out_size)
{
    const float* x        = (const float*)d_in[0];
    const float* context  = (const float*)d_in[1];
    const float* norm_g   = (const float*)d_in[2];
    const float* to_q_w   = (const float*)d_in[3];
    const float* to_kv_w  = (const float*)d_in[4];
    const float* null_kv  = (const float*)d_in[5];
    const float* to_out_w = (const float*)d_in[6];
    const float* out_ng   = (const float*)d_in[7];
    float* out = (float*)d_out;

    static bool init_done = false;
    static cudaStream_t s1;
    static cudaEvent_t evFork, evJoin;
    if (!init_done) {
        cudaFuncSetAttribute(gemm_hmma<GQPROJ>,  cudaFuncAttributeMaxDynamicSharedMemorySize, GEMM_SMEM);
        cudaFuncSetAttribute(gemm_hmma<GKVPROJ>, cudaFuncAttributeMaxDynamicSharedMemorySize, GEMM_SMEM);
        cudaFuncSetAttribute(gemm_hmma<GSIM>,    cudaFuncAttributeMaxDynamicSharedMemorySize, GEMM_SMEM);
        cudaFuncSetAttribute(gemm_hmma<GAV>,     cudaFuncAttributeMaxDynamicSharedMemorySize, GEMM_SMEM);
        cudaFuncSetAttribute(gemm_hmma<GOPROJ>,  cudaFuncAttributeMaxDynamicSharedMemorySize, GEMM_SMEM);
        cudaStreamCreateWithFlags(&s1, cudaStreamNonBlocking);
        cudaEventCreateWithFlags(&evFork, cudaEventDisableTiming);
        cudaEventCreateWithFlags(&evJoin, cudaEventDisableTiming);
        init_done = true;
    }

    __half *wqh, *wkvh, *woh, *ctxh;
    cudaGetSymbolAddress((void**)&wqh,  g_wqh);
    cudaGetSymbolAddress((void**)&wkvh, g_wkvh);
    cudaGetSymbolAddress((void**)&woh,  g_woh);
    cudaGetSymbolAddress((void**)&ctxh, g_ctxh);

    // fork: secondary stream handles the Q branch
    cudaEventRecord(evFork, 0);
    cudaStreamWaitEvent(s1, evFork, 0);

    // stream s1: wq conv -> LN -> QPROJ
    conv_h<<<(512*512/4 + 255)/256, 256, 0, s1>>>(to_q_w, wqh, 512*512/4);
    ln_in<<<NROWS, 128, 0, s1>>>(x, norm_g);
    gemm_hmma<GQPROJ><<<dim3(512/128, NROWS/128, 1), 256, GEMM_SMEM, s1>>>(nullptr);
    cudaEventRecord(evJoin, s1);

    // default stream: ctx/wkv/wo convs -> KVPROJ
    conv_h<<<(NROWS*NDIM/4 + 255)/256, 256>>>(context, ctxh, NROWS*NDIM/4);
    conv_h<<<(1024*512/4 + 255)/256, 256>>>(to_kv_w, wkvh, 1024*512/4);
    conv_h<<<(512*512/4 + 255)/256, 256>>>(to_out_w, woh, 512*512/4);
    gemm_hmma<GKVPROJ><<<dim3(1024/128, NROWS/128, 1), 256, GEMM_SMEM>>>(nullptr);

    // join: SIM needs both branches
    cudaStreamWaitEvent(0, evJoin, 0);

    // sim[:,1:] = (q @ k^T) * scale -> fp16 [bh,i,1024]
    gemm_hmma<GSIM><<<dim3(NS/128, NS/128, BH), 256, GEMM_SMEM>>>(nullptr);
    // softmax in place (computes null col itself, stores a0)
    softmax_kernel<<<BH * NS, 256>>>(null_kv);
    // o = attn @ v (trans-B from [j,rd]) + a0*null_v -> o fp16 [b,n,r,(h d)]
    gemm_hmma<GAV><<<dim3(RD/128, NS/128, BH), 256, GEMM_SMEM>>>(null_kv);
    // out = o @ Wout^T -> fp16 g_outh
    gemm_hmma<GOPROJ><<<dim3(512/128, NROWS/128, 1), 256, GEMM_SMEM>>>(nullptr);
    // final LN -> d_out
    ln_final<<<NROWS, 128>>>(out_ng, out);
    (void)in_sizes; (void)n_in; (void)out_size;
}